// round 8
// baseline (speedup 1.0000x reference)
#include <cuda_runtime.h>
#include <cuda_bf16.h>
#include <math_constants.h>
#include <cstdint>
#include <cstddef>

#define B_ 8
#define L_ 1024
#define C_ 1024
#define H_ 16
#define D_ 64
#define MAXSC 4.6051701859880914f  // log(100)

// ---------------------------------------------------------------------------
// Scratch (bss, no runtime allocation)
// ---------------------------------------------------------------------------
__device__ float g_qkv[B_ * L_ * 3 * C_];

__device__ __nv_bfloat16 g_xhi[B_ * L_ * C_];
__device__ __nv_bfloat16 g_xlo[B_ * L_ * C_];
__device__ __nv_bfloat16 g_wqh[3 * C_ * C_];
__device__ __nv_bfloat16 g_wql[3 * C_ * C_];
__device__ __nv_bfloat16 g_wph[C_ * C_];
__device__ __nv_bfloat16 g_wpl[C_ * C_];

__device__ __nv_bfloat16 g_qh[B_ * H_ * L_ * D_];
__device__ __nv_bfloat16 g_ql[B_ * H_ * L_ * D_];
__device__ __nv_bfloat16 g_kh[B_ * H_ * L_ * D_];
__device__ __nv_bfloat16 g_kl[B_ * H_ * L_ * D_];
__device__ __nv_bfloat16 g_vh[B_ * H_ * L_ * D_];
__device__ __nv_bfloat16 g_vl[B_ * H_ * L_ * D_];

__device__ __nv_bfloat16 g_aoh[B_ * L_ * C_];
__device__ __nv_bfloat16 g_aol[B_ * L_ * C_];

// ---------------------------------------------------------------------------
// Helpers
// ---------------------------------------------------------------------------
__device__ __forceinline__ uint32_t smem_u32(const void* p) {
    uint32_t a;
    asm("{ .reg .u64 t; cvta.to.shared.u64 t, %1; cvt.u32.u64 %0, t; }"
        : "=r"(a) : "l"(p));
    return a;
}

__device__ __forceinline__ void mma16816(float* c, const uint32_t* a,
                                         uint32_t b0, uint32_t b1)
{
    asm volatile(
        "mma.sync.aligned.m16n8k16.row.col.f32.bf16.bf16.f32 "
        "{%0,%1,%2,%3}, {%4,%5,%6,%7}, {%8,%9}, {%0,%1,%2,%3};"
        : "+f"(c[0]), "+f"(c[1]), "+f"(c[2]), "+f"(c[3])
        : "r"(a[0]), "r"(a[1]), "r"(a[2]), "r"(a[3]), "r"(b0), "r"(b1));
}

__device__ __forceinline__ void ldsm_x4(uint32_t* r, uint32_t addr) {
    asm volatile("ldmatrix.sync.aligned.m8n8.x4.shared.b16 {%0,%1,%2,%3}, [%4];"
        : "=r"(r[0]), "=r"(r[1]), "=r"(r[2]), "=r"(r[3]) : "r"(addr));
}
__device__ __forceinline__ void ldsm_x4_t(uint32_t* r, uint32_t addr) {
    asm volatile("ldmatrix.sync.aligned.m8n8.x4.trans.shared.b16 {%0,%1,%2,%3}, [%4];"
        : "=r"(r[0]), "=r"(r[1]), "=r"(r[2]), "=r"(r[3]) : "r"(addr));
}

__device__ __forceinline__ uint32_t pack_bf16(float a, float b) {
    __nv_bfloat162 t = __floats2bfloat162_rn(a, b);
    return *(uint32_t*)&t;
}

__device__ __forceinline__ void cp_async16(uint32_t saddr, const void* gptr) {
    asm volatile("cp.async.cg.shared.global [%0], [%1], 16;"
        :: "r"(saddr), "l"(gptr) : "memory");
}
__device__ __forceinline__ void cp_commit() {
    asm volatile("cp.async.commit_group;" ::: "memory");
}
template <int N>
__device__ __forceinline__ void cp_wait() {
    asm volatile("cp.async.wait_group %0;" :: "n"(N) : "memory");
}

// ---------------------------------------------------------------------------
// fp32 -> (hi, lo) bf16 split
// ---------------------------------------------------------------------------
__global__ __launch_bounds__(256) void conv_split_kernel(
    const float* __restrict__ src, __nv_bfloat16* __restrict__ hi,
    __nv_bfloat16* __restrict__ lo, int n4)
{
    int i = blockIdx.x * blockDim.x + threadIdx.x;
    if (i >= n4) return;
    float4 v = ((const float4*)src)[i];
    __nv_bfloat16 h0 = __float2bfloat16(v.x);
    __nv_bfloat16 h1 = __float2bfloat16(v.y);
    __nv_bfloat16 h2 = __float2bfloat16(v.z);
    __nv_bfloat16 h3 = __float2bfloat16(v.w);
    __nv_bfloat16 l0 = __float2bfloat16(v.x - __bfloat162float(h0));
    __nv_bfloat16 l1 = __float2bfloat16(v.y - __bfloat162float(h1));
    __nv_bfloat16 l2 = __float2bfloat16(v.z - __bfloat162float(h2));
    __nv_bfloat16 l3 = __float2bfloat16(v.w - __bfloat162float(h3));
    ((__nv_bfloat162*)hi)[2 * i]     = __nv_bfloat162(h0, h1);
    ((__nv_bfloat162*)hi)[2 * i + 1] = __nv_bfloat162(h2, h3);
    ((__nv_bfloat162*)lo)[2 * i]     = __nv_bfloat162(l0, l1);
    ((__nv_bfloat162*)lo)[2 * i + 1] = __nv_bfloat162(l2, l3);
}

// ---------------------------------------------------------------------------
// HMMA GEMM, 2-stage cp.async pipeline, term-major MMA order.
// ---------------------------------------------------------------------------
#define SSTRIDE 40
#define GMATSZ (128 * SSTRIDE)   // elements per matrix per stage
__global__ __launch_bounds__(256, 2) void gemm_mma_kernel(
    const __nv_bfloat16* __restrict__ Ahi, const __nv_bfloat16* __restrict__ Alo,
    const __nv_bfloat16* __restrict__ Bhi, const __nv_bfloat16* __restrict__ Blo,
    float* __restrict__ Cm,
    const float* __restrict__ bias_q, const float* __restrict__ bias_v,
    int N, int K, int mode)
{
    extern __shared__ __align__(16) __nv_bfloat16 sm[];
    int t = threadIdx.x;
    int wid = t >> 5, lane = t & 31;
    int wm = wid & 3, wn = wid >> 2;
    int m0 = blockIdx.y * 128, n0 = blockIdx.x * 128;
    uint32_t sb = smem_u32(sm);

    float acc[2][8][4];
    #pragma unroll
    for (int i = 0; i < 2; i++)
        #pragma unroll
        for (int j = 0; j < 8; j++)
            #pragma unroll
            for (int u = 0; u < 4; u++) acc[i][j][u] = 0.f;

    int qrow = lane >> 2;
    int qk   = (lane & 3) * 2;
    int g = lane >> 3, r8 = lane & 7;
    uint32_t loff = 2u * (uint32_t)(((g & 1) * 8 + r8) * SSTRIDE + (g >> 1) * 8);
    const int niter = K >> 5;

    auto issue = [&](int it, int s) {
        int k0 = it << 5;
        #pragma unroll
        for (int i = 0; i < 2; i++) {
            int c = t + i * 256;
            int row = c >> 2, seg = c & 3;
            size_t ga = (size_t)(m0 + row) * K + k0 + seg * 8;
            size_t gb = (size_t)(n0 + row) * K + k0 + seg * 8;
            uint32_t so = sb + (uint32_t)(s * 4 * GMATSZ + row * SSTRIDE + seg * 8) * 2;
            cp_async16(so,              Ahi + ga);
            cp_async16(so + GMATSZ * 2, Alo + ga);
            cp_async16(so + GMATSZ * 4, Bhi + gb);
            cp_async16(so + GMATSZ * 6, Blo + gb);
        }
        cp_commit();
    };

    issue(0, 0);
    for (int it = 0; it < niter; it++) {
        int s = it & 1;
        if (it + 1 < niter) { issue(it + 1, s ^ 1); cp_wait<1>(); }
        else                { cp_wait<0>(); }
        __syncthreads();

        uint32_t bAh = sb + (uint32_t)(s * 4 * GMATSZ) * 2;
        uint32_t bAl = bAh + GMATSZ * 2;
        uint32_t bBh = bAl + GMATSZ * 2;
        uint32_t bBl = bBh + GMATSZ * 2;

        #pragma unroll
        for (int ks = 0; ks < 2; ks++) {
            int kk = ks * 16;
            uint32_t afh[2][4], afl[2][4];
            #pragma unroll
            for (int mf = 0; mf < 2; mf++) {
                uint32_t rb = 2u * (uint32_t)((wm * 32 + mf * 16) * SSTRIDE + kk);
                ldsm_x4(afh[mf], bAh + rb + loff);
                ldsm_x4(afl[mf], bAl + rb + loff);
            }
            // nfp pairs: load 2 B tiles, then term-major MMA issue
            #pragma unroll
            for (int pp = 0; pp < 2; pp++) {
                uint32_t bh4[2][4], bl4[2][4];
                #pragma unroll
                for (int j = 0; j < 2; j++) {
                    int nfp = pp * 2 + j;
                    uint32_t rb = 2u * (uint32_t)((wn * 64 + nfp * 16) * SSTRIDE + kk);
                    ldsm_x4(bh4[j], bBh + rb + loff);
                    ldsm_x4(bl4[j], bBl + rb + loff);
                }
                // term 1: Ahi * Bhi (8 independent MMAs)
                #pragma unroll
                for (int j = 0; j < 2; j++)
                    #pragma unroll
                    for (int mf = 0; mf < 2; mf++) {
                        int nb = 2 * (pp * 2 + j);
                        mma16816(acc[mf][nb],     afh[mf], bh4[j][0], bh4[j][2]);
                        mma16816(acc[mf][nb + 1], afh[mf], bh4[j][1], bh4[j][3]);
                    }
                // term 2: Ahi * Blo
                #pragma unroll
                for (int j = 0; j < 2; j++)
                    #pragma unroll
                    for (int mf = 0; mf < 2; mf++) {
                        int nb = 2 * (pp * 2 + j);
                        mma16816(acc[mf][nb],     afh[mf], bl4[j][0], bl4[j][2]);
                        mma16816(acc[mf][nb + 1], afh[mf], bl4[j][1], bl4[j][3]);
                    }
                // term 3: Alo * Bhi
                #pragma unroll
                for (int j = 0; j < 2; j++)
                    #pragma unroll
                    for (int mf = 0; mf < 2; mf++) {
                        int nb = 2 * (pp * 2 + j);
                        mma16816(acc[mf][nb],     afl[mf], bh4[j][0], bh4[j][2]);
                        mma16816(acc[mf][nb + 1], afl[mf], bh4[j][1], bh4[j][3]);
                    }
            }
        }
        __syncthreads();
    }

    #pragma unroll
    for (int mf = 0; mf < 2; mf++) {
        #pragma unroll
        for (int nf = 0; nf < 8; nf++) {
            int row = m0 + wm * 32 + mf * 16 + qrow;
            int col = n0 + wn * 64 + nf * 8 + qk;
            float bv0, bv1;
            if (mode == 0) {
                bv0 = (col < C_) ? bias_q[col]
                    : ((col < 2 * C_) ? 0.f : bias_v[col - 2 * C_]);
                bv1 = (col + 1 < C_) ? bias_q[col + 1]
                    : ((col + 1 < 2 * C_) ? 0.f : bias_v[col + 1 - 2 * C_]);
            } else {
                bv0 = bias_q[col];
                bv1 = bias_q[col + 1];
            }
            *(float2*)(Cm + (size_t)row * N + col) =
                make_float2(acc[mf][nf][0] + bv0, acc[mf][nf][1] + bv1);
            *(float2*)(Cm + (size_t)(row + 8) * N + col) =
                make_float2(acc[mf][nf][2] + bv0, acc[mf][nf][3] + bv1);
        }
    }
}

// ---------------------------------------------------------------------------
// Transform: l2norm(+scale) + RoPE; writes q/k/v as bf16 hi/lo [b,h,l,d]
// ---------------------------------------------------------------------------
__global__ __launch_bounds__(256) void transform_kernel(
    const float* __restrict__ freqs, const float* __restrict__ sml)
{
    int w    = blockIdx.x * 8 + (threadIdx.x >> 5);
    int lane = threadIdx.x & 31;
    int h = w & 15;
    int l = (w >> 4) & 1023;
    int b = w >> 14;

    const float* base = g_qkv + (size_t)(b * L_ + l) * (3 * C_);
    float2 q2 = ((const float2*)(base + 0 * C_ + h * D_))[lane];
    float2 k2 = ((const float2*)(base + 1 * C_ + h * D_))[lane];
    float2 v2 = ((const float2*)(base + 2 * C_ + h * D_))[lane];

    float qs = q2.x * q2.x + q2.y * q2.y;
    float ks = k2.x * k2.x + k2.y * k2.y;
    #pragma unroll
    for (int o = 16; o > 0; o >>= 1) {
        qs += __shfl_xor_sync(0xffffffffu, qs, o);
        ks += __shfl_xor_sync(0xffffffffu, ks, o);
    }
    float qinv = expf(fminf(sml[h], MAXSC)) / fmaxf(sqrtf(qs), 1e-12f);
    float kinv = 1.f / fmaxf(sqrtf(ks), 1e-12f);

    float2 fc = ((const float2*)(freqs + l * D_))[lane];
    float qx = q2.x * qinv, qy = q2.y * qinv;
    float kx = k2.x * kinv, ky = k2.y * kinv;
    float qox = qx * fc.x - qy * fc.y, qoy = qx * fc.y + qy * fc.x;
    float kox = kx * fc.x - ky * fc.y, koy = kx * fc.y + ky * fc.x;

    size_t oidx = (size_t)((b * H_ + h) * L_ + l) * D_;
    float qhx = __bfloat162float(__float2bfloat16(qox));
    float qhy = __bfloat162float(__float2bfloat16(qoy));
    float khx = __bfloat162float(__float2bfloat16(kox));
    float khy = __bfloat162float(__float2bfloat16(koy));
    float vhx = __bfloat162float(__float2bfloat16(v2.x));
    float vhy = __bfloat162float(__float2bfloat16(v2.y));
    ((uint32_t*)(g_qh + oidx))[lane] = pack_bf16(qox, qoy);
    ((uint32_t*)(g_ql + oidx))[lane] = pack_bf16(qox - qhx, qoy - qhy);
    ((uint32_t*)(g_kh + oidx))[lane] = pack_bf16(kox, koy);
    ((uint32_t*)(g_kl + oidx))[lane] = pack_bf16(kox - khx, koy - khy);
    ((uint32_t*)(g_vh + oidx))[lane] = pack_bf16(v2.x, v2.y);
    ((uint32_t*)(g_vl + oidx))[lane] = pack_bf16(v2.x - vhx, v2.y - vhy);
}

// ---------------------------------------------------------------------------
// Flash attention, bf16 HMMA, 2-stage cp.async pipeline, term-major MMA order.
// ---------------------------------------------------------------------------
#define AST 72
#define ATSZ (64 * AST * 2)   // bytes per tile
__global__ __launch_bounds__(128) void attn_mma_kernel(
    const float* __restrict__ bias)
{
    extern __shared__ __align__(16) char asmem[];
    uint32_t sbase = smem_u32(asmem);

    int t = threadIdx.x;
    int wid = t >> 5, lane = t & 31;
    int q0 = blockIdx.x * 64;
    int bh = blockIdx.y;
    int b = bh >> 4, h = bh & 15;

    const __nv_bfloat16* Qh = g_qh + (size_t)bh * L_ * D_;
    const __nv_bfloat16* Ql = g_ql + (size_t)bh * L_ * D_;
    const __nv_bfloat16* Kh = g_kh + (size_t)bh * L_ * D_;
    const __nv_bfloat16* Kl = g_kl + (size_t)bh * L_ * D_;
    const __nv_bfloat16* Vh = g_vh + (size_t)bh * L_ * D_;
    const __nv_bfloat16* Vl = g_vl + (size_t)bh * L_ * D_;

    int rA = q0 + wid * 16 + (lane >> 2);
    int c0 = (lane & 3) * 2;

    uint32_t qa_h[4][4], qa_l[4][4];
    #pragma unroll
    for (int kf = 0; kf < 4; kf++) {
        int cb = kf * 16 + c0;
        qa_h[kf][0] = *(const uint32_t*)(Qh + (size_t)rA * D_ + cb);
        qa_h[kf][1] = *(const uint32_t*)(Qh + (size_t)(rA + 8) * D_ + cb);
        qa_h[kf][2] = *(const uint32_t*)(Qh + (size_t)rA * D_ + cb + 8);
        qa_h[kf][3] = *(const uint32_t*)(Qh + (size_t)(rA + 8) * D_ + cb + 8);
        qa_l[kf][0] = *(const uint32_t*)(Ql + (size_t)rA * D_ + cb);
        qa_l[kf][1] = *(const uint32_t*)(Ql + (size_t)(rA + 8) * D_ + cb);
        qa_l[kf][2] = *(const uint32_t*)(Ql + (size_t)rA * D_ + cb + 8);
        qa_l[kf][3] = *(const uint32_t*)(Ql + (size_t)(rA + 8) * D_ + cb + 8);
    }

    float m0 = -CUDART_INF_F, m1 = -CUDART_INF_F;
    float l0 = 0.f, l1 = 0.f;
    float oacc[8][4];
    #pragma unroll
    for (int nf = 0; nf < 8; nf++)
        #pragma unroll
        for (int u = 0; u < 4; u++) oacc[nf][u] = 0.f;

    int g = lane >> 3, r8 = lane & 7;
    uint32_t koff = 2u * ((uint32_t)((8 * (g >> 1) + r8) * AST + 8 * (g & 1)));
    uint32_t voff = 2u * ((uint32_t)((8 * (g & 1) + r8) * AST + 8 * (g >> 1)));

    const float* brow0 = bias + (size_t)rA * L_;
    const float* brow1 = bias + (size_t)(rA + 8) * L_;

    auto issue_kv = [&](int k0, int s) {
        #pragma unroll
        for (int i = 0; i < 4; i++) {
            int c = t + i * 128;
            int row = c >> 3, seg = c & 7;
            size_t gsrc = (size_t)(k0 + row) * D_ + seg * 8;
            uint32_t so = sbase + (uint32_t)(s * 4) * ATSZ
                        + (uint32_t)(row * AST + seg * 8) * 2;
            cp_async16(so,            Kh + gsrc);
            cp_async16(so + ATSZ,     Kl + gsrc);
            cp_async16(so + 2 * ATSZ, Vh + gsrc);
            cp_async16(so + 3 * ATSZ, Vl + gsrc);
        }
        cp_commit();
    };

    issue_kv(0, 0);
    const int NIT = L_ / 64;
    for (int ki = 0; ki < NIT; ki++) {
        int s = ki & 1;
        if (ki + 1 < NIT) { issue_kv((ki + 1) * 64, s ^ 1); cp_wait<1>(); }
        else              { cp_wait<0>(); }
        __syncthreads();

        uint32_t skh = sbase + (uint32_t)(s * 4) * ATSZ;
        uint32_t skl = skh + ATSZ;
        uint32_t svh = skl + ATSZ;
        uint32_t svl = svh + ATSZ;
        int k0 = ki * 64;

        float sacc[8][4];
        #pragma unroll
        for (int nf = 0; nf < 8; nf++)
            #pragma unroll
            for (int u = 0; u < 4; u++) sacc[nf][u] = 0.f;

        // S = Q K^T: kf outer, all 4 nfp frags loaded, term-major issue
        #pragma unroll
        for (int kf = 0; kf < 4; kf++) {
            uint32_t kbh[4][4], kbl[4][4];
            #pragma unroll
            for (int nfp = 0; nfp < 4; nfp++) {
                uint32_t stp = 2u * (uint32_t)(16 * nfp * AST + 16 * kf);
                ldsm_x4(kbh[nfp], skh + stp + koff);
                ldsm_x4(kbl[nfp], skl + stp + koff);
            }
            #pragma unroll
            for (int nfp = 0; nfp < 4; nfp++) {
                mma16816(sacc[2 * nfp],     qa_h[kf], kbh[nfp][0], kbh[nfp][1]);
                mma16816(sacc[2 * nfp + 1], qa_h[kf], kbh[nfp][2], kbh[nfp][3]);
            }
            #pragma unroll
            for (int nfp = 0; nfp < 4; nfp++) {
                mma16816(sacc[2 * nfp],     qa_h[kf], kbl[nfp][0], kbl[nfp][1]);
                mma16816(sacc[2 * nfp + 1], qa_h[kf], kbl[nfp][2], kbl[nfp][3]);
            }
            #pragma unroll
            for (int nfp = 0; nfp < 4; nfp++) {
                mma16816(sacc[2 * nfp],     qa_l[kf], kbh[nfp][0], kbh[nfp][1]);
                mma16816(sacc[2 * nfp + 1], qa_l[kf], kbh[nfp][2], kbh[nfp][3]);
            }
        }

        #pragma unroll
        for (int nf = 0; nf < 8; nf++) {
            int kc = k0 + nf * 8 + c0;
            float2 b0 = *(const float2*)(brow0 + kc);
            float2 b1 = *(const float2*)(brow1 + kc);
            sacc[nf][0] += b0.x; sacc[nf][1] += b0.y;
            sacc[nf][2] += b1.x; sacc[nf][3] += b1.y;
        }

        float mx0 = -CUDART_INF_F, mx1 = -CUDART_INF_F;
        #pragma unroll
        for (int nf = 0; nf < 8; nf++) {
            mx0 = fmaxf(mx0, fmaxf(sacc[nf][0], sacc[nf][1]));
            mx1 = fmaxf(mx1, fmaxf(sacc[nf][2], sacc[nf][3]));
        }
        mx0 = fmaxf(mx0, __shfl_xor_sync(0xffffffffu, mx0, 1));
        mx0 = fmaxf(mx0, __shfl_xor_sync(0xffffffffu, mx0, 2));
        mx1 = fmaxf(mx1, __shfl_xor_sync(0xffffffffu, mx1, 1));
        mx1 = fmaxf(mx1, __shfl_xor_sync(0xffffffffu, mx1, 2));

        float mn0 = fmaxf(m0, mx0), mn1 = fmaxf(m1, mx1);
        float cr0 = __expf(m0 - mn0), cr1 = __expf(m1 - mn1);
        float rs0 = 0.f, rs1 = 0.f;
        #pragma unroll
        for (int nf = 0; nf < 8; nf++) {
            sacc[nf][0] = __expf(sacc[nf][0] - mn0);
            sacc[nf][1] = __expf(sacc[nf][1] - mn0);
            sacc[nf][2] = __expf(sacc[nf][2] - mn1);
            sacc[nf][3] = __expf(sacc[nf][3] - mn1);
            rs0 += sacc[nf][0] + sacc[nf][1];
            rs1 += sacc[nf][2] + sacc[nf][3];
        }
        rs0 += __shfl_xor_sync(0xffffffffu, rs0, 1);
        rs0 += __shfl_xor_sync(0xffffffffu, rs0, 2);
        rs1 += __shfl_xor_sync(0xffffffffu, rs1, 1);
        rs1 += __shfl_xor_sync(0xffffffffu, rs1, 2);
        l0 = l0 * cr0 + rs0;
        l1 = l1 * cr1 + rs1;
        m0 = mn0; m1 = mn1;

        #pragma unroll
        for (int nf = 0; nf < 8; nf++) {
            oacc[nf][0] *= cr0; oacc[nf][1] *= cr0;
            oacc[nf][2] *= cr1; oacc[nf][3] *= cr1;
        }

        uint32_t pa_h[4][4], pa_l[4][4];
        #pragma unroll
        for (int kf = 0; kf < 4; kf++) {
            #pragma unroll
            for (int half = 0; half < 2; half++) {
                int nf = 2 * kf + half;
                float p0 = sacc[nf][0], p1 = sacc[nf][1];
                float p2 = sacc[nf][2], p3 = sacc[nf][3];
                uint32_t hi01 = pack_bf16(p0, p1);
                uint32_t hi23 = pack_bf16(p2, p3);
                __nv_bfloat162 h01 = *(__nv_bfloat162*)&hi01;
                __nv_bfloat162 h23 = *(__nv_bfloat162*)&hi23;
                uint32_t lo01 = pack_bf16(p0 - __bfloat162float(h01.x),
                                          p1 - __bfloat162float(h01.y));
                uint32_t lo23 = pack_bf16(p2 - __bfloat162float(h23.x),
                                          p3 - __bfloat162float(h23.y));
                pa_h[kf][2 * half]     = hi01;
                pa_h[kf][2 * half + 1] = hi23;
                pa_l[kf][2 * half]     = lo01;
                pa_l[kf][2 * half + 1] = lo23;
            }
        }

        // O += P V: kf outer, all 4 nfp V frags, term-major issue
        #pragma unroll
        for (int kf = 0; kf < 4; kf++) {
            uint32_t vbh[4][4], vbl[4][4];
            #pragma unroll
            for (int nfp = 0; nfp < 4; nfp++) {
                uint32_t stp = 2u * (uint32_t)(16 * kf * AST + 16 * nfp);
                ldsm_x4_t(vbh[nfp], svh + stp + voff);
                ldsm_x4_t(vbl[nfp], svl + stp + voff);
            }
            #pragma unroll
            for (int nfp = 0; nfp < 4; nfp++) {
                mma16816(oacc[2 * nfp],     pa_h[kf], vbh[nfp][0], vbh[nfp][1]);
                mma16816(oacc[2 * nfp + 1], pa_h[kf], vbh[nfp][2], vbh[nfp][3]);
            }
            #pragma unroll
            for (int nfp = 0; nfp < 4; nfp++) {
                mma16816(oacc[2 * nfp],     pa_h[kf], vbl[nfp][0], vbl[nfp][1]);
                mma16816(oacc[2 * nfp + 1], pa_h[kf], vbl[nfp][2], vbl[nfp][3]);
            }
            #pragma unroll
            for (int nfp = 0; nfp < 4; nfp++) {
                mma16816(oacc[2 * nfp],     pa_l[kf], vbh[nfp][0], vbh[nfp][1]);
                mma16816(oacc[2 * nfp + 1], pa_l[kf], vbh[nfp][2], vbh[nfp][3]);
            }
        }
        __syncthreads();
    }

    float inv0 = 1.f / l0, inv1 = 1.f / l1;
    size_t orow0 = (size_t)(b * L_ + rA) * C_ + h * D_;
    size_t orow1 = (size_t)(b * L_ + rA + 8) * C_ + h * D_;
    #pragma unroll
    for (int nf = 0; nf < 8; nf++) {
        int d = nf * 8 + c0;
        float v0 = oacc[nf][0] * inv0, v1 = oacc[nf][1] * inv0;
        float v2 = oacc[nf][2] * inv1, v3 = oacc[nf][3] * inv1;
        uint32_t h01 = pack_bf16(v0, v1);
        uint32_t h23 = pack_bf16(v2, v3);
        __nv_bfloat162 b01 = *(__nv_bfloat162*)&h01;
        __nv_bfloat162 b23 = *(__nv_bfloat162*)&h23;
        uint32_t l01 = pack_bf16(v0 - __bfloat162float(b01.x),
                                 v1 - __bfloat162float(b01.y));
        uint32_t l23 = pack_bf16(v2 - __bfloat162float(b23.x),
                                 v3 - __bfloat162float(b23.y));
        *(uint32_t*)(g_aoh + orow0 + d) = h01;
        *(uint32_t*)(g_aol + orow0 + d) = l01;
        *(uint32_t*)(g_aoh + orow1 + d) = h23;
        *(uint32_t*)(g_aol + orow1 + d) = l23;
    }
}

// ---------------------------------------------------------------------------
extern "C" void kernel_launch(void* const* d_in, const int* in_sizes, int n_in,
                              void* d_out, int out_size)
{
    const float* x         = (const float*)d_in[0];
    const float* freqs     = (const float*)d_in[1];
    const float* attn_bias = (const float*)d_in[2];
    const float* W_qkv     = (const float*)d_in[3];
    const float* q_bias    = (const float*)d_in[4];
    const float* v_bias    = (const float*)d_in[5];
    const float* sml       = (const float*)d_in[6];
    const float* W_proj    = (const float*)d_in[7];
    const float* b_proj    = (const float*)d_in[8];
    float* out = (float*)d_out;

    void* p;
    cudaGetSymbolAddress(&p, g_qkv); float* qkv = (float*)p;
    cudaGetSymbolAddress(&p, g_xhi); __nv_bfloat16* xhi = (__nv_bfloat16*)p;
    cudaGetSymbolAddress(&p, g_xlo); __nv_bfloat16* xlo = (__nv_bfloat16*)p;
    cudaGetSymbolAddress(&p, g_wqh); __nv_bfloat16* wqh = (__nv_bfloat16*)p;
    cudaGetSymbolAddress(&p, g_wql); __nv_bfloat16* wql = (__nv_bfloat16*)p;
    cudaGetSymbolAddress(&p, g_wph); __nv_bfloat16* wph = (__nv_bfloat16*)p;
    cudaGetSymbolAddress(&p, g_wpl); __nv_bfloat16* wpl = (__nv_bfloat16*)p;
    cudaGetSymbolAddress(&p, g_aoh); __nv_bfloat16* aoh = (__nv_bfloat16*)p;
    cudaGetSymbolAddress(&p, g_aol); __nv_bfloat16* aol = (__nv_bfloat16*)p;

    int gsm = 2 * 4 * GMATSZ * (int)sizeof(__nv_bfloat16);  // 81920
    int asm_ = 2 * 4 * ATSZ;                                 // 73728
    static bool attr_set = false;
    if (!attr_set) {
        cudaFuncSetAttribute(gemm_mma_kernel,
                             cudaFuncAttributeMaxDynamicSharedMemorySize, gsm);
        cudaFuncSetAttribute(attn_mma_kernel,
                             cudaFuncAttributeMaxDynamicSharedMemorySize, asm_);
        attr_set = true;
    }

    conv_split_kernel<<<(B_ * L_ * C_ / 4 + 255) / 256, 256>>>(x, xhi, xlo, B_ * L_ * C_ / 4);
    conv_split_kernel<<<(3 * C_ * C_ / 4 + 255) / 256, 256>>>(W_qkv, wqh, wql, 3 * C_ * C_ / 4);
    conv_split_kernel<<<(C_ * C_ / 4 + 255) / 256, 256>>>(W_proj, wph, wpl, C_ * C_ / 4);

    gemm_mma_kernel<<<dim3(3 * C_ / 128, B_ * L_ / 128), 256, gsm>>>(
        xhi, xlo, wqh, wql, qkv, q_bias, v_bias, 3 * C_, C_, 0);

    transform_kernel<<<(B_ * L_ * H_) / 8, 256>>>(freqs, sml);

    attn_mma_kernel<<<dim3(L_ / 64, B_ * H_), 128, asm_>>>(attn_bias);

    gemm_mma_kernel<<<dim3(C_ / 128, B_ * L_ / 128), 256, gsm>>>(
        aoh, aol, wph, wpl, out, b_proj, nullptr, C_, C_, 1);
}

// round 9
// speedup vs baseline: 1.0646x; 1.0646x over previous
#include <cuda_runtime.h>
#include <cuda_bf16.h>
#include <math_constants.h>
#include <cstdint>
#include <cstddef>

#define B_ 8
#define L_ 1024
#define C_ 1024
#define H_ 16
#define D_ 64
#define MAXSC 4.6051701859880914f  // log(100)

// ---------------------------------------------------------------------------
// Scratch (bss, no runtime allocation)
// ---------------------------------------------------------------------------
__device__ float g_qkv[B_ * L_ * 3 * C_];

__device__ __nv_bfloat16 g_xhi[B_ * L_ * C_];
__device__ __nv_bfloat16 g_xlo[B_ * L_ * C_];
__device__ __nv_bfloat16 g_wqh[3 * C_ * C_];
__device__ __nv_bfloat16 g_wql[3 * C_ * C_];
__device__ __nv_bfloat16 g_wph[C_ * C_];
__device__ __nv_bfloat16 g_wpl[C_ * C_];

__device__ __nv_bfloat16 g_qh[B_ * H_ * L_ * D_];
__device__ __nv_bfloat16 g_ql[B_ * H_ * L_ * D_];
__device__ __nv_bfloat16 g_kh[B_ * H_ * L_ * D_];
__device__ __nv_bfloat16 g_kl[B_ * H_ * L_ * D_];
__device__ __nv_bfloat16 g_vh[B_ * H_ * L_ * D_];
__device__ __nv_bfloat16 g_vl[B_ * H_ * L_ * D_];

__device__ __nv_bfloat16 g_aoh[B_ * L_ * C_];
__device__ __nv_bfloat16 g_aol[B_ * L_ * C_];

// ---------------------------------------------------------------------------
// Helpers
// ---------------------------------------------------------------------------
__device__ __forceinline__ uint32_t smem_u32(const void* p) {
    uint32_t a;
    asm("{ .reg .u64 t; cvta.to.shared.u64 t, %1; cvt.u32.u64 %0, t; }"
        : "=r"(a) : "l"(p));
    return a;
}

__device__ __forceinline__ void mma16816(float* c, const uint32_t* a,
                                         uint32_t b0, uint32_t b1)
{
    asm volatile(
        "mma.sync.aligned.m16n8k16.row.col.f32.bf16.bf16.f32 "
        "{%0,%1,%2,%3}, {%4,%5,%6,%7}, {%8,%9}, {%0,%1,%2,%3};"
        : "+f"(c[0]), "+f"(c[1]), "+f"(c[2]), "+f"(c[3])
        : "r"(a[0]), "r"(a[1]), "r"(a[2]), "r"(a[3]), "r"(b0), "r"(b1));
}

__device__ __forceinline__ void ldsm_x4(uint32_t* r, uint32_t addr) {
    asm volatile("ldmatrix.sync.aligned.m8n8.x4.shared.b16 {%0,%1,%2,%3}, [%4];"
        : "=r"(r[0]), "=r"(r[1]), "=r"(r[2]), "=r"(r[3]) : "r"(addr));
}
__device__ __forceinline__ void ldsm_x4_t(uint32_t* r, uint32_t addr) {
    asm volatile("ldmatrix.sync.aligned.m8n8.x4.trans.shared.b16 {%0,%1,%2,%3}, [%4];"
        : "=r"(r[0]), "=r"(r[1]), "=r"(r[2]), "=r"(r[3]) : "r"(addr));
}

__device__ __forceinline__ uint32_t pack_bf16(float a, float b) {
    __nv_bfloat162 t = __floats2bfloat162_rn(a, b);
    return *(uint32_t*)&t;
}

__device__ __forceinline__ void cp_async16(uint32_t saddr, const void* gptr) {
    asm volatile("cp.async.cg.shared.global [%0], [%1], 16;"
        :: "r"(saddr), "l"(gptr) : "memory");
}
__device__ __forceinline__ void cp_commit() {
    asm volatile("cp.async.commit_group;" ::: "memory");
}
template <int N>
__device__ __forceinline__ void cp_wait() {
    asm volatile("cp.async.wait_group %0;" :: "n"(N) : "memory");
}

// ---------------------------------------------------------------------------
// fp32 -> (hi, lo) bf16 split
// ---------------------------------------------------------------------------
__global__ __launch_bounds__(256) void conv_split_kernel(
    const float* __restrict__ src, __nv_bfloat16* __restrict__ hi,
    __nv_bfloat16* __restrict__ lo, int n4)
{
    int i = blockIdx.x * blockDim.x + threadIdx.x;
    if (i >= n4) return;
    float4 v = ((const float4*)src)[i];
    __nv_bfloat16 h0 = __float2bfloat16(v.x);
    __nv_bfloat16 h1 = __float2bfloat16(v.y);
    __nv_bfloat16 h2 = __float2bfloat16(v.z);
    __nv_bfloat16 h3 = __float2bfloat16(v.w);
    __nv_bfloat16 l0 = __float2bfloat16(v.x - __bfloat162float(h0));
    __nv_bfloat16 l1 = __float2bfloat16(v.y - __bfloat162float(h1));
    __nv_bfloat16 l2 = __float2bfloat16(v.z - __bfloat162float(h2));
    __nv_bfloat16 l3 = __float2bfloat16(v.w - __bfloat162float(h3));
    ((__nv_bfloat162*)hi)[2 * i]     = __nv_bfloat162(h0, h1);
    ((__nv_bfloat162*)hi)[2 * i + 1] = __nv_bfloat162(h2, h3);
    ((__nv_bfloat162*)lo)[2 * i]     = __nv_bfloat162(l0, l1);
    ((__nv_bfloat162*)lo)[2 * i + 1] = __nv_bfloat162(l2, l3);
}

// ---------------------------------------------------------------------------
// HMMA GEMM, 3-stage cp.async pipeline, SW128-swizzled packed hi|lo layout.
// Stage: A rows [Ahi 64B | Alo 64B] x128 = 16KB, B same = 16KB -> 32KB/stage.
// ---------------------------------------------------------------------------
#define GSTAGE 32768
__global__ __launch_bounds__(256, 2) void gemm_mma_kernel(
    const __nv_bfloat16* __restrict__ Ahi, const __nv_bfloat16* __restrict__ Alo,
    const __nv_bfloat16* __restrict__ Bhi, const __nv_bfloat16* __restrict__ Blo,
    float* __restrict__ Cm,
    const float* __restrict__ bias_q, const float* __restrict__ bias_v,
    int N, int K, int mode)
{
    extern __shared__ __align__(16) char smc[];
    uint32_t sb = smem_u32(smc);
    int t = threadIdx.x;
    int wid = t >> 5, lane = t & 31;
    int wm = wid & 3, wn = wid >> 2;
    int m0 = blockIdx.y * 128, n0 = blockIdx.x * 128;

    float acc[2][8][4];
    #pragma unroll
    for (int i = 0; i < 2; i++)
        #pragma unroll
        for (int j = 0; j < 8; j++)
            #pragma unroll
            for (int u = 0; u < 4; u++) acc[i][j][u] = 0.f;

    int qrow = lane >> 2;
    int qk   = (lane & 3) * 2;
    int g = lane >> 3, r8 = lane & 7;
    int arow = (g & 1) * 8 + r8;           // lane's row within a 16-row tile
    uint32_t xv   = (uint32_t)(r8 << 4);   // SW128 xor for this lane's rows
    uint32_t ccol = (uint32_t)((g >> 1) * 16);
    const int niter = K >> 5;

    auto issue = [&](int it, int s) {
        int k0 = it << 5;
        uint32_t stb = sb + (uint32_t)s * GSTAGE;
        #pragma unroll
        for (int i = 0; i < 4; i++) {
            int c = t + i * 256;           // 0..1023 A chunks
            int row = c >> 3, cg = c & 7;
            uint32_t off = (uint32_t)(row * 128 + cg * 16);
            uint32_t swo = off ^ ((off >> 3) & 0x70);
            const __nv_bfloat16* src = (cg < 4)
                ? (Ahi + (size_t)(m0 + row) * K + k0 + cg * 8)
                : (Alo + (size_t)(m0 + row) * K + k0 + (cg - 4) * 8);
            cp_async16(stb + swo, src);
        }
        #pragma unroll
        for (int i = 0; i < 4; i++) {
            int c = t + i * 256;           // 0..1023 B chunks
            int row = c >> 3, cg = c & 7;
            uint32_t off = (uint32_t)(row * 128 + cg * 16);
            uint32_t swo = off ^ ((off >> 3) & 0x70);
            const __nv_bfloat16* src = (cg < 4)
                ? (Bhi + (size_t)(n0 + row) * K + k0 + cg * 8)
                : (Blo + (size_t)(n0 + row) * K + k0 + (cg - 4) * 8);
            cp_async16(stb + 16384 + swo, src);
        }
        cp_commit();
    };

    issue(0, 0);
    issue(1, 1);
    int s = 0;
    for (int it = 0; it < niter; it++) {
        if (it + 1 < niter) cp_wait<1>(); else cp_wait<0>();
        __syncthreads();
        if (it + 2 < niter) {
            int s2 = s + 2; if (s2 >= 3) s2 -= 3;
            issue(it + 2, s2);
        }

        uint32_t sA = sb + (uint32_t)s * GSTAGE;
        uint32_t sB = sA + 16384;

        #pragma unroll
        for (int ks = 0; ks < 2; ks++) {
            uint32_t chh = (uint32_t)(ks * 32);        // hi col base (bytes)
            uint32_t chl = (uint32_t)(64 + ks * 32);   // lo col base
            uint32_t ah = (chh + ccol) ^ xv;
            uint32_t al = (chl + ccol) ^ xv;
            uint32_t afh[2][4], afl[2][4];
            #pragma unroll
            for (int mf = 0; mf < 2; mf++) {
                uint32_t rb = (uint32_t)((wm * 32 + mf * 16 + arow) * 128);
                ldsm_x4(afh[mf], sA + rb + ah);
                ldsm_x4(afl[mf], sA + rb + al);
            }
            #pragma unroll
            for (int nfp = 0; nfp < 4; nfp++) {
                uint32_t rb = (uint32_t)((wn * 64 + nfp * 16 + arow) * 128);
                uint32_t bh4[4], bl4[4];
                ldsm_x4(bh4, sB + rb + ah);
                ldsm_x4(bl4, sB + rb + al);
                #pragma unroll
                for (int mf = 0; mf < 2; mf++) {
                    mma16816(acc[mf][2 * nfp],     afh[mf], bh4[0], bh4[2]);
                    mma16816(acc[mf][2 * nfp],     afh[mf], bl4[0], bl4[2]);
                    mma16816(acc[mf][2 * nfp],     afl[mf], bh4[0], bh4[2]);
                    mma16816(acc[mf][2 * nfp + 1], afh[mf], bh4[1], bh4[3]);
                    mma16816(acc[mf][2 * nfp + 1], afh[mf], bl4[1], bl4[3]);
                    mma16816(acc[mf][2 * nfp + 1], afl[mf], bh4[1], bh4[3]);
                }
            }
        }
        if (++s >= 3) s -= 3;
    }

    #pragma unroll
    for (int mf = 0; mf < 2; mf++) {
        #pragma unroll
        for (int nf = 0; nf < 8; nf++) {
            int row = m0 + wm * 32 + mf * 16 + qrow;
            int col = n0 + wn * 64 + nf * 8 + qk;
            float bv0, bv1;
            if (mode == 0) {
                bv0 = (col < C_) ? bias_q[col]
                    : ((col < 2 * C_) ? 0.f : bias_v[col - 2 * C_]);
                bv1 = (col + 1 < C_) ? bias_q[col + 1]
                    : ((col + 1 < 2 * C_) ? 0.f : bias_v[col + 1 - 2 * C_]);
            } else {
                bv0 = bias_q[col];
                bv1 = bias_q[col + 1];
            }
            *(float2*)(Cm + (size_t)row * N + col) =
                make_float2(acc[mf][nf][0] + bv0, acc[mf][nf][1] + bv1);
            *(float2*)(Cm + (size_t)(row + 8) * N + col) =
                make_float2(acc[mf][nf][2] + bv0, acc[mf][nf][3] + bv1);
        }
    }
}

// ---------------------------------------------------------------------------
// Transform: l2norm(+scale) + RoPE; writes q/k/v as bf16 hi/lo [b,h,l,d]
// ---------------------------------------------------------------------------
__global__ __launch_bounds__(256) void transform_kernel(
    const float* __restrict__ freqs, const float* __restrict__ sml)
{
    int w    = blockIdx.x * 8 + (threadIdx.x >> 5);
    int lane = threadIdx.x & 31;
    int h = w & 15;
    int l = (w >> 4) & 1023;
    int b = w >> 14;

    const float* base = g_qkv + (size_t)(b * L_ + l) * (3 * C_);
    float2 q2 = ((const float2*)(base + 0 * C_ + h * D_))[lane];
    float2 k2 = ((const float2*)(base + 1 * C_ + h * D_))[lane];
    float2 v2 = ((const float2*)(base + 2 * C_ + h * D_))[lane];

    float qs = q2.x * q2.x + q2.y * q2.y;
    float ks = k2.x * k2.x + k2.y * k2.y;
    #pragma unroll
    for (int o = 16; o > 0; o >>= 1) {
        qs += __shfl_xor_sync(0xffffffffu, qs, o);
        ks += __shfl_xor_sync(0xffffffffu, ks, o);
    }
    float qinv = expf(fminf(sml[h], MAXSC)) / fmaxf(sqrtf(qs), 1e-12f);
    float kinv = 1.f / fmaxf(sqrtf(ks), 1e-12f);

    float2 fc = ((const float2*)(freqs + l * D_))[lane];
    float qx = q2.x * qinv, qy = q2.y * qinv;
    float kx = k2.x * kinv, ky = k2.y * kinv;
    float qox = qx * fc.x - qy * fc.y, qoy = qx * fc.y + qy * fc.x;
    float kox = kx * fc.x - ky * fc.y, koy = kx * fc.y + ky * fc.x;

    size_t oidx = (size_t)((b * H_ + h) * L_ + l) * D_;
    float qhx = __bfloat162float(__float2bfloat16(qox));
    float qhy = __bfloat162float(__float2bfloat16(qoy));
    float khx = __bfloat162float(__float2bfloat16(kox));
    float khy = __bfloat162float(__float2bfloat16(koy));
    float vhx = __bfloat162float(__float2bfloat16(v2.x));
    float vhy = __bfloat162float(__float2bfloat16(v2.y));
    ((uint32_t*)(g_qh + oidx))[lane] = pack_bf16(qox, qoy);
    ((uint32_t*)(g_ql + oidx))[lane] = pack_bf16(qox - qhx, qoy - qhy);
    ((uint32_t*)(g_kh + oidx))[lane] = pack_bf16(kox, koy);
    ((uint32_t*)(g_kl + oidx))[lane] = pack_bf16(kox - khx, koy - khy);
    ((uint32_t*)(g_vh + oidx))[lane] = pack_bf16(v2.x, v2.y);
    ((uint32_t*)(g_vl + oidx))[lane] = pack_bf16(v2.x - vhx, v2.y - vhy);
}

// ---------------------------------------------------------------------------
// Flash attention, bf16 HMMA, 2-stage cp.async pipeline (R6 best version).
// ---------------------------------------------------------------------------
#define AST 72
#define ATSZ (64 * AST * 2)   // bytes per tile
__global__ __launch_bounds__(128) void attn_mma_kernel(
    const float* __restrict__ bias)
{
    extern __shared__ __align__(16) char asmem[];
    uint32_t sbase = smem_u32(asmem);

    int t = threadIdx.x;
    int wid = t >> 5, lane = t & 31;
    int q0 = blockIdx.x * 64;
    int bh = blockIdx.y;
    int b = bh >> 4, h = bh & 15;

    const __nv_bfloat16* Qh = g_qh + (size_t)bh * L_ * D_;
    const __nv_bfloat16* Ql = g_ql + (size_t)bh * L_ * D_;
    const __nv_bfloat16* Kh = g_kh + (size_t)bh * L_ * D_;
    const __nv_bfloat16* Kl = g_kl + (size_t)bh * L_ * D_;
    const __nv_bfloat16* Vh = g_vh + (size_t)bh * L_ * D_;
    const __nv_bfloat16* Vl = g_vl + (size_t)bh * L_ * D_;

    int rA = q0 + wid * 16 + (lane >> 2);
    int c0 = (lane & 3) * 2;

    uint32_t qa_h[4][4], qa_l[4][4];
    #pragma unroll
    for (int kf = 0; kf < 4; kf++) {
        int cb = kf * 16 + c0;
        qa_h[kf][0] = *(const uint32_t*)(Qh + (size_t)rA * D_ + cb);
        qa_h[kf][1] = *(const uint32_t*)(Qh + (size_t)(rA + 8) * D_ + cb);
        qa_h[kf][2] = *(const uint32_t*)(Qh + (size_t)rA * D_ + cb + 8);
        qa_h[kf][3] = *(const uint32_t*)(Qh + (size_t)(rA + 8) * D_ + cb + 8);
        qa_l[kf][0] = *(const uint32_t*)(Ql + (size_t)rA * D_ + cb);
        qa_l[kf][1] = *(const uint32_t*)(Ql + (size_t)(rA + 8) * D_ + cb);
        qa_l[kf][2] = *(const uint32_t*)(Ql + (size_t)rA * D_ + cb + 8);
        qa_l[kf][3] = *(const uint32_t*)(Ql + (size_t)(rA + 8) * D_ + cb + 8);
    }

    float m0 = -CUDART_INF_F, m1 = -CUDART_INF_F;
    float l0 = 0.f, l1 = 0.f;
    float oacc[8][4];
    #pragma unroll
    for (int nf = 0; nf < 8; nf++)
        #pragma unroll
        for (int u = 0; u < 4; u++) oacc[nf][u] = 0.f;

    int g = lane >> 3, r8 = lane & 7;
    uint32_t koff = 2u * ((uint32_t)((8 * (g >> 1) + r8) * AST + 8 * (g & 1)));
    uint32_t voff = 2u * ((uint32_t)((8 * (g & 1) + r8) * AST + 8 * (g >> 1)));

    const float* brow0 = bias + (size_t)rA * L_;
    const float* brow1 = bias + (size_t)(rA + 8) * L_;

    auto issue_kv = [&](int k0, int s) {
        #pragma unroll
        for (int i = 0; i < 4; i++) {
            int c = t + i * 128;
            int row = c >> 3, seg = c & 7;
            size_t gsrc = (size_t)(k0 + row) * D_ + seg * 8;
            uint32_t so = sbase + (uint32_t)(s * 4) * ATSZ
                        + (uint32_t)(row * AST + seg * 8) * 2;
            cp_async16(so,            Kh + gsrc);
            cp_async16(so + ATSZ,     Kl + gsrc);
            cp_async16(so + 2 * ATSZ, Vh + gsrc);
            cp_async16(so + 3 * ATSZ, Vl + gsrc);
        }
        cp_commit();
    };

    issue_kv(0, 0);
    const int NIT = L_ / 64;
    for (int ki = 0; ki < NIT; ki++) {
        int s = ki & 1;
        if (ki + 1 < NIT) { issue_kv((ki + 1) * 64, s ^ 1); cp_wait<1>(); }
        else              { cp_wait<0>(); }
        __syncthreads();

        uint32_t skh = sbase + (uint32_t)(s * 4) * ATSZ;
        uint32_t skl = skh + ATSZ;
        uint32_t svh = skl + ATSZ;
        uint32_t svl = svh + ATSZ;
        int k0 = ki * 64;

        float sacc[8][4];
        #pragma unroll
        for (int nf = 0; nf < 8; nf++)
            #pragma unroll
            for (int u = 0; u < 4; u++) sacc[nf][u] = 0.f;

        #pragma unroll
        for (int nfp = 0; nfp < 4; nfp++) {
            #pragma unroll
            for (int kf = 0; kf < 4; kf++) {
                uint32_t stp = 2u * (uint32_t)(16 * nfp * AST + 16 * kf);
                uint32_t bh4[4], bl4[4];
                ldsm_x4(bh4, skh + stp + koff);
                ldsm_x4(bl4, skl + stp + koff);
                mma16816(sacc[2 * nfp],     qa_h[kf], bh4[0], bh4[1]);
                mma16816(sacc[2 * nfp],     qa_h[kf], bl4[0], bl4[1]);
                mma16816(sacc[2 * nfp],     qa_l[kf], bh4[0], bh4[1]);
                mma16816(sacc[2 * nfp + 1], qa_h[kf], bh4[2], bh4[3]);
                mma16816(sacc[2 * nfp + 1], qa_h[kf], bl4[2], bl4[3]);
                mma16816(sacc[2 * nfp + 1], qa_l[kf], bh4[2], bh4[3]);
            }
        }

        #pragma unroll
        for (int nf = 0; nf < 8; nf++) {
            int kc = k0 + nf * 8 + c0;
            float2 b0 = *(const float2*)(brow0 + kc);
            float2 b1 = *(const float2*)(brow1 + kc);
            sacc[nf][0] += b0.x; sacc[nf][1] += b0.y;
            sacc[nf][2] += b1.x; sacc[nf][3] += b1.y;
        }

        float mx0 = -CUDART_INF_F, mx1 = -CUDART_INF_F;
        #pragma unroll
        for (int nf = 0; nf < 8; nf++) {
            mx0 = fmaxf(mx0, fmaxf(sacc[nf][0], sacc[nf][1]));
            mx1 = fmaxf(mx1, fmaxf(sacc[nf][2], sacc[nf][3]));
        }
        mx0 = fmaxf(mx0, __shfl_xor_sync(0xffffffffu, mx0, 1));
        mx0 = fmaxf(mx0, __shfl_xor_sync(0xffffffffu, mx0, 2));
        mx1 = fmaxf(mx1, __shfl_xor_sync(0xffffffffu, mx1, 1));
        mx1 = fmaxf(mx1, __shfl_xor_sync(0xffffffffu, mx1, 2));

        float mn0 = fmaxf(m0, mx0), mn1 = fmaxf(m1, mx1);
        float cr0 = __expf(m0 - mn0), cr1 = __expf(m1 - mn1);
        float rs0 = 0.f, rs1 = 0.f;
        #pragma unroll
        for (int nf = 0; nf < 8; nf++) {
            sacc[nf][0] = __expf(sacc[nf][0] - mn0);
            sacc[nf][1] = __expf(sacc[nf][1] - mn0);
            sacc[nf][2] = __expf(sacc[nf][2] - mn1);
            sacc[nf][3] = __expf(sacc[nf][3] - mn1);
            rs0 += sacc[nf][0] + sacc[nf][1];
            rs1 += sacc[nf][2] + sacc[nf][3];
        }
        rs0 += __shfl_xor_sync(0xffffffffu, rs0, 1);
        rs0 += __shfl_xor_sync(0xffffffffu, rs0, 2);
        rs1 += __shfl_xor_sync(0xffffffffu, rs1, 1);
        rs1 += __shfl_xor_sync(0xffffffffu, rs1, 2);
        l0 = l0 * cr0 + rs0;
        l1 = l1 * cr1 + rs1;
        m0 = mn0; m1 = mn1;

        #pragma unroll
        for (int nf = 0; nf < 8; nf++) {
            oacc[nf][0] *= cr0; oacc[nf][1] *= cr0;
            oacc[nf][2] *= cr1; oacc[nf][3] *= cr1;
        }

        uint32_t pa_h[4][4], pa_l[4][4];
        #pragma unroll
        for (int kf = 0; kf < 4; kf++) {
            #pragma unroll
            for (int half = 0; half < 2; half++) {
                int nf = 2 * kf + half;
                float p0 = sacc[nf][0], p1 = sacc[nf][1];
                float p2 = sacc[nf][2], p3 = sacc[nf][3];
                uint32_t hi01 = pack_bf16(p0, p1);
                uint32_t hi23 = pack_bf16(p2, p3);
                __nv_bfloat162 h01 = *(__nv_bfloat162*)&hi01;
                __nv_bfloat162 h23 = *(__nv_bfloat162*)&hi23;
                uint32_t lo01 = pack_bf16(p0 - __bfloat162float(h01.x),
                                          p1 - __bfloat162float(h01.y));
                uint32_t lo23 = pack_bf16(p2 - __bfloat162float(h23.x),
                                          p3 - __bfloat162float(h23.y));
                pa_h[kf][2 * half]     = hi01;
                pa_h[kf][2 * half + 1] = hi23;
                pa_l[kf][2 * half]     = lo01;
                pa_l[kf][2 * half + 1] = lo23;
            }
        }

        #pragma unroll
        for (int nfp = 0; nfp < 4; nfp++) {
            #pragma unroll
            for (int kf = 0; kf < 4; kf++) {
                uint32_t stp = 2u * (uint32_t)(16 * kf * AST + 16 * nfp);
                uint32_t vh4[4], vl4[4];
                ldsm_x4_t(vh4, svh + stp + voff);
                ldsm_x4_t(vl4, svl + stp + voff);
                mma16816(oacc[2 * nfp],     pa_h[kf], vh4[0], vh4[1]);
                mma16816(oacc[2 * nfp],     pa_h[kf], vl4[0], vl4[1]);
                mma16816(oacc[2 * nfp],     pa_l[kf], vh4[0], vh4[1]);
                mma16816(oacc[2 * nfp + 1], pa_h[kf], vh4[2], vh4[3]);
                mma16816(oacc[2 * nfp + 1], pa_h[kf], vl4[2], vl4[3]);
                mma16816(oacc[2 * nfp + 1], pa_l[kf], vh4[2], vh4[3]);
            }
        }
        __syncthreads();
    }

    float inv0 = 1.f / l0, inv1 = 1.f / l1;
    size_t orow0 = (size_t)(b * L_ + rA) * C_ + h * D_;
    size_t orow1 = (size_t)(b * L_ + rA + 8) * C_ + h * D_;
    #pragma unroll
    for (int nf = 0; nf < 8; nf++) {
        int d = nf * 8 + c0;
        float v0 = oacc[nf][0] * inv0, v1 = oacc[nf][1] * inv0;
        float v2 = oacc[nf][2] * inv1, v3 = oacc[nf][3] * inv1;
        uint32_t h01 = pack_bf16(v0, v1);
        uint32_t h23 = pack_bf16(v2, v3);
        __nv_bfloat162 b01 = *(__nv_bfloat162*)&h01;
        __nv_bfloat162 b23 = *(__nv_bfloat162*)&h23;
        uint32_t l01 = pack_bf16(v0 - __bfloat162float(b01.x),
                                 v1 - __bfloat162float(b01.y));
        uint32_t l23 = pack_bf16(v2 - __bfloat162float(b23.x),
                                 v3 - __bfloat162float(b23.y));
        *(uint32_t*)(g_aoh + orow0 + d) = h01;
        *(uint32_t*)(g_aol + orow0 + d) = l01;
        *(uint32_t*)(g_aoh + orow1 + d) = h23;
        *(uint32_t*)(g_aol + orow1 + d) = l23;
    }
}

// ---------------------------------------------------------------------------
extern "C" void kernel_launch(void* const* d_in, const int* in_sizes, int n_in,
                              void* d_out, int out_size)
{
    const float* x         = (const float*)d_in[0];
    const float* freqs     = (const float*)d_in[1];
    const float* attn_bias = (const float*)d_in[2];
    const float* W_qkv     = (const float*)d_in[3];
    const float* q_bias    = (const float*)d_in[4];
    const float* v_bias    = (const float*)d_in[5];
    const float* sml       = (const float*)d_in[6];
    const float* W_proj    = (const float*)d_in[7];
    const float* b_proj    = (const float*)d_in[8];
    float* out = (float*)d_out;

    void* p;
    cudaGetSymbolAddress(&p, g_qkv); float* qkv = (float*)p;
    cudaGetSymbolAddress(&p, g_xhi); __nv_bfloat16* xhi = (__nv_bfloat16*)p;
    cudaGetSymbolAddress(&p, g_xlo); __nv_bfloat16* xlo = (__nv_bfloat16*)p;
    cudaGetSymbolAddress(&p, g_wqh); __nv_bfloat16* wqh = (__nv_bfloat16*)p;
    cudaGetSymbolAddress(&p, g_wql); __nv_bfloat16* wql = (__nv_bfloat16*)p;
    cudaGetSymbolAddress(&p, g_wph); __nv_bfloat16* wph = (__nv_bfloat16*)p;
    cudaGetSymbolAddress(&p, g_wpl); __nv_bfloat16* wpl = (__nv_bfloat16*)p;
    cudaGetSymbolAddress(&p, g_aoh); __nv_bfloat16* aoh = (__nv_bfloat16*)p;
    cudaGetSymbolAddress(&p, g_aol); __nv_bfloat16* aol = (__nv_bfloat16*)p;

    int gsm = 3 * GSTAGE;      // 98304
    int asm_ = 2 * 4 * ATSZ;   // 73728
    static bool attr_set = false;
    if (!attr_set) {
        cudaFuncSetAttribute(gemm_mma_kernel,
                             cudaFuncAttributeMaxDynamicSharedMemorySize, gsm);
        cudaFuncSetAttribute(attn_mma_kernel,
                             cudaFuncAttributeMaxDynamicSharedMemorySize, asm_);
        attr_set = true;
    }

    conv_split_kernel<<<(B_ * L_ * C_ / 4 + 255) / 256, 256>>>(x, xhi, xlo, B_ * L_ * C_ / 4);
    conv_split_kernel<<<(3 * C_ * C_ / 4 + 255) / 256, 256>>>(W_qkv, wqh, wql, 3 * C_ * C_ / 4);
    conv_split_kernel<<<(C_ * C_ / 4 + 255) / 256, 256>>>(W_proj, wph, wpl, C_ * C_ / 4);

    gemm_mma_kernel<<<dim3(3 * C_ / 128, B_ * L_ / 128), 256, gsm>>>(
        xhi, xlo, wqh, wql, qkv, q_bias, v_bias, 3 * C_, C_, 0);

    transform_kernel<<<(B_ * L_ * H_) / 8, 256>>>(freqs, sml);

    attn_mma_kernel<<<dim3(L_ / 64, B_ * H_), 128, asm_>>>(attn_bias);

    gemm_mma_kernel<<<dim3(C_ / 128, B_ * L_ / 128), 256, gsm>>>(
        aoh, aol, wph, wpl, out, b_proj, nullptr, C_, C_, 1);
}

// round 10
// speedup vs baseline: 1.5563x; 1.4618x over previous
#include <cuda_runtime.h>
#include <cuda_fp16.h>
#include <math_constants.h>
#include <cstdint>
#include <cstddef>

#define B_ 8
#define L_ 1024
#define C_ 1024
#define H_ 16
#define D_ 64
#define MAXSC 4.6051701859880914f  // log(100)

// ---------------------------------------------------------------------------
// Scratch (bss, no runtime allocation)
// ---------------------------------------------------------------------------
__device__ float g_qkv[B_ * L_ * 3 * C_];

__device__ __half g_xhi[B_ * L_ * C_];
__device__ __half g_xlo[B_ * L_ * C_];
__device__ __half g_wqh[3 * C_ * C_];
__device__ __half g_wph[C_ * C_];

__device__ __half g_qh[B_ * H_ * L_ * D_];
__device__ __half g_ql[B_ * H_ * L_ * D_];
__device__ __half g_kh[B_ * H_ * L_ * D_];
__device__ __half g_vh[B_ * H_ * L_ * D_];

__device__ __half g_aoh[B_ * L_ * C_];
__device__ __half g_aol[B_ * L_ * C_];

// ---------------------------------------------------------------------------
// Helpers
// ---------------------------------------------------------------------------
__device__ __forceinline__ uint32_t smem_u32(const void* p) {
    uint32_t a;
    asm("{ .reg .u64 t; cvta.to.shared.u64 t, %1; cvt.u32.u64 %0, t; }"
        : "=r"(a) : "l"(p));
    return a;
}

__device__ __forceinline__ void mma16816(float* c, const uint32_t* a,
                                         uint32_t b0, uint32_t b1)
{
    asm volatile(
        "mma.sync.aligned.m16n8k16.row.col.f32.f16.f16.f32 "
        "{%0,%1,%2,%3}, {%4,%5,%6,%7}, {%8,%9}, {%0,%1,%2,%3};"
        : "+f"(c[0]), "+f"(c[1]), "+f"(c[2]), "+f"(c[3])
        : "r"(a[0]), "r"(a[1]), "r"(a[2]), "r"(a[3]), "r"(b0), "r"(b1));
}

__device__ __forceinline__ void ldsm_x4(uint32_t* r, uint32_t addr) {
    asm volatile("ldmatrix.sync.aligned.m8n8.x4.shared.b16 {%0,%1,%2,%3}, [%4];"
        : "=r"(r[0]), "=r"(r[1]), "=r"(r[2]), "=r"(r[3]) : "r"(addr));
}
__device__ __forceinline__ void ldsm_x4_t(uint32_t* r, uint32_t addr) {
    asm volatile("ldmatrix.sync.aligned.m8n8.x4.trans.shared.b16 {%0,%1,%2,%3}, [%4];"
        : "=r"(r[0]), "=r"(r[1]), "=r"(r[2]), "=r"(r[3]) : "r"(addr));
}

__device__ __forceinline__ uint32_t pack_f16(float a, float b) {
    __half2 t = __floats2half2_rn(a, b);
    return *(uint32_t*)&t;
}

__device__ __forceinline__ void cp_async16(uint32_t saddr, const void* gptr) {
    asm volatile("cp.async.cg.shared.global [%0], [%1], 16;"
        :: "r"(saddr), "l"(gptr) : "memory");
}
__device__ __forceinline__ void cp_commit() {
    asm volatile("cp.async.commit_group;" ::: "memory");
}
template <int N>
__device__ __forceinline__ void cp_wait() {
    asm volatile("cp.async.wait_group %0;" :: "n"(N) : "memory");
}

// ---------------------------------------------------------------------------
// fp32 -> (hi, lo) fp16 split / hi-only
// ---------------------------------------------------------------------------
__global__ __launch_bounds__(256) void conv_split_kernel(
    const float* __restrict__ src, __half* __restrict__ hi,
    __half* __restrict__ lo, int n4)
{
    int i = blockIdx.x * blockDim.x + threadIdx.x;
    if (i >= n4) return;
    float4 v = ((const float4*)src)[i];
    __half h0 = __float2half_rn(v.x);
    __half h1 = __float2half_rn(v.y);
    __half h2 = __float2half_rn(v.z);
    __half h3 = __float2half_rn(v.w);
    __half l0 = __float2half_rn(v.x - __half2float(h0));
    __half l1 = __float2half_rn(v.y - __half2float(h1));
    __half l2 = __float2half_rn(v.z - __half2float(h2));
    __half l3 = __float2half_rn(v.w - __half2float(h3));
    ((__half2*)hi)[2 * i]     = __half2(h0, h1);
    ((__half2*)hi)[2 * i + 1] = __half2(h2, h3);
    ((__half2*)lo)[2 * i]     = __half2(l0, l1);
    ((__half2*)lo)[2 * i + 1] = __half2(l2, l3);
}

__global__ __launch_bounds__(256) void conv_hi_kernel(
    const float* __restrict__ src, __half* __restrict__ hi, int n4)
{
    int i = blockIdx.x * blockDim.x + threadIdx.x;
    if (i >= n4) return;
    float4 v = ((const float4*)src)[i];
    ((__half2*)hi)[2 * i]     = __floats2half2_rn(v.x, v.y);
    ((__half2*)hi)[2 * i + 1] = __floats2half2_rn(v.z, v.w);
}

// ---------------------------------------------------------------------------
// HMMA GEMM: C = A*B^T + bias.  A fp16 2-term (hi+lo), B fp16 hi-only.
// 3-stage cp.async pipeline.  Stage: A 128x128B (hi|lo) + B 128x64B = 24KB.
// ---------------------------------------------------------------------------
#define GSTAGE 24576
__global__ __launch_bounds__(256, 2) void gemm_mma_kernel(
    const __half* __restrict__ Ahi, const __half* __restrict__ Alo,
    const __half* __restrict__ Bhi,
    float* __restrict__ Cm,
    const float* __restrict__ bias_q, const float* __restrict__ bias_v,
    int N, int K, int mode)
{
    extern __shared__ __align__(16) char smc[];
    uint32_t sb = smem_u32(smc);
    int t = threadIdx.x;
    int wid = t >> 5, lane = t & 31;
    int wm = wid & 3, wn = wid >> 2;
    int m0 = blockIdx.y * 128, n0 = blockIdx.x * 128;

    float acc[2][8][4];
    #pragma unroll
    for (int i = 0; i < 2; i++)
        #pragma unroll
        for (int j = 0; j < 8; j++)
            #pragma unroll
            for (int u = 0; u < 4; u++) acc[i][j][u] = 0.f;

    int qrow = lane >> 2;
    int qk   = (lane & 3) * 2;
    int g = lane >> 3, r8 = lane & 7;
    int arow = (g & 1) * 8 + r8;               // lane row within 16-row tile
    uint32_t xv = (uint32_t)(r8 << 4);          // A swizzle xor (128B rows)
    uint32_t xb = (uint32_t)(((arow >> 1) & 3) << 4);  // B swizzle xor (64B rows)
    uint32_t ccol = (uint32_t)((g >> 1) * 16);
    const int niter = K >> 5;

    auto issue = [&](int it, int s) {
        int k0 = it << 5;
        uint32_t stb = sb + (uint32_t)s * GSTAGE;
        // A: 1024 chunks (8/row: 4 hi + 4 lo), SW128 on 128B rows
        #pragma unroll
        for (int i = 0; i < 4; i++) {
            int c = t + i * 256;
            int row = c >> 3, cg = c & 7;
            uint32_t off = (uint32_t)(row * 128 + cg * 16);
            uint32_t swo = off ^ ((off >> 3) & 0x70);
            const __half* src = (cg < 4)
                ? (Ahi + (size_t)(m0 + row) * K + k0 + cg * 8)
                : (Alo + (size_t)(m0 + row) * K + k0 + (cg - 4) * 8);
            cp_async16(stb + swo, src);
        }
        // B: 512 chunks (4/row), 64B rows, sw64 xor
        #pragma unroll
        for (int i = 0; i < 2; i++) {
            int c = t + i * 256;
            int row = c >> 2, cg = c & 3;
            uint32_t off = (uint32_t)(row * 64 + cg * 16);
            uint32_t swo = off ^ ((off >> 3) & 0x30);
            cp_async16(stb + 16384 + swo,
                       Bhi + (size_t)(n0 + row) * K + k0 + cg * 8);
        }
        cp_commit();
    };

    issue(0, 0);
    issue(1, 1);
    int s = 0;
    for (int it = 0; it < niter; it++) {
        if (it + 1 < niter) cp_wait<1>(); else cp_wait<0>();
        __syncthreads();
        if (it + 2 < niter) {
            int s2 = s + 2; if (s2 >= 3) s2 -= 3;
            issue(it + 2, s2);
        }

        uint32_t sA = sb + (uint32_t)s * GSTAGE;
        uint32_t sB = sA + 16384;

        #pragma unroll
        for (int ks = 0; ks < 2; ks++) {
            uint32_t ah = ((uint32_t)(ks * 32) + ccol) ^ xv;        // A hi
            uint32_t al = ((uint32_t)(64 + ks * 32) + ccol) ^ xv;   // A lo
            uint32_t bc = ((uint32_t)(ks * 32) + ccol) ^ xb;        // B hi
            uint32_t afh[2][4], afl[2][4];
            #pragma unroll
            for (int mf = 0; mf < 2; mf++) {
                uint32_t rb = (uint32_t)((wm * 32 + mf * 16 + arow) * 128);
                ldsm_x4(afh[mf], sA + rb + ah);
                ldsm_x4(afl[mf], sA + rb + al);
            }
            #pragma unroll
            for (int nfp = 0; nfp < 4; nfp++) {
                uint32_t rb = (uint32_t)((wn * 64 + nfp * 16 + arow) * 64);
                uint32_t b4[4];
                ldsm_x4(b4, sB + rb + bc);
                #pragma unroll
                for (int mf = 0; mf < 2; mf++) {
                    mma16816(acc[mf][2 * nfp],     afh[mf], b4[0], b4[2]);
                    mma16816(acc[mf][2 * nfp],     afl[mf], b4[0], b4[2]);
                    mma16816(acc[mf][2 * nfp + 1], afh[mf], b4[1], b4[3]);
                    mma16816(acc[mf][2 * nfp + 1], afl[mf], b4[1], b4[3]);
                }
            }
        }
        if (++s >= 3) s -= 3;
    }

    #pragma unroll
    for (int mf = 0; mf < 2; mf++) {
        #pragma unroll
        for (int nf = 0; nf < 8; nf++) {
            int row = m0 + wm * 32 + mf * 16 + qrow;
            int col = n0 + wn * 64 + nf * 8 + qk;
            float bv0, bv1;
            if (mode == 0) {
                bv0 = (col < C_) ? bias_q[col]
                    : ((col < 2 * C_) ? 0.f : bias_v[col - 2 * C_]);
                bv1 = (col + 1 < C_) ? bias_q[col + 1]
                    : ((col + 1 < 2 * C_) ? 0.f : bias_v[col + 1 - 2 * C_]);
            } else {
                bv0 = bias_q[col];
                bv1 = bias_q[col + 1];
            }
            *(float2*)(Cm + (size_t)row * N + col) =
                make_float2(acc[mf][nf][0] + bv0, acc[mf][nf][1] + bv1);
            *(float2*)(Cm + (size_t)(row + 8) * N + col) =
                make_float2(acc[mf][nf][2] + bv0, acc[mf][nf][3] + bv1);
        }
    }
}

// ---------------------------------------------------------------------------
// Transform: l2norm(+scale) + RoPE; q -> fp16 hi/lo, k/v -> fp16 hi.
// ---------------------------------------------------------------------------
__global__ __launch_bounds__(256) void transform_kernel(
    const float* __restrict__ freqs, const float* __restrict__ sml)
{
    int w    = blockIdx.x * 8 + (threadIdx.x >> 5);
    int lane = threadIdx.x & 31;
    int h = w & 15;
    int l = (w >> 4) & 1023;
    int b = w >> 14;

    const float* base = g_qkv + (size_t)(b * L_ + l) * (3 * C_);
    float2 q2 = ((const float2*)(base + 0 * C_ + h * D_))[lane];
    float2 k2 = ((const float2*)(base + 1 * C_ + h * D_))[lane];
    float2 v2 = ((const float2*)(base + 2 * C_ + h * D_))[lane];

    float qs = q2.x * q2.x + q2.y * q2.y;
    float ks = k2.x * k2.x + k2.y * k2.y;
    #pragma unroll
    for (int o = 16; o > 0; o >>= 1) {
        qs += __shfl_xor_sync(0xffffffffu, qs, o);
        ks += __shfl_xor_sync(0xffffffffu, ks, o);
    }
    float qinv = expf(fminf(sml[h], MAXSC)) / fmaxf(sqrtf(qs), 1e-12f);
    float kinv = 1.f / fmaxf(sqrtf(ks), 1e-12f);

    float2 fc = ((const float2*)(freqs + l * D_))[lane];
    float qx = q2.x * qinv, qy = q2.y * qinv;
    float kx = k2.x * kinv, ky = k2.y * kinv;
    float qox = qx * fc.x - qy * fc.y, qoy = qx * fc.y + qy * fc.x;
    float kox = kx * fc.x - ky * fc.y, koy = kx * fc.y + ky * fc.x;

    size_t oidx = (size_t)((b * H_ + h) * L_ + l) * D_;
    float qhx = __half2float(__float2half_rn(qox));
    float qhy = __half2float(__float2half_rn(qoy));
    ((uint32_t*)(g_qh + oidx))[lane] = pack_f16(qox, qoy);
    ((uint32_t*)(g_ql + oidx))[lane] = pack_f16(qox - qhx, qoy - qhy);
    ((uint32_t*)(g_kh + oidx))[lane] = pack_f16(kox, koy);
    ((uint32_t*)(g_vh + oidx))[lane] = pack_f16(v2.x, v2.y);
}

// ---------------------------------------------------------------------------
// Flash attention, fp16 HMMA: Q 2-term, K/V 1-term. 2-stage cp.async.
// Stage: K tile 64x128B + V tile 64x128B = 16KB (SW128).
// ---------------------------------------------------------------------------
#define ASTAGE 16384
__global__ __launch_bounds__(128) void attn_mma_kernel(
    const float* __restrict__ bias)
{
    extern __shared__ __align__(16) char asmem[];
    uint32_t sbase = smem_u32(asmem);

    int t = threadIdx.x;
    int wid = t >> 5, lane = t & 31;
    int q0 = blockIdx.x * 64;
    int bh = blockIdx.y;
    int b = bh >> 4, h = bh & 15;

    const __half* Qh = g_qh + (size_t)bh * L_ * D_;
    const __half* Ql = g_ql + (size_t)bh * L_ * D_;
    const __half* Kh = g_kh + (size_t)bh * L_ * D_;
    const __half* Vh = g_vh + (size_t)bh * L_ * D_;

    int rA = q0 + wid * 16 + (lane >> 2);
    int c0 = (lane & 3) * 2;

    uint32_t qa_h[4][4], qa_l[4][4];
    #pragma unroll
    for (int kf = 0; kf < 4; kf++) {
        int cb = kf * 16 + c0;
        qa_h[kf][0] = *(const uint32_t*)(Qh + (size_t)rA * D_ + cb);
        qa_h[kf][1] = *(const uint32_t*)(Qh + (size_t)(rA + 8) * D_ + cb);
        qa_h[kf][2] = *(const uint32_t*)(Qh + (size_t)rA * D_ + cb + 8);
        qa_h[kf][3] = *(const uint32_t*)(Qh + (size_t)(rA + 8) * D_ + cb + 8);
        qa_l[kf][0] = *(const uint32_t*)(Ql + (size_t)rA * D_ + cb);
        qa_l[kf][1] = *(const uint32_t*)(Ql + (size_t)(rA + 8) * D_ + cb);
        qa_l[kf][2] = *(const uint32_t*)(Ql + (size_t)rA * D_ + cb + 8);
        qa_l[kf][3] = *(const uint32_t*)(Ql + (size_t)(rA + 8) * D_ + cb + 8);
    }

    float m0 = -CUDART_INF_F, m1 = -CUDART_INF_F;
    float l0 = 0.f, l1 = 0.f;
    float oacc[8][4];
    #pragma unroll
    for (int nf = 0; nf < 8; nf++)
        #pragma unroll
        for (int u = 0; u < 4; u++) oacc[nf][u] = 0.f;

    int g = lane >> 3, r8 = lane & 7;
    uint32_t xv = (uint32_t)(r8 << 4);
    // K (non-trans): row = nfp*16 + (g>>1)*8 + r8 ; col = kf*32 + (g&1)*16
    uint32_t krow = (uint32_t)((g >> 1) * 8 + r8);
    uint32_t kcol = (uint32_t)((g & 1) * 16);
    // V (trans): row = kf*16 + (g&1)*8 + r8 ; col = nfp*32 + (g>>1)*16
    uint32_t vrow = (uint32_t)((g & 1) * 8 + r8);
    uint32_t vcol = (uint32_t)((g >> 1) * 16);

    const float* brow0 = bias + (size_t)rA * L_;
    const float* brow1 = bias + (size_t)(rA + 8) * L_;

    auto issue_kv = [&](int k0, int s) {
        uint32_t stb = sbase + (uint32_t)s * ASTAGE;
        #pragma unroll
        for (int i = 0; i < 4; i++) {
            int c = t + i * 128;
            int row = c >> 3, cg = c & 7;
            uint32_t off = (uint32_t)(row * 128 + cg * 16);
            uint32_t swo = off ^ ((off >> 3) & 0x70);
            size_t gsrc = (size_t)(k0 + row) * D_ + cg * 8;
            cp_async16(stb + swo,        Kh + gsrc);
            cp_async16(stb + 8192 + swo, Vh + gsrc);
        }
        cp_commit();
    };

    issue_kv(0, 0);
    const int NIT = L_ / 64;
    for (int ki = 0; ki < NIT; ki++) {
        int s = ki & 1;
        if (ki + 1 < NIT) { issue_kv((ki + 1) * 64, s ^ 1); cp_wait<1>(); }
        else              { cp_wait<0>(); }
        __syncthreads();

        uint32_t sk = sbase + (uint32_t)s * ASTAGE;
        uint32_t sv = sk + 8192;
        int k0 = ki * 64;

        float sacc[8][4];
        #pragma unroll
        for (int nf = 0; nf < 8; nf++)
            #pragma unroll
            for (int u = 0; u < 4; u++) sacc[nf][u] = 0.f;

        #pragma unroll
        for (int nfp = 0; nfp < 4; nfp++) {
            #pragma unroll
            for (int kf = 0; kf < 4; kf++) {
                uint32_t addr = sk + (uint32_t)((nfp * 16 + krow) * 128)
                              + (((uint32_t)(kf * 32) + kcol) ^ xv);
                uint32_t kb4[4];
                ldsm_x4(kb4, addr);
                mma16816(sacc[2 * nfp],     qa_h[kf], kb4[0], kb4[1]);
                mma16816(sacc[2 * nfp],     qa_l[kf], kb4[0], kb4[1]);
                mma16816(sacc[2 * nfp + 1], qa_h[kf], kb4[2], kb4[3]);
                mma16816(sacc[2 * nfp + 1], qa_l[kf], kb4[2], kb4[3]);
            }
        }

        #pragma unroll
        for (int nf = 0; nf < 8; nf++) {
            int kc = k0 + nf * 8 + c0;
            float2 b0 = *(const float2*)(brow0 + kc);
            float2 b1 = *(const float2*)(brow1 + kc);
            sacc[nf][0] += b0.x; sacc[nf][1] += b0.y;
            sacc[nf][2] += b1.x; sacc[nf][3] += b1.y;
        }

        float mx0 = -CUDART_INF_F, mx1 = -CUDART_INF_F;
        #pragma unroll
        for (int nf = 0; nf < 8; nf++) {
            mx0 = fmaxf(mx0, fmaxf(sacc[nf][0], sacc[nf][1]));
            mx1 = fmaxf(mx1, fmaxf(sacc[nf][2], sacc[nf][3]));
        }
        mx0 = fmaxf(mx0, __shfl_xor_sync(0xffffffffu, mx0, 1));
        mx0 = fmaxf(mx0, __shfl_xor_sync(0xffffffffu, mx0, 2));
        mx1 = fmaxf(mx1, __shfl_xor_sync(0xffffffffu, mx1, 1));
        mx1 = fmaxf(mx1, __shfl_xor_sync(0xffffffffu, mx1, 2));

        float mn0 = fmaxf(m0, mx0), mn1 = fmaxf(m1, mx1);
        float cr0 = __expf(m0 - mn0), cr1 = __expf(m1 - mn1);
        float rs0 = 0.f, rs1 = 0.f;
        #pragma unroll
        for (int nf = 0; nf < 8; nf++) {
            sacc[nf][0] = __expf(sacc[nf][0] - mn0);
            sacc[nf][1] = __expf(sacc[nf][1] - mn0);
            sacc[nf][2] = __expf(sacc[nf][2] - mn1);
            sacc[nf][3] = __expf(sacc[nf][3] - mn1);
            rs0 += sacc[nf][0] + sacc[nf][1];
            rs1 += sacc[nf][2] + sacc[nf][3];
        }
        rs0 += __shfl_xor_sync(0xffffffffu, rs0, 1);
        rs0 += __shfl_xor_sync(0xffffffffu, rs0, 2);
        rs1 += __shfl_xor_sync(0xffffffffu, rs1, 1);
        rs1 += __shfl_xor_sync(0xffffffffu, rs1, 2);
        l0 = l0 * cr0 + rs0;
        l1 = l1 * cr1 + rs1;
        m0 = mn0; m1 = mn1;

        #pragma unroll
        for (int nf = 0; nf < 8; nf++) {
            oacc[nf][0] *= cr0; oacc[nf][1] *= cr0;
            oacc[nf][2] *= cr1; oacc[nf][3] *= cr1;
        }

        uint32_t pa_h[4][4], pa_l[4][4];
        #pragma unroll
        for (int kf = 0; kf < 4; kf++) {
            #pragma unroll
            for (int half = 0; half < 2; half++) {
                int nf = 2 * kf + half;
                float p0 = sacc[nf][0], p1 = sacc[nf][1];
                float p2 = sacc[nf][2], p3 = sacc[nf][3];
                uint32_t hi01 = pack_f16(p0, p1);
                uint32_t hi23 = pack_f16(p2, p3);
                __half2 h01 = *(__half2*)&hi01;
                __half2 h23 = *(__half2*)&hi23;
                uint32_t lo01 = pack_f16(p0 - __half2float(h01.x),
                                         p1 - __half2float(h01.y));
                uint32_t lo23 = pack_f16(p2 - __half2float(h23.x),
                                         p3 - __half2float(h23.y));
                pa_h[kf][2 * half]     = hi01;
                pa_h[kf][2 * half + 1] = hi23;
                pa_l[kf][2 * half]     = lo01;
                pa_l[kf][2 * half + 1] = lo23;
            }
        }

        #pragma unroll
        for (int nfp = 0; nfp < 4; nfp++) {
            #pragma unroll
            for (int kf = 0; kf < 4; kf++) {
                uint32_t addr = sv + (uint32_t)((kf * 16 + vrow) * 128)
                              + (((uint32_t)(nfp * 32) + vcol) ^ xv);
                uint32_t vb4[4];
                ldsm_x4_t(vb4, addr);
                mma16816(oacc[2 * nfp],     pa_h[kf], vb4[0], vb4[1]);
                mma16816(oacc[2 * nfp],     pa_l[kf], vb4[0], vb4[1]);
                mma16816(oacc[2 * nfp + 1], pa_h[kf], vb4[2], vb4[3]);
                mma16816(oacc[2 * nfp + 1], pa_l[kf], vb4[2], vb4[3]);
            }
        }
        __syncthreads();
    }

    float inv0 = 1.f / l0, inv1 = 1.f / l1;
    size_t orow0 = (size_t)(b * L_ + rA) * C_ + h * D_;
    size_t orow1 = (size_t)(b * L_ + rA + 8) * C_ + h * D_;
    #pragma unroll
    for (int nf = 0; nf < 8; nf++) {
        int d = nf * 8 + c0;
        float v0 = oacc[nf][0] * inv0, v1 = oacc[nf][1] * inv0;
        float v2 = oacc[nf][2] * inv1, v3 = oacc[nf][3] * inv1;
        uint32_t h01 = pack_f16(v0, v1);
        uint32_t h23 = pack_f16(v2, v3);
        __half2 b01 = *(__half2*)&h01;
        __half2 b23 = *(__half2*)&h23;
        uint32_t l01 = pack_f16(v0 - __half2float(b01.x),
                                v1 - __half2float(b01.y));
        uint32_t l23 = pack_f16(v2 - __half2float(b23.x),
                                v3 - __half2float(b23.y));
        *(uint32_t*)(g_aoh + orow0 + d) = h01;
        *(uint32_t*)(g_aol + orow0 + d) = l01;
        *(uint32_t*)(g_aoh + orow1 + d) = h23;
        *(uint32_t*)(g_aol + orow1 + d) = l23;
    }
}

// ---------------------------------------------------------------------------
extern "C" void kernel_launch(void* const* d_in, const int* in_sizes, int n_in,
                              void* d_out, int out_size)
{
    const float* x         = (const float*)d_in[0];
    const float* freqs     = (const float*)d_in[1];
    const float* attn_bias = (const float*)d_in[2];
    const float* W_qkv     = (const float*)d_in[3];
    const float* q_bias    = (const float*)d_in[4];
    const float* v_bias    = (const float*)d_in[5];
    const float* sml       = (const float*)d_in[6];
    const float* W_proj    = (const float*)d_in[7];
    const float* b_proj    = (const float*)d_in[8];
    float* out = (float*)d_out;

    void* p;
    cudaGetSymbolAddress(&p, g_qkv); float* qkv = (float*)p;
    cudaGetSymbolAddress(&p, g_xhi); __half* xhi = (__half*)p;
    cudaGetSymbolAddress(&p, g_xlo); __half* xlo = (__half*)p;
    cudaGetSymbolAddress(&p, g_wqh); __half* wqh = (__half*)p;
    cudaGetSymbolAddress(&p, g_wph); __half* wph = (__half*)p;
    cudaGetSymbolAddress(&p, g_aoh); __half* aoh = (__half*)p;
    cudaGetSymbolAddress(&p, g_aol); __half* aol = (__half*)p;

    int gsm = 3 * GSTAGE;      // 73728
    int asm_ = 2 * ASTAGE;     // 32768
    static bool attr_set = false;
    if (!attr_set) {
        cudaFuncSetAttribute(gemm_mma_kernel,
                             cudaFuncAttributeMaxDynamicSharedMemorySize, gsm);
        cudaFuncSetAttribute(attn_mma_kernel,
                             cudaFuncAttributeMaxDynamicSharedMemorySize, asm_);
        attr_set = true;
    }

    conv_split_kernel<<<(B_ * L_ * C_ / 4 + 255) / 256, 256>>>(x, xhi, xlo, B_ * L_ * C_ / 4);
    conv_hi_kernel<<<(3 * C_ * C_ / 4 + 255) / 256, 256>>>(W_qkv, wqh, 3 * C_ * C_ / 4);
    conv_hi_kernel<<<(C_ * C_ / 4 + 255) / 256, 256>>>(W_proj, wph, C_ * C_ / 4);

    gemm_mma_kernel<<<dim3(3 * C_ / 128, B_ * L_ / 128), 256, gsm>>>(
        xhi, xlo, wqh, qkv, q_bias, v_bias, 3 * C_, C_, 0);

    transform_kernel<<<(B_ * L_ * H_) / 8, 256>>>(freqs, sml);

    attn_mma_kernel<<<dim3(L_ / 64, B_ * H_), 128, asm_>>>(attn_bias);

    gemm_mma_kernel<<<dim3(C_ / 128, B_ * L_ / 128), 256, gsm>>>(
        aoh, aol, wph, out, b_proj, nullptr, C_, C_, 1);
}

// round 11
// speedup vs baseline: 1.5830x; 1.0171x over previous
#include <cuda_runtime.h>
#include <cuda_fp16.h>
#include <math_constants.h>
#include <cstdint>
#include <cstddef>

#define B_ 8
#define L_ 1024
#define C_ 1024
#define H_ 16
#define D_ 64
#define MAXSC 4.6051701859880914f  // log(100)

// ---------------------------------------------------------------------------
// Scratch (bss, no runtime allocation)
// ---------------------------------------------------------------------------
__device__ float g_qkv[B_ * L_ * 3 * C_];

__device__ __half g_xhi[B_ * L_ * C_];
__device__ __half g_xlo[B_ * L_ * C_];
__device__ __half g_wqh[3 * C_ * C_];
__device__ __half g_wph[C_ * C_];

__device__ __half g_qh[B_ * H_ * L_ * D_];
__device__ __half g_ql[B_ * H_ * L_ * D_];
__device__ __half g_kh[B_ * H_ * L_ * D_];
__device__ __half g_vh[B_ * H_ * L_ * D_];

__device__ __half g_aoh[B_ * L_ * C_];
__device__ __half g_aol[B_ * L_ * C_];

// ---------------------------------------------------------------------------
// Helpers
// ---------------------------------------------------------------------------
__device__ __forceinline__ uint32_t smem_u32(const void* p) {
    uint32_t a;
    asm("{ .reg .u64 t; cvta.to.shared.u64 t, %1; cvt.u32.u64 %0, t; }"
        : "=r"(a) : "l"(p));
    return a;
}

__device__ __forceinline__ void mma16816(float* c, const uint32_t* a,
                                         uint32_t b0, uint32_t b1)
{
    asm volatile(
        "mma.sync.aligned.m16n8k16.row.col.f32.f16.f16.f32 "
        "{%0,%1,%2,%3}, {%4,%5,%6,%7}, {%8,%9}, {%0,%1,%2,%3};"
        : "+f"(c[0]), "+f"(c[1]), "+f"(c[2]), "+f"(c[3])
        : "r"(a[0]), "r"(a[1]), "r"(a[2]), "r"(a[3]), "r"(b0), "r"(b1));
}

__device__ __forceinline__ void ldsm_x4(uint32_t* r, uint32_t addr) {
    asm volatile("ldmatrix.sync.aligned.m8n8.x4.shared.b16 {%0,%1,%2,%3}, [%4];"
        : "=r"(r[0]), "=r"(r[1]), "=r"(r[2]), "=r"(r[3]) : "r"(addr));
}
__device__ __forceinline__ void ldsm_x4_t(uint32_t* r, uint32_t addr) {
    asm volatile("ldmatrix.sync.aligned.m8n8.x4.trans.shared.b16 {%0,%1,%2,%3}, [%4];"
        : "=r"(r[0]), "=r"(r[1]), "=r"(r[2]), "=r"(r[3]) : "r"(addr));
}

__device__ __forceinline__ uint32_t pack_f16(float a, float b) {
    __half2 t = __floats2half2_rn(a, b);
    return *(uint32_t*)&t;
}

__device__ __forceinline__ void cp_async16(uint32_t saddr, const void* gptr) {
    asm volatile("cp.async.cg.shared.global [%0], [%1], 16;"
        :: "r"(saddr), "l"(gptr) : "memory");
}
__device__ __forceinline__ void cp_commit() {
    asm volatile("cp.async.commit_group;" ::: "memory");
}
template <int N>
__device__ __forceinline__ void cp_wait() {
    asm volatile("cp.async.wait_group %0;" :: "n"(N) : "memory");
}

// ---------------------------------------------------------------------------
// fp32 -> (hi, lo) fp16 split / hi-only
// ---------------------------------------------------------------------------
__global__ __launch_bounds__(256) void conv_split_kernel(
    const float* __restrict__ src, __half* __restrict__ hi,
    __half* __restrict__ lo, int n4)
{
    int i = blockIdx.x * blockDim.x + threadIdx.x;
    if (i >= n4) return;
    float4 v = ((const float4*)src)[i];
    __half h0 = __float2half_rn(v.x);
    __half h1 = __float2half_rn(v.y);
    __half h2 = __float2half_rn(v.z);
    __half h3 = __float2half_rn(v.w);
    __half l0 = __float2half_rn(v.x - __half2float(h0));
    __half l1 = __float2half_rn(v.y - __half2float(h1));
    __half l2 = __float2half_rn(v.z - __half2float(h2));
    __half l3 = __float2half_rn(v.w - __half2float(h3));
    ((__half2*)hi)[2 * i]     = __half2(h0, h1);
    ((__half2*)hi)[2 * i + 1] = __half2(h2, h3);
    ((__half2*)lo)[2 * i]     = __half2(l0, l1);
    ((__half2*)lo)[2 * i + 1] = __half2(l2, l3);
}

__global__ __launch_bounds__(256) void conv_hi_kernel(
    const float* __restrict__ src, __half* __restrict__ hi, int n4)
{
    int i = blockIdx.x * blockDim.x + threadIdx.x;
    if (i >= n4) return;
    float4 v = ((const float4*)src)[i];
    ((__half2*)hi)[2 * i]     = __floats2half2_rn(v.x, v.y);
    ((__half2*)hi)[2 * i + 1] = __floats2half2_rn(v.z, v.w);
}

// ---------------------------------------------------------------------------
// HMMA GEMM: C = A*B^T + bias.  A fp16 2-term (hi+lo), B fp16 hi-only.
// K-chunk 64, 2-stage cp.async pipeline.
// Stage: A 128 rows x 256B (hi 128B | lo 128B) = 32KB + B 128 rows x 128B
// = 16KB  ->  48KB/stage.  Row-XOR swizzle keeps ldmatrix conflict-free.
// ---------------------------------------------------------------------------
#define GSTAGE 49152
__global__ __launch_bounds__(256, 2) void gemm_mma_kernel(
    const __half* __restrict__ Ahi, const __half* __restrict__ Alo,
    const __half* __restrict__ Bhi,
    float* __restrict__ Cm,
    const float* __restrict__ bias_q, const float* __restrict__ bias_v,
    int N, int K, int mode)
{
    extern __shared__ __align__(16) char smc[];
    uint32_t sb = smem_u32(smc);
    int t = threadIdx.x;
    int wid = t >> 5, lane = t & 31;
    int wm = wid & 3, wn = wid >> 2;
    int m0 = blockIdx.y * 128, n0 = blockIdx.x * 128;

    float acc[2][8][4];
    #pragma unroll
    for (int i = 0; i < 2; i++)
        #pragma unroll
        for (int j = 0; j < 8; j++)
            #pragma unroll
            for (int u = 0; u < 4; u++) acc[i][j][u] = 0.f;

    int qrow = lane >> 2;
    int qk   = (lane & 3) * 2;
    int g = lane >> 3, r8 = lane & 7;
    int arow = (g & 1) * 8 + r8;
    uint32_t xv = (uint32_t)(r8 << 4);
    uint32_t ccol = (uint32_t)((g >> 1) * 16);
    const int niter = K >> 6;

    auto issue = [&](int it, int s) {
        int k0 = it << 6;
        uint32_t stb = sb + (uint32_t)s * GSTAGE;
        // A: 2048 chunks (16/row: 8 hi + 8 lo), 256B rows, row-XOR swizzle
        #pragma unroll
        for (int i = 0; i < 8; i++) {
            int c = t + i * 256;
            int row = c >> 4, cg = c & 15;
            uint32_t swo = (uint32_t)(row * 256 + cg * 16) ^ ((uint32_t)(row & 7) << 4);
            const __half* src = (cg < 8)
                ? (Ahi + (size_t)(m0 + row) * K + k0 + cg * 8)
                : (Alo + (size_t)(m0 + row) * K + k0 + (cg - 8) * 8);
            cp_async16(stb + swo, src);
        }
        // B: 1024 chunks (8/row), 128B rows, SW128
        #pragma unroll
        for (int i = 0; i < 4; i++) {
            int c = t + i * 256;
            int row = c >> 3, cg = c & 7;
            uint32_t off = (uint32_t)(row * 128 + cg * 16);
            uint32_t swo = off ^ ((off >> 3) & 0x70);
            cp_async16(stb + 32768 + swo,
                       Bhi + (size_t)(n0 + row) * K + k0 + cg * 8);
        }
        cp_commit();
    };

    issue(0, 0);
    for (int it = 0; it < niter; it++) {
        int s = it & 1;
        cp_wait<0>();
        __syncthreads();
        if (it + 1 < niter) issue(it + 1, s ^ 1);

        uint32_t sA = sb + (uint32_t)s * GSTAGE;
        uint32_t sB = sA + 32768;

        #pragma unroll
        for (int ks = 0; ks < 4; ks++) {
            uint32_t ah = ((uint32_t)(ks * 32) + ccol) ^ xv;         // A hi
            uint32_t al = ((uint32_t)(128 + ks * 32) + ccol) ^ xv;   // A lo
            uint32_t bc = ((uint32_t)(ks * 32) + ccol) ^ xv;         // B
            uint32_t afh[2][4], afl[2][4];
            #pragma unroll
            for (int mf = 0; mf < 2; mf++) {
                uint32_t rb = (uint32_t)((wm * 32 + mf * 16 + arow) * 256);
                ldsm_x4(afh[mf], sA + rb + ah);
                ldsm_x4(afl[mf], sA + rb + al);
            }
            #pragma unroll
            for (int nfp = 0; nfp < 4; nfp++) {
                uint32_t rb = (uint32_t)((wn * 64 + nfp * 16 + arow) * 128);
                uint32_t b4[4];
                ldsm_x4(b4, sB + rb + bc);
                #pragma unroll
                for (int mf = 0; mf < 2; mf++) {
                    mma16816(acc[mf][2 * nfp],     afh[mf], b4[0], b4[2]);
                    mma16816(acc[mf][2 * nfp],     afl[mf], b4[0], b4[2]);
                    mma16816(acc[mf][2 * nfp + 1], afh[mf], b4[1], b4[3]);
                    mma16816(acc[mf][2 * nfp + 1], afl[mf], b4[1], b4[3]);
                }
            }
        }
    }

    #pragma unroll
    for (int mf = 0; mf < 2; mf++) {
        #pragma unroll
        for (int nf = 0; nf < 8; nf++) {
            int row = m0 + wm * 32 + mf * 16 + qrow;
            int col = n0 + wn * 64 + nf * 8 + qk;
            float bv0, bv1;
            if (mode == 0) {
                bv0 = (col < C_) ? bias_q[col]
                    : ((col < 2 * C_) ? 0.f : bias_v[col - 2 * C_]);
                bv1 = (col + 1 < C_) ? bias_q[col + 1]
                    : ((col + 1 < 2 * C_) ? 0.f : bias_v[col + 1 - 2 * C_]);
            } else {
                bv0 = bias_q[col];
                bv1 = bias_q[col + 1];
            }
            *(float2*)(Cm + (size_t)row * N + col) =
                make_float2(acc[mf][nf][0] + bv0, acc[mf][nf][1] + bv1);
            *(float2*)(Cm + (size_t)(row + 8) * N + col) =
                make_float2(acc[mf][nf][2] + bv0, acc[mf][nf][3] + bv1);
        }
    }
}

// ---------------------------------------------------------------------------
// Transform: l2norm(+scale) + RoPE; q -> fp16 hi/lo, k/v -> fp16 hi.
// ---------------------------------------------------------------------------
__global__ __launch_bounds__(256) void transform_kernel(
    const float* __restrict__ freqs, const float* __restrict__ sml)
{
    int w    = blockIdx.x * 8 + (threadIdx.x >> 5);
    int lane = threadIdx.x & 31;
    int h = w & 15;
    int l = (w >> 4) & 1023;
    int b = w >> 14;

    const float* base = g_qkv + (size_t)(b * L_ + l) * (3 * C_);
    float2 q2 = ((const float2*)(base + 0 * C_ + h * D_))[lane];
    float2 k2 = ((const float2*)(base + 1 * C_ + h * D_))[lane];
    float2 v2 = ((const float2*)(base + 2 * C_ + h * D_))[lane];

    float qs = q2.x * q2.x + q2.y * q2.y;
    float ks = k2.x * k2.x + k2.y * k2.y;
    #pragma unroll
    for (int o = 16; o > 0; o >>= 1) {
        qs += __shfl_xor_sync(0xffffffffu, qs, o);
        ks += __shfl_xor_sync(0xffffffffu, ks, o);
    }
    float qinv = expf(fminf(sml[h], MAXSC)) / fmaxf(sqrtf(qs), 1e-12f);
    float kinv = 1.f / fmaxf(sqrtf(ks), 1e-12f);

    float2 fc = ((const float2*)(freqs + l * D_))[lane];
    float qx = q2.x * qinv, qy = q2.y * qinv;
    float kx = k2.x * kinv, ky = k2.y * kinv;
    float qox = qx * fc.x - qy * fc.y, qoy = qx * fc.y + qy * fc.x;
    float kox = kx * fc.x - ky * fc.y, koy = kx * fc.y + ky * fc.x;

    size_t oidx = (size_t)((b * H_ + h) * L_ + l) * D_;
    float qhx = __half2float(__float2half_rn(qox));
    float qhy = __half2float(__float2half_rn(qoy));
    ((uint32_t*)(g_qh + oidx))[lane] = pack_f16(qox, qoy);
    ((uint32_t*)(g_ql + oidx))[lane] = pack_f16(qox - qhx, qoy - qhy);
    ((uint32_t*)(g_kh + oidx))[lane] = pack_f16(kox, koy);
    ((uint32_t*)(g_vh + oidx))[lane] = pack_f16(v2.x, v2.y);
}

// ---------------------------------------------------------------------------
// Flash attention, fp16 HMMA: Q 2-term, K/V 1-term. 3-stage cp.async.
// Stage: K tile 64x128B + V tile 64x128B = 16KB (SW128).
// ---------------------------------------------------------------------------
#define ASTAGE 16384
__global__ __launch_bounds__(128) void attn_mma_kernel(
    const float* __restrict__ bias)
{
    extern __shared__ __align__(16) char asmem[];
    uint32_t sbase = smem_u32(asmem);

    int t = threadIdx.x;
    int wid = t >> 5, lane = t & 31;
    int q0 = blockIdx.x * 64;
    int bh = blockIdx.y;
    int b = bh >> 4, h = bh & 15;

    const __half* Qh = g_qh + (size_t)bh * L_ * D_;
    const __half* Ql = g_ql + (size_t)bh * L_ * D_;
    const __half* Kh = g_kh + (size_t)bh * L_ * D_;
    const __half* Vh = g_vh + (size_t)bh * L_ * D_;

    int rA = q0 + wid * 16 + (lane >> 2);
    int c0 = (lane & 3) * 2;

    uint32_t qa_h[4][4], qa_l[4][4];
    #pragma unroll
    for (int kf = 0; kf < 4; kf++) {
        int cb = kf * 16 + c0;
        qa_h[kf][0] = *(const uint32_t*)(Qh + (size_t)rA * D_ + cb);
        qa_h[kf][1] = *(const uint32_t*)(Qh + (size_t)(rA + 8) * D_ + cb);
        qa_h[kf][2] = *(const uint32_t*)(Qh + (size_t)rA * D_ + cb + 8);
        qa_h[kf][3] = *(const uint32_t*)(Qh + (size_t)(rA + 8) * D_ + cb + 8);
        qa_l[kf][0] = *(const uint32_t*)(Ql + (size_t)rA * D_ + cb);
        qa_l[kf][1] = *(const uint32_t*)(Ql + (size_t)(rA + 8) * D_ + cb);
        qa_l[kf][2] = *(const uint32_t*)(Ql + (size_t)rA * D_ + cb + 8);
        qa_l[kf][3] = *(const uint32_t*)(Ql + (size_t)(rA + 8) * D_ + cb + 8);
    }

    float m0 = -CUDART_INF_F, m1 = -CUDART_INF_F;
    float l0 = 0.f, l1 = 0.f;
    float oacc[8][4];
    #pragma unroll
    for (int nf = 0; nf < 8; nf++)
        #pragma unroll
        for (int u = 0; u < 4; u++) oacc[nf][u] = 0.f;

    int g = lane >> 3, r8 = lane & 7;
    uint32_t xv = (uint32_t)(r8 << 4);
    uint32_t krow = (uint32_t)((g >> 1) * 8 + r8);
    uint32_t kcol = (uint32_t)((g & 1) * 16);
    uint32_t vrow = (uint32_t)((g & 1) * 8 + r8);
    uint32_t vcol = (uint32_t)((g >> 1) * 16);

    const float* brow0 = bias + (size_t)rA * L_;
    const float* brow1 = bias + (size_t)(rA + 8) * L_;

    auto issue_kv = [&](int k0, int s) {
        uint32_t stb = sbase + (uint32_t)s * ASTAGE;
        #pragma unroll
        for (int i = 0; i < 4; i++) {
            int c = t + i * 128;
            int row = c >> 3, cg = c & 7;
            uint32_t off = (uint32_t)(row * 128 + cg * 16);
            uint32_t swo = off ^ ((off >> 3) & 0x70);
            size_t gsrc = (size_t)(k0 + row) * D_ + cg * 8;
            cp_async16(stb + swo,        Kh + gsrc);
            cp_async16(stb + 8192 + swo, Vh + gsrc);
        }
        cp_commit();
    };

    issue_kv(0, 0);
    issue_kv(64, 1);
    const int NIT = L_ / 64;
    int s = 0;
    for (int ki = 0; ki < NIT; ki++) {
        if (ki + 1 < NIT) cp_wait<1>(); else cp_wait<0>();
        __syncthreads();
        if (ki + 2 < NIT) {
            int s2 = s + 2; if (s2 >= 3) s2 -= 3;
            issue_kv((ki + 2) * 64, s2);
        }

        uint32_t sk = sbase + (uint32_t)s * ASTAGE;
        uint32_t sv = sk + 8192;
        int k0 = ki * 64;

        float sacc[8][4];
        #pragma unroll
        for (int nf = 0; nf < 8; nf++)
            #pragma unroll
            for (int u = 0; u < 4; u++) sacc[nf][u] = 0.f;

        #pragma unroll
        for (int nfp = 0; nfp < 4; nfp++) {
            #pragma unroll
            for (int kf = 0; kf < 4; kf++) {
                uint32_t addr = sk + (uint32_t)((nfp * 16 + krow) * 128)
                              + (((uint32_t)(kf * 32) + kcol) ^ xv);
                uint32_t kb4[4];
                ldsm_x4(kb4, addr);
                mma16816(sacc[2 * nfp],     qa_h[kf], kb4[0], kb4[1]);
                mma16816(sacc[2 * nfp],     qa_l[kf], kb4[0], kb4[1]);
                mma16816(sacc[2 * nfp + 1], qa_h[kf], kb4[2], kb4[3]);
                mma16816(sacc[2 * nfp + 1], qa_l[kf], kb4[2], kb4[3]);
            }
        }

        #pragma unroll
        for (int nf = 0; nf < 8; nf++) {
            int kc = k0 + nf * 8 + c0;
            float2 b0 = *(const float2*)(brow0 + kc);
            float2 b1 = *(const float2*)(brow1 + kc);
            sacc[nf][0] += b0.x; sacc[nf][1] += b0.y;
            sacc[nf][2] += b1.x; sacc[nf][3] += b1.y;
        }

        float mx0 = -CUDART_INF_F, mx1 = -CUDART_INF_F;
        #pragma unroll
        for (int nf = 0; nf < 8; nf++) {
            mx0 = fmaxf(mx0, fmaxf(sacc[nf][0], sacc[nf][1]));
            mx1 = fmaxf(mx1, fmaxf(sacc[nf][2], sacc[nf][3]));
        }
        mx0 = fmaxf(mx0, __shfl_xor_sync(0xffffffffu, mx0, 1));
        mx0 = fmaxf(mx0, __shfl_xor_sync(0xffffffffu, mx0, 2));
        mx1 = fmaxf(mx1, __shfl_xor_sync(0xffffffffu, mx1, 1));
        mx1 = fmaxf(mx1, __shfl_xor_sync(0xffffffffu, mx1, 2));

        float mn0 = fmaxf(m0, mx0), mn1 = fmaxf(m1, mx1);
        float cr0 = __expf(m0 - mn0), cr1 = __expf(m1 - mn1);
        float rs0 = 0.f, rs1 = 0.f;
        #pragma unroll
        for (int nf = 0; nf < 8; nf++) {
            sacc[nf][0] = __expf(sacc[nf][0] - mn0);
            sacc[nf][1] = __expf(sacc[nf][1] - mn0);
            sacc[nf][2] = __expf(sacc[nf][2] - mn1);
            sacc[nf][3] = __expf(sacc[nf][3] - mn1);
            rs0 += sacc[nf][0] + sacc[nf][1];
            rs1 += sacc[nf][2] + sacc[nf][3];
        }
        rs0 += __shfl_xor_sync(0xffffffffu, rs0, 1);
        rs0 += __shfl_xor_sync(0xffffffffu, rs0, 2);
        rs1 += __shfl_xor_sync(0xffffffffu, rs1, 1);
        rs1 += __shfl_xor_sync(0xffffffffu, rs1, 2);
        l0 = l0 * cr0 + rs0;
        l1 = l1 * cr1 + rs1;
        m0 = mn0; m1 = mn1;

        #pragma unroll
        for (int nf = 0; nf < 8; nf++) {
            oacc[nf][0] *= cr0; oacc[nf][1] *= cr0;
            oacc[nf][2] *= cr1; oacc[nf][3] *= cr1;
        }

        uint32_t pa_h[4][4], pa_l[4][4];
        #pragma unroll
        for (int kf = 0; kf < 4; kf++) {
            #pragma unroll
            for (int half = 0; half < 2; half++) {
                int nf = 2 * kf + half;
                float p0 = sacc[nf][0], p1 = sacc[nf][1];
                float p2 = sacc[nf][2], p3 = sacc[nf][3];
                uint32_t hi01 = pack_f16(p0, p1);
                uint32_t hi23 = pack_f16(p2, p3);
                __half2 h01 = *(__half2*)&hi01;
                __half2 h23 = *(__half2*)&hi23;
                uint32_t lo01 = pack_f16(p0 - __half2float(h01.x),
                                         p1 - __half2float(h01.y));
                uint32_t lo23 = pack_f16(p2 - __half2float(h23.x),
                                         p3 - __half2float(h23.y));
                pa_h[kf][2 * half]     = hi01;
                pa_h[kf][2 * half + 1] = hi23;
                pa_l[kf][2 * half]     = lo01;
                pa_l[kf][2 * half + 1] = lo23;
            }
        }

        #pragma unroll
        for (int nfp = 0; nfp < 4; nfp++) {
            #pragma unroll
            for (int kf = 0; kf < 4; kf++) {
                uint32_t addr = sv + (uint32_t)((kf * 16 + vrow) * 128)
                              + (((uint32_t)(nfp * 32) + vcol) ^ xv);
                uint32_t vb4[4];
                ldsm_x4_t(vb4, addr);
                mma16816(oacc[2 * nfp],     pa_h[kf], vb4[0], vb4[1]);
                mma16816(oacc[2 * nfp],     pa_l[kf], vb4[0], vb4[1]);
                mma16816(oacc[2 * nfp + 1], pa_h[kf], vb4[2], vb4[3]);
                mma16816(oacc[2 * nfp + 1], pa_l[kf], vb4[2], vb4[3]);
            }
        }
        if (++s >= 3) s -= 3;
    }

    float inv0 = 1.f / l0, inv1 = 1.f / l1;
    size_t orow0 = (size_t)(b * L_ + rA) * C_ + h * D_;
    size_t orow1 = (size_t)(b * L_ + rA + 8) * C_ + h * D_;
    #pragma unroll
    for (int nf = 0; nf < 8; nf++) {
        int d = nf * 8 + c0;
        float v0 = oacc[nf][0] * inv0, v1 = oacc[nf][1] * inv0;
        float v2 = oacc[nf][2] * inv1, v3 = oacc[nf][3] * inv1;
        uint32_t h01 = pack_f16(v0, v1);
        uint32_t h23 = pack_f16(v2, v3);
        __half2 b01 = *(__half2*)&h01;
        __half2 b23 = *(__half2*)&h23;
        uint32_t l01 = pack_f16(v0 - __half2float(b01.x),
                                v1 - __half2float(b01.y));
        uint32_t l23 = pack_f16(v2 - __half2float(b23.x),
                                v3 - __half2float(b23.y));
        *(uint32_t*)(g_aoh + orow0 + d) = h01;
        *(uint32_t*)(g_aol + orow0 + d) = l01;
        *(uint32_t*)(g_aoh + orow1 + d) = h23;
        *(uint32_t*)(g_aol + orow1 + d) = l23;
    }
}

// ---------------------------------------------------------------------------
extern "C" void kernel_launch(void* const* d_in, const int* in_sizes, int n_in,
                              void* d_out, int out_size)
{
    const float* x         = (const float*)d_in[0];
    const float* freqs     = (const float*)d_in[1];
    const float* attn_bias = (const float*)d_in[2];
    const float* W_qkv     = (const float*)d_in[3];
    const float* q_bias    = (const float*)d_in[4];
    const float* v_bias    = (const float*)d_in[5];
    const float* sml       = (const float*)d_in[6];
    const float* W_proj    = (const float*)d_in[7];
    const float* b_proj    = (const float*)d_in[8];
    float* out = (float*)d_out;

    void* p;
    cudaGetSymbolAddress(&p, g_qkv); float* qkv = (float*)p;
    cudaGetSymbolAddress(&p, g_xhi); __half* xhi = (__half*)p;
    cudaGetSymbolAddress(&p, g_xlo); __half* xlo = (__half*)p;
    cudaGetSymbolAddress(&p, g_wqh); __half* wqh = (__half*)p;
    cudaGetSymbolAddress(&p, g_wph); __half* wph = (__half*)p;
    cudaGetSymbolAddress(&p, g_aoh); __half* aoh = (__half*)p;
    cudaGetSymbolAddress(&p, g_aol); __half* aol = (__half*)p;

    int gsm = 2 * GSTAGE;      // 98304
    int asm_ = 3 * ASTAGE;     // 49152
    static bool attr_set = false;
    if (!attr_set) {
        cudaFuncSetAttribute(gemm_mma_kernel,
                             cudaFuncAttributeMaxDynamicSharedMemorySize, gsm);
        cudaFuncSetAttribute(attn_mma_kernel,
                             cudaFuncAttributeMaxDynamicSharedMemorySize, asm_);
        attr_set = true;
    }

    conv_split_kernel<<<(B_ * L_ * C_ / 4 + 255) / 256, 256>>>(x, xhi, xlo, B_ * L_ * C_ / 4);
    conv_hi_kernel<<<(3 * C_ * C_ / 4 + 255) / 256, 256>>>(W_qkv, wqh, 3 * C_ * C_ / 4);
    conv_hi_kernel<<<(C_ * C_ / 4 + 255) / 256, 256>>>(W_proj, wph, C_ * C_ / 4);

    gemm_mma_kernel<<<dim3(3 * C_ / 128, B_ * L_ / 128), 256, gsm>>>(
        xhi, xlo, wqh, qkv, q_bias, v_bias, 3 * C_, C_, 0);

    transform_kernel<<<(B_ * L_ * H_) / 8, 256>>>(freqs, sml);

    attn_mma_kernel<<<dim3(L_ / 64, B_ * H_), 128, asm_>>>(attn_bias);

    gemm_mma_kernel<<<dim3(C_ / 128, B_ * L_ / 128), 256, gsm>>>(
        aoh, aol, wph, out, b_proj, nullptr, C_, C_, 1);
}

// round 12
// speedup vs baseline: 1.6307x; 1.0302x over previous
#include <cuda_runtime.h>
#include <cuda_fp16.h>
#include <math_constants.h>
#include <cstdint>
#include <cstddef>

#define B_ 8
#define L_ 1024
#define C_ 1024
#define H_ 16
#define D_ 64
#define MAXSC 4.6051701859880914f  // log(100)

// ---------------------------------------------------------------------------
// Scratch (bss, no runtime allocation)
// ---------------------------------------------------------------------------
__device__ __half g_xhi[B_ * L_ * C_];
__device__ __half g_xlo[B_ * L_ * C_];
__device__ __half g_wqh[3 * C_ * C_];
__device__ __half g_wph[C_ * C_];

__device__ __half g_qh[B_ * H_ * L_ * D_];
__device__ __half g_ql[B_ * H_ * L_ * D_];
__device__ __half g_kh[B_ * H_ * L_ * D_];
__device__ __half g_vh[B_ * H_ * L_ * D_];

__device__ __half g_aoh[B_ * L_ * C_];
__device__ __half g_aol[B_ * L_ * C_];

// ---------------------------------------------------------------------------
// Helpers
// ---------------------------------------------------------------------------
__device__ __forceinline__ uint32_t smem_u32(const void* p) {
    uint32_t a;
    asm("{ .reg .u64 t; cvta.to.shared.u64 t, %1; cvt.u32.u64 %0, t; }"
        : "=r"(a) : "l"(p));
    return a;
}

__device__ __forceinline__ void mma16816(float* c, const uint32_t* a,
                                         uint32_t b0, uint32_t b1)
{
    asm volatile(
        "mma.sync.aligned.m16n8k16.row.col.f32.f16.f16.f32 "
        "{%0,%1,%2,%3}, {%4,%5,%6,%7}, {%8,%9}, {%0,%1,%2,%3};"
        : "+f"(c[0]), "+f"(c[1]), "+f"(c[2]), "+f"(c[3])
        : "r"(a[0]), "r"(a[1]), "r"(a[2]), "r"(a[3]), "r"(b0), "r"(b1));
}

__device__ __forceinline__ void ldsm_x4(uint32_t* r, uint32_t addr) {
    asm volatile("ldmatrix.sync.aligned.m8n8.x4.shared.b16 {%0,%1,%2,%3}, [%4];"
        : "=r"(r[0]), "=r"(r[1]), "=r"(r[2]), "=r"(r[3]) : "r"(addr));
}
__device__ __forceinline__ void ldsm_x4_t(uint32_t* r, uint32_t addr) {
    asm volatile("ldmatrix.sync.aligned.m8n8.x4.trans.shared.b16 {%0,%1,%2,%3}, [%4];"
        : "=r"(r[0]), "=r"(r[1]), "=r"(r[2]), "=r"(r[3]) : "r"(addr));
}

__device__ __forceinline__ uint32_t pack_f16(float a, float b) {
    __half2 t = __floats2half2_rn(a, b);
    return *(uint32_t*)&t;
}

__device__ __forceinline__ void cp_async16(uint32_t saddr, const void* gptr) {
    asm volatile("cp.async.cg.shared.global [%0], [%1], 16;"
        :: "r"(saddr), "l"(gptr) : "memory");
}
__device__ __forceinline__ void cp_commit() {
    asm volatile("cp.async.commit_group;" ::: "memory");
}
template <int N>
__device__ __forceinline__ void cp_wait() {
    asm volatile("cp.async.wait_group %0;" :: "n"(N) : "memory");
}

// ---------------------------------------------------------------------------
// fp32 -> (hi, lo) fp16 split / hi-only
// ---------------------------------------------------------------------------
__global__ __launch_bounds__(256) void conv_split_kernel(
    const float* __restrict__ src, __half* __restrict__ hi,
    __half* __restrict__ lo, int n4)
{
    int i = blockIdx.x * blockDim.x + threadIdx.x;
    if (i >= n4) return;
    float4 v = ((const float4*)src)[i];
    __half h0 = __float2half_rn(v.x);
    __half h1 = __float2half_rn(v.y);
    __half h2 = __float2half_rn(v.z);
    __half h3 = __float2half_rn(v.w);
    __half l0 = __float2half_rn(v.x - __half2float(h0));
    __half l1 = __float2half_rn(v.y - __half2float(h1));
    __half l2 = __float2half_rn(v.z - __half2float(h2));
    __half l3 = __float2half_rn(v.w - __half2float(h3));
    ((__half2*)hi)[2 * i]     = __half2(h0, h1);
    ((__half2*)hi)[2 * i + 1] = __half2(h2, h3);
    ((__half2*)lo)[2 * i]     = __half2(l0, l1);
    ((__half2*)lo)[2 * i + 1] = __half2(l2, l3);
}

__global__ __launch_bounds__(256) void conv_hi_kernel(
    const float* __restrict__ src, __half* __restrict__ hi, int n4)
{
    int i = blockIdx.x * blockDim.x + threadIdx.x;
    if (i >= n4) return;
    float4 v = ((const float4*)src)[i];
    ((__half2*)hi)[2 * i]     = __floats2half2_rn(v.x, v.y);
    ((__half2*)hi)[2 * i + 1] = __floats2half2_rn(v.z, v.w);
}

// ---------------------------------------------------------------------------
// HMMA GEMM: A fp16 2-term, B fp16. K-chunk 64, 2-stage cp.async.
// mode 0 (QKV): fused epilogue -> l2norm + scale + RoPE -> g_qh/ql/kh/vh.
// mode 1 (proj): fp32 out + bias.
// ---------------------------------------------------------------------------
#define GSTAGE 49152
__global__ __launch_bounds__(256, 2) void gemm_mma_kernel(
    const __half* __restrict__ Ahi, const __half* __restrict__ Alo,
    const __half* __restrict__ Bhi,
    float* __restrict__ Cm,
    const float* __restrict__ bias_q, const float* __restrict__ bias_v,
    const float* __restrict__ freqs, const float* __restrict__ sml,
    int N, int K, int mode)
{
    extern __shared__ __align__(16) char smc[];
    uint32_t sb = smem_u32(smc);
    int t = threadIdx.x;
    int wid = t >> 5, lane = t & 31;
    int wm = wid & 3, wn = wid >> 2;
    int m0 = blockIdx.y * 128, n0 = blockIdx.x * 128;

    float acc[2][8][4];
    #pragma unroll
    for (int i = 0; i < 2; i++)
        #pragma unroll
        for (int j = 0; j < 8; j++)
            #pragma unroll
            for (int u = 0; u < 4; u++) acc[i][j][u] = 0.f;

    int qrow = lane >> 2;
    int qk   = (lane & 3) * 2;
    int g = lane >> 3, r8 = lane & 7;
    int arow = (g & 1) * 8 + r8;
    uint32_t xv = (uint32_t)(r8 << 4);
    uint32_t ccol = (uint32_t)((g >> 1) * 16);
    const int niter = K >> 6;

    auto issue = [&](int it, int s) {
        int k0 = it << 6;
        uint32_t stb = sb + (uint32_t)s * GSTAGE;
        #pragma unroll
        for (int i = 0; i < 8; i++) {
            int c = t + i * 256;
            int row = c >> 4, cg = c & 15;
            uint32_t swo = (uint32_t)(row * 256 + cg * 16) ^ ((uint32_t)(row & 7) << 4);
            const __half* src = (cg < 8)
                ? (Ahi + (size_t)(m0 + row) * K + k0 + cg * 8)
                : (Alo + (size_t)(m0 + row) * K + k0 + (cg - 8) * 8);
            cp_async16(stb + swo, src);
        }
        #pragma unroll
        for (int i = 0; i < 4; i++) {
            int c = t + i * 256;
            int row = c >> 3, cg = c & 7;
            uint32_t off = (uint32_t)(row * 128 + cg * 16);
            uint32_t swo = off ^ ((off >> 3) & 0x70);
            cp_async16(stb + 32768 + swo,
                       Bhi + (size_t)(n0 + row) * K + k0 + cg * 8);
        }
        cp_commit();
    };

    issue(0, 0);
    for (int it = 0; it < niter; it++) {
        int s = it & 1;
        cp_wait<0>();
        __syncthreads();
        if (it + 1 < niter) issue(it + 1, s ^ 1);

        uint32_t sA = sb + (uint32_t)s * GSTAGE;
        uint32_t sB = sA + 32768;

        #pragma unroll
        for (int ks = 0; ks < 4; ks++) {
            uint32_t ah = ((uint32_t)(ks * 32) + ccol) ^ xv;
            uint32_t al = ((uint32_t)(128 + ks * 32) + ccol) ^ xv;
            uint32_t bc = ((uint32_t)(ks * 32) + ccol) ^ xv;
            uint32_t afh[2][4], afl[2][4];
            #pragma unroll
            for (int mf = 0; mf < 2; mf++) {
                uint32_t rb = (uint32_t)((wm * 32 + mf * 16 + arow) * 256);
                ldsm_x4(afh[mf], sA + rb + ah);
                ldsm_x4(afl[mf], sA + rb + al);
            }
            #pragma unroll
            for (int nfp = 0; nfp < 4; nfp++) {
                uint32_t rb = (uint32_t)((wn * 64 + nfp * 16 + arow) * 128);
                uint32_t b4[4];
                ldsm_x4(b4, sB + rb + bc);
                #pragma unroll
                for (int mf = 0; mf < 2; mf++) {
                    mma16816(acc[mf][2 * nfp],     afh[mf], b4[0], b4[2]);
                    mma16816(acc[mf][2 * nfp],     afl[mf], b4[0], b4[2]);
                    mma16816(acc[mf][2 * nfp + 1], afh[mf], b4[1], b4[3]);
                    mma16816(acc[mf][2 * nfp + 1], afl[mf], b4[1], b4[3]);
                }
            }
        }
    }

    if (mode == 1) {
        #pragma unroll
        for (int mf = 0; mf < 2; mf++) {
            #pragma unroll
            for (int nf = 0; nf < 8; nf++) {
                int row = m0 + wm * 32 + mf * 16 + qrow;
                int col = n0 + wn * 64 + nf * 8 + qk;
                float bv0 = bias_q[col];
                float bv1 = bias_q[col + 1];
                *(float2*)(Cm + (size_t)row * N + col) =
                    make_float2(acc[mf][nf][0] + bv0, acc[mf][nf][1] + bv1);
                *(float2*)(Cm + (size_t)(row + 8) * N + col) =
                    make_float2(acc[mf][nf][2] + bv0, acc[mf][nf][3] + bv1);
            }
        }
        return;
    }

    // ---------------- mode 0: fused l2norm + scale + RoPE epilogue --------
    // region: 0=q, 1=k, 2=v ; warp wn owns exactly one head (64 cols).
    int region = blockIdx.x >> 3;
    int head   = ((blockIdx.x & 7) << 1) + wn;
    float smul = (region == 0) ? __expf(fminf(sml[head], MAXSC)) : 1.f;
    const float2* fr2 = (const float2*)freqs;

    #pragma unroll
    for (int mf = 0; mf < 2; mf++) {
        int r0 = m0 + wm * 32 + mf * 16 + qrow;      // global row A
        int bb = r0 >> 10;
        int lA = r0 & 1023, lB = lA + 8;
        size_t baseA = ((size_t)(bb * H_ + head) * L_ + lA) * D_;
        size_t baseB = baseA + 8 * D_;

        // add bias, accumulate row sums of squares (q/k only)
        float sA = 0.f, sB = 0.f;
        #pragma unroll
        for (int nf = 0; nf < 8; nf++) {
            int d = nf * 8 + qk;
            float bv0 = 0.f, bv1 = 0.f;
            if (region == 0) { bv0 = bias_q[head * D_ + d]; bv1 = bias_q[head * D_ + d + 1]; }
            if (region == 2) { bv0 = bias_v[head * D_ + d]; bv1 = bias_v[head * D_ + d + 1]; }
            acc[mf][nf][0] += bv0; acc[mf][nf][1] += bv1;
            acc[mf][nf][2] += bv0; acc[mf][nf][3] += bv1;
            if (region < 2) {
                sA += acc[mf][nf][0] * acc[mf][nf][0] + acc[mf][nf][1] * acc[mf][nf][1];
                sB += acc[mf][nf][2] * acc[mf][nf][2] + acc[mf][nf][3] * acc[mf][nf][3];
            }
        }

        if (region < 2) {
            sA += __shfl_xor_sync(0xffffffffu, sA, 1);
            sA += __shfl_xor_sync(0xffffffffu, sA, 2);
            sB += __shfl_xor_sync(0xffffffffu, sB, 1);
            sB += __shfl_xor_sync(0xffffffffu, sB, 2);
            float invA = smul / fmaxf(sqrtf(sA), 1e-12f);
            float invB = smul / fmaxf(sqrtf(sB), 1e-12f);

            #pragma unroll
            for (int nf = 0; nf < 8; nf++) {
                int d = nf * 8 + qk;
                float2 fA = fr2[lA * (D_ / 2) + (d >> 1)];
                float2 fB = fr2[lB * (D_ / 2) + (d >> 1)];
                float reA = acc[mf][nf][0] * invA, imA = acc[mf][nf][1] * invA;
                float reB = acc[mf][nf][2] * invB, imB = acc[mf][nf][3] * invB;
                float oA0 = reA * fA.x - imA * fA.y, oA1 = reA * fA.y + imA * fA.x;
                float oB0 = reB * fB.x - imB * fB.y, oB1 = reB * fB.y + imB * fB.x;
                if (region == 0) {
                    uint32_t hA = pack_f16(oA0, oA1);
                    uint32_t hB = pack_f16(oB0, oB1);
                    __half2 a2 = *(__half2*)&hA;
                    __half2 b2 = *(__half2*)&hB;
                    uint32_t lAp = pack_f16(oA0 - __half2float(a2.x),
                                            oA1 - __half2float(a2.y));
                    uint32_t lBp = pack_f16(oB0 - __half2float(b2.x),
                                            oB1 - __half2float(b2.y));
                    *(uint32_t*)(g_qh + baseA + d) = hA;
                    *(uint32_t*)(g_ql + baseA + d) = lAp;
                    *(uint32_t*)(g_qh + baseB + d) = hB;
                    *(uint32_t*)(g_ql + baseB + d) = lBp;
                } else {
                    *(uint32_t*)(g_kh + baseA + d) = pack_f16(oA0, oA1);
                    *(uint32_t*)(g_kh + baseB + d) = pack_f16(oB0, oB1);
                }
            }
        } else {
            #pragma unroll
            for (int nf = 0; nf < 8; nf++) {
                int d = nf * 8 + qk;
                *(uint32_t*)(g_vh + baseA + d) = pack_f16(acc[mf][nf][0], acc[mf][nf][1]);
                *(uint32_t*)(g_vh + baseB + d) = pack_f16(acc[mf][nf][2], acc[mf][nf][3]);
            }
        }
    }
}

// ---------------------------------------------------------------------------
// Flash attention, fp16 HMMA: Q 2-term, K/V 1-term. 3-stage cp.async.
// ---------------------------------------------------------------------------
#define ASTAGE 16384
__global__ __launch_bounds__(128) void attn_mma_kernel(
    const float* __restrict__ bias)
{
    extern __shared__ __align__(16) char asmem[];
    uint32_t sbase = smem_u32(asmem);

    int t = threadIdx.x;
    int wid = t >> 5, lane = t & 31;
    int q0 = blockIdx.x * 64;
    int bh = blockIdx.y;
    int b = bh >> 4, h = bh & 15;

    const __half* Qh = g_qh + (size_t)bh * L_ * D_;
    const __half* Ql = g_ql + (size_t)bh * L_ * D_;
    const __half* Kh = g_kh + (size_t)bh * L_ * D_;
    const __half* Vh = g_vh + (size_t)bh * L_ * D_;

    int rA = q0 + wid * 16 + (lane >> 2);
    int c0 = (lane & 3) * 2;

    uint32_t qa_h[4][4], qa_l[4][4];
    #pragma unroll
    for (int kf = 0; kf < 4; kf++) {
        int cb = kf * 16 + c0;
        qa_h[kf][0] = *(const uint32_t*)(Qh + (size_t)rA * D_ + cb);
        qa_h[kf][1] = *(const uint32_t*)(Qh + (size_t)(rA + 8) * D_ + cb);
        qa_h[kf][2] = *(const uint32_t*)(Qh + (size_t)rA * D_ + cb + 8);
        qa_h[kf][3] = *(const uint32_t*)(Qh + (size_t)(rA + 8) * D_ + cb + 8);
        qa_l[kf][0] = *(const uint32_t*)(Ql + (size_t)rA * D_ + cb);
        qa_l[kf][1] = *(const uint32_t*)(Ql + (size_t)(rA + 8) * D_ + cb);
        qa_l[kf][2] = *(const uint32_t*)(Ql + (size_t)rA * D_ + cb + 8);
        qa_l[kf][3] = *(const uint32_t*)(Ql + (size_t)(rA + 8) * D_ + cb + 8);
    }

    float m0 = -CUDART_INF_F, m1 = -CUDART_INF_F;
    float l0 = 0.f, l1 = 0.f;
    float oacc[8][4];
    #pragma unroll
    for (int nf = 0; nf < 8; nf++)
        #pragma unroll
        for (int u = 0; u < 4; u++) oacc[nf][u] = 0.f;

    int g = lane >> 3, r8 = lane & 7;
    uint32_t xv = (uint32_t)(r8 << 4);
    uint32_t krow = (uint32_t)((g >> 1) * 8 + r8);
    uint32_t kcol = (uint32_t)((g & 1) * 16);
    uint32_t vrow = (uint32_t)((g & 1) * 8 + r8);
    uint32_t vcol = (uint32_t)((g >> 1) * 16);

    const float* brow0 = bias + (size_t)rA * L_;
    const float* brow1 = bias + (size_t)(rA + 8) * L_;

    auto issue_kv = [&](int k0, int s) {
        uint32_t stb = sbase + (uint32_t)s * ASTAGE;
        #pragma unroll
        for (int i = 0; i < 4; i++) {
            int c = t + i * 128;
            int row = c >> 3, cg = c & 7;
            uint32_t off = (uint32_t)(row * 128 + cg * 16);
            uint32_t swo = off ^ ((off >> 3) & 0x70);
            size_t gsrc = (size_t)(k0 + row) * D_ + cg * 8;
            cp_async16(stb + swo,        Kh + gsrc);
            cp_async16(stb + 8192 + swo, Vh + gsrc);
        }
        cp_commit();
    };

    issue_kv(0, 0);
    issue_kv(64, 1);
    const int NIT = L_ / 64;
    int s = 0;
    for (int ki = 0; ki < NIT; ki++) {
        if (ki + 1 < NIT) cp_wait<1>(); else cp_wait<0>();
        __syncthreads();
        if (ki + 2 < NIT) {
            int s2 = s + 2; if (s2 >= 3) s2 -= 3;
            issue_kv((ki + 2) * 64, s2);
        }

        uint32_t sk = sbase + (uint32_t)s * ASTAGE;
        uint32_t sv = sk + 8192;
        int k0 = ki * 64;

        float sacc[8][4];
        #pragma unroll
        for (int nf = 0; nf < 8; nf++)
            #pragma unroll
            for (int u = 0; u < 4; u++) sacc[nf][u] = 0.f;

        #pragma unroll
        for (int nfp = 0; nfp < 4; nfp++) {
            #pragma unroll
            for (int kf = 0; kf < 4; kf++) {
                uint32_t addr = sk + (uint32_t)((nfp * 16 + krow) * 128)
                              + (((uint32_t)(kf * 32) + kcol) ^ xv);
                uint32_t kb4[4];
                ldsm_x4(kb4, addr);
                mma16816(sacc[2 * nfp],     qa_h[kf], kb4[0], kb4[1]);
                mma16816(sacc[2 * nfp],     qa_l[kf], kb4[0], kb4[1]);
                mma16816(sacc[2 * nfp + 1], qa_h[kf], kb4[2], kb4[3]);
                mma16816(sacc[2 * nfp + 1], qa_l[kf], kb4[2], kb4[3]);
            }
        }

        #pragma unroll
        for (int nf = 0; nf < 8; nf++) {
            int kc = k0 + nf * 8 + c0;
            float2 b0 = *(const float2*)(brow0 + kc);
            float2 b1 = *(const float2*)(brow1 + kc);
            sacc[nf][0] += b0.x; sacc[nf][1] += b0.y;
            sacc[nf][2] += b1.x; sacc[nf][3] += b1.y;
        }

        float mx0 = -CUDART_INF_F, mx1 = -CUDART_INF_F;
        #pragma unroll
        for (int nf = 0; nf < 8; nf++) {
            mx0 = fmaxf(mx0, fmaxf(sacc[nf][0], sacc[nf][1]));
            mx1 = fmaxf(mx1, fmaxf(sacc[nf][2], sacc[nf][3]));
        }
        mx0 = fmaxf(mx0, __shfl_xor_sync(0xffffffffu, mx0, 1));
        mx0 = fmaxf(mx0, __shfl_xor_sync(0xffffffffu, mx0, 2));
        mx1 = fmaxf(mx1, __shfl_xor_sync(0xffffffffu, mx1, 1));
        mx1 = fmaxf(mx1, __shfl_xor_sync(0xffffffffu, mx1, 2));

        float mn0 = fmaxf(m0, mx0), mn1 = fmaxf(m1, mx1);
        float cr0 = __expf(m0 - mn0), cr1 = __expf(m1 - mn1);
        float rs0 = 0.f, rs1 = 0.f;
        #pragma unroll
        for (int nf = 0; nf < 8; nf++) {
            sacc[nf][0] = __expf(sacc[nf][0] - mn0);
            sacc[nf][1] = __expf(sacc[nf][1] - mn0);
            sacc[nf][2] = __expf(sacc[nf][2] - mn1);
            sacc[nf][3] = __expf(sacc[nf][3] - mn1);
            rs0 += sacc[nf][0] + sacc[nf][1];
            rs1 += sacc[nf][2] + sacc[nf][3];
        }
        rs0 += __shfl_xor_sync(0xffffffffu, rs0, 1);
        rs0 += __shfl_xor_sync(0xffffffffu, rs0, 2);
        rs1 += __shfl_xor_sync(0xffffffffu, rs1, 1);
        rs1 += __shfl_xor_sync(0xffffffffu, rs1, 2);
        l0 = l0 * cr0 + rs0;
        l1 = l1 * cr1 + rs1;
        m0 = mn0; m1 = mn1;

        #pragma unroll
        for (int nf = 0; nf < 8; nf++) {
            oacc[nf][0] *= cr0; oacc[nf][1] *= cr0;
            oacc[nf][2] *= cr1; oacc[nf][3] *= cr1;
        }

        uint32_t pa_h[4][4], pa_l[4][4];
        #pragma unroll
        for (int kf = 0; kf < 4; kf++) {
            #pragma unroll
            for (int half = 0; half < 2; half++) {
                int nf = 2 * kf + half;
                float p0 = sacc[nf][0], p1 = sacc[nf][1];
                float p2 = sacc[nf][2], p3 = sacc[nf][3];
                uint32_t hi01 = pack_f16(p0, p1);
                uint32_t hi23 = pack_f16(p2, p3);
                __half2 h01 = *(__half2*)&hi01;
                __half2 h23 = *(__half2*)&hi23;
                uint32_t lo01 = pack_f16(p0 - __half2float(h01.x),
                                         p1 - __half2float(h01.y));
                uint32_t lo23 = pack_f16(p2 - __half2float(h23.x),
                                         p3 - __half2float(h23.y));
                pa_h[kf][2 * half]     = hi01;
                pa_h[kf][2 * half + 1] = hi23;
                pa_l[kf][2 * half]     = lo01;
                pa_l[kf][2 * half + 1] = lo23;
            }
        }

        #pragma unroll
        for (int nfp = 0; nfp < 4; nfp++) {
            #pragma unroll
            for (int kf = 0; kf < 4; kf++) {
                uint32_t addr = sv + (uint32_t)((kf * 16 + vrow) * 128)
                              + (((uint32_t)(nfp * 32) + vcol) ^ xv);
                uint32_t vb4[4];
                ldsm_x4_t(vb4, addr);
                mma16816(oacc[2 * nfp],     pa_h[kf], vb4[0], vb4[1]);
                mma16816(oacc[2 * nfp],     pa_l[kf], vb4[0], vb4[1]);
                mma16816(oacc[2 * nfp + 1], pa_h[kf], vb4[2], vb4[3]);
                mma16816(oacc[2 * nfp + 1], pa_l[kf], vb4[2], vb4[3]);
            }
        }
        if (++s >= 3) s -= 3;
    }

    float inv0 = 1.f / l0, inv1 = 1.f / l1;
    size_t orow0 = (size_t)(b * L_ + rA) * C_ + h * D_;
    size_t orow1 = (size_t)(b * L_ + rA + 8) * C_ + h * D_;
    #pragma unroll
    for (int nf = 0; nf < 8; nf++) {
        int d = nf * 8 + c0;
        float v0 = oacc[nf][0] * inv0, v1 = oacc[nf][1] * inv0;
        float v2 = oacc[nf][2] * inv1, v3 = oacc[nf][3] * inv1;
        uint32_t h01 = pack_f16(v0, v1);
        uint32_t h23 = pack_f16(v2, v3);
        __half2 b01 = *(__half2*)&h01;
        __half2 b23 = *(__half2*)&h23;
        uint32_t l01 = pack_f16(v0 - __half2float(b01.x),
                                v1 - __half2float(b01.y));
        uint32_t l23 = pack_f16(v2 - __half2float(b23.x),
                                v3 - __half2float(b23.y));
        *(uint32_t*)(g_aoh + orow0 + d) = h01;
        *(uint32_t*)(g_aol + orow0 + d) = l01;
        *(uint32_t*)(g_aoh + orow1 + d) = h23;
        *(uint32_t*)(g_aol + orow1 + d) = l23;
    }
}

// ---------------------------------------------------------------------------
extern "C" void kernel_launch(void* const* d_in, const int* in_sizes, int n_in,
                              void* d_out, int out_size)
{
    const float* x         = (const float*)d_in[0];
    const float* freqs     = (const float*)d_in[1];
    const float* attn_bias = (const float*)d_in[2];
    const float* W_qkv     = (const float*)d_in[3];
    const float* q_bias    = (const float*)d_in[4];
    const float* v_bias    = (const float*)d_in[5];
    const float* sml       = (const float*)d_in[6];
    const float* W_proj    = (const float*)d_in[7];
    const float* b_proj    = (const float*)d_in[8];
    float* out = (float*)d_out;

    void* p;
    cudaGetSymbolAddress(&p, g_xhi); __half* xhi = (__half*)p;
    cudaGetSymbolAddress(&p, g_xlo); __half* xlo = (__half*)p;
    cudaGetSymbolAddress(&p, g_wqh); __half* wqh = (__half*)p;
    cudaGetSymbolAddress(&p, g_wph); __half* wph = (__half*)p;
    cudaGetSymbolAddress(&p, g_aoh); __half* aoh = (__half*)p;
    cudaGetSymbolAddress(&p, g_aol); __half* aol = (__half*)p;

    int gsm = 2 * GSTAGE;      // 98304
    int asm_ = 3 * ASTAGE;     // 49152
    static bool attr_set = false;
    if (!attr_set) {
        cudaFuncSetAttribute(gemm_mma_kernel,
                             cudaFuncAttributeMaxDynamicSharedMemorySize, gsm);
        cudaFuncSetAttribute(attn_mma_kernel,
                             cudaFuncAttributeMaxDynamicSharedMemorySize, asm_);
        attr_set = true;
    }

    conv_split_kernel<<<(B_ * L_ * C_ / 4 + 255) / 256, 256>>>(x, xhi, xlo, B_ * L_ * C_ / 4);
    conv_hi_kernel<<<(3 * C_ * C_ / 4 + 255) / 256, 256>>>(W_qkv, wqh, 3 * C_ * C_ / 4);
    conv_hi_kernel<<<(C_ * C_ / 4 + 255) / 256, 256>>>(W_proj, wph, C_ * C_ / 4);

    // QKV GEMM with fused l2norm+scale+RoPE epilogue -> g_qh/ql/kh/vh
    gemm_mma_kernel<<<dim3(3 * C_ / 128, B_ * L_ / 128), 256, gsm>>>(
        xhi, xlo, wqh, nullptr, q_bias, v_bias, freqs, sml, 3 * C_, C_, 0);

    attn_mma_kernel<<<dim3(L_ / 64, B_ * H_), 128, asm_>>>(attn_bias);

    gemm_mma_kernel<<<dim3(C_ / 128, B_ * L_ / 128), 256, gsm>>>(
        aoh, aol, wph, out, b_proj, nullptr, nullptr, nullptr, C_, C_, 1);
}

// round 13
// speedup vs baseline: 1.8744x; 1.1494x over previous
#include <cuda_runtime.h>
#include <cuda_fp16.h>
#include <math_constants.h>
#include <cstdint>
#include <cstddef>

#define B_ 8
#define L_ 1024
#define C_ 1024
#define H_ 16
#define D_ 64
#define MAXSC 4.6051701859880914f  // log(100)

// ---------------------------------------------------------------------------
// Scratch (bss, no runtime allocation)
// ---------------------------------------------------------------------------
__device__ __half g_xhi[B_ * L_ * C_];
__device__ __half g_xlo[B_ * L_ * C_];
__device__ __half g_wqh[3 * C_ * C_];
__device__ __half g_wph[C_ * C_];

__device__ __half g_qh[B_ * H_ * L_ * D_];
__device__ __half g_ql[B_ * H_ * L_ * D_];
__device__ __half g_kh[B_ * H_ * L_ * D_];
__device__ __half g_vh[B_ * H_ * L_ * D_];

__device__ __half g_aoh[B_ * L_ * C_];

// ---------------------------------------------------------------------------
// Helpers
// ---------------------------------------------------------------------------
__device__ __forceinline__ uint32_t smem_u32(const void* p) {
    uint32_t a;
    asm("{ .reg .u64 t; cvta.to.shared.u64 t, %1; cvt.u32.u64 %0, t; }"
        : "=r"(a) : "l"(p));
    return a;
}

__device__ __forceinline__ void mma16816(float* c, const uint32_t* a,
                                         uint32_t b0, uint32_t b1)
{
    asm volatile(
        "mma.sync.aligned.m16n8k16.row.col.f32.f16.f16.f32 "
        "{%0,%1,%2,%3}, {%4,%5,%6,%7}, {%8,%9}, {%0,%1,%2,%3};"
        : "+f"(c[0]), "+f"(c[1]), "+f"(c[2]), "+f"(c[3])
        : "r"(a[0]), "r"(a[1]), "r"(a[2]), "r"(a[3]), "r"(b0), "r"(b1));
}

__device__ __forceinline__ void ldsm_x4(uint32_t* r, uint32_t addr) {
    asm volatile("ldmatrix.sync.aligned.m8n8.x4.shared.b16 {%0,%1,%2,%3}, [%4];"
        : "=r"(r[0]), "=r"(r[1]), "=r"(r[2]), "=r"(r[3]) : "r"(addr));
}
__device__ __forceinline__ void ldsm_x4_t(uint32_t* r, uint32_t addr) {
    asm volatile("ldmatrix.sync.aligned.m8n8.x4.trans.shared.b16 {%0,%1,%2,%3}, [%4];"
        : "=r"(r[0]), "=r"(r[1]), "=r"(r[2]), "=r"(r[3]) : "r"(addr));
}

__device__ __forceinline__ uint32_t pack_f16(float a, float b) {
    __half2 t = __floats2half2_rn(a, b);
    return *(uint32_t*)&t;
}

__device__ __forceinline__ void cp_async16(uint32_t saddr, const void* gptr) {
    asm volatile("cp.async.cg.shared.global [%0], [%1], 16;"
        :: "r"(saddr), "l"(gptr) : "memory");
}
__device__ __forceinline__ void cp_commit() {
    asm volatile("cp.async.commit_group;" ::: "memory");
}
template <int N>
__device__ __forceinline__ void cp_wait() {
    asm volatile("cp.async.wait_group %0;" :: "n"(N) : "memory");
}

// ---------------------------------------------------------------------------
// fp32 -> (hi, lo) fp16 split / hi-only
// ---------------------------------------------------------------------------
__global__ __launch_bounds__(256) void conv_split_kernel(
    const float* __restrict__ src, __half* __restrict__ hi,
    __half* __restrict__ lo, int n4)
{
    int i = blockIdx.x * blockDim.x + threadIdx.x;
    if (i >= n4) return;
    float4 v = ((const float4*)src)[i];
    __half h0 = __float2half_rn(v.x);
    __half h1 = __float2half_rn(v.y);
    __half h2 = __float2half_rn(v.z);
    __half h3 = __float2half_rn(v.w);
    __half l0 = __float2half_rn(v.x - __half2float(h0));
    __half l1 = __float2half_rn(v.y - __half2float(h1));
    __half l2 = __float2half_rn(v.z - __half2float(h2));
    __half l3 = __float2half_rn(v.w - __half2float(h3));
    ((__half2*)hi)[2 * i]     = __half2(h0, h1);
    ((__half2*)hi)[2 * i + 1] = __half2(h2, h3);
    ((__half2*)lo)[2 * i]     = __half2(l0, l1);
    ((__half2*)lo)[2 * i + 1] = __half2(l2, l3);
}

__global__ __launch_bounds__(256) void conv_hi_kernel(
    const float* __restrict__ src, __half* __restrict__ hi, int n4)
{
    int i = blockIdx.x * blockDim.x + threadIdx.x;
    if (i >= n4) return;
    float4 v = ((const float4*)src)[i];
    ((__half2*)hi)[2 * i]     = __floats2half2_rn(v.x, v.y);
    ((__half2*)hi)[2 * i + 1] = __floats2half2_rn(v.z, v.w);
}

// ---------------------------------------------------------------------------
// QKV GEMM: A fp16 2-term, B fp16 1-term. K-chunk 64, 2-stage cp.async.
// Fused epilogue: l2norm + scale + RoPE -> g_qh/ql/kh/vh.
// ---------------------------------------------------------------------------
#define GSTAGE 49152
__global__ __launch_bounds__(256, 2) void gemm_qkv_kernel(
    const __half* __restrict__ Ahi, const __half* __restrict__ Alo,
    const __half* __restrict__ Bhi,
    const float* __restrict__ bias_q, const float* __restrict__ bias_v,
    const float* __restrict__ freqs, const float* __restrict__ sml,
    int N, int K)
{
    extern __shared__ __align__(16) char smc[];
    uint32_t sb = smem_u32(smc);
    int t = threadIdx.x;
    int wid = t >> 5, lane = t & 31;
    int wm = wid & 3, wn = wid >> 2;
    int m0 = blockIdx.y * 128, n0 = blockIdx.x * 128;

    float acc[2][8][4];
    #pragma unroll
    for (int i = 0; i < 2; i++)
        #pragma unroll
        for (int j = 0; j < 8; j++)
            #pragma unroll
            for (int u = 0; u < 4; u++) acc[i][j][u] = 0.f;

    int qrow = lane >> 2;
    int qk   = (lane & 3) * 2;
    int g = lane >> 3, r8 = lane & 7;
    int arow = (g & 1) * 8 + r8;
    uint32_t xv = (uint32_t)(r8 << 4);
    uint32_t ccol = (uint32_t)((g >> 1) * 16);
    const int niter = K >> 6;

    auto issue = [&](int it, int s) {
        int k0 = it << 6;
        uint32_t stb = sb + (uint32_t)s * GSTAGE;
        #pragma unroll
        for (int i = 0; i < 8; i++) {
            int c = t + i * 256;
            int row = c >> 4, cg = c & 15;
            uint32_t swo = (uint32_t)(row * 256 + cg * 16) ^ ((uint32_t)(row & 7) << 4);
            const __half* src = (cg < 8)
                ? (Ahi + (size_t)(m0 + row) * K + k0 + cg * 8)
                : (Alo + (size_t)(m0 + row) * K + k0 + (cg - 8) * 8);
            cp_async16(stb + swo, src);
        }
        #pragma unroll
        for (int i = 0; i < 4; i++) {
            int c = t + i * 256;
            int row = c >> 3, cg = c & 7;
            uint32_t off = (uint32_t)(row * 128 + cg * 16);
            uint32_t swo = off ^ ((off >> 3) & 0x70);
            cp_async16(stb + 32768 + swo,
                       Bhi + (size_t)(n0 + row) * K + k0 + cg * 8);
        }
        cp_commit();
    };

    issue(0, 0);
    for (int it = 0; it < niter; it++) {
        int s = it & 1;
        cp_wait<0>();
        __syncthreads();
        if (it + 1 < niter) issue(it + 1, s ^ 1);

        uint32_t sA = sb + (uint32_t)s * GSTAGE;
        uint32_t sB = sA + 32768;

        #pragma unroll
        for (int ks = 0; ks < 4; ks++) {
            uint32_t ah = ((uint32_t)(ks * 32) + ccol) ^ xv;
            uint32_t al = ((uint32_t)(128 + ks * 32) + ccol) ^ xv;
            uint32_t bc = ((uint32_t)(ks * 32) + ccol) ^ xv;
            uint32_t afh[2][4], afl[2][4];
            #pragma unroll
            for (int mf = 0; mf < 2; mf++) {
                uint32_t rb = (uint32_t)((wm * 32 + mf * 16 + arow) * 256);
                ldsm_x4(afh[mf], sA + rb + ah);
                ldsm_x4(afl[mf], sA + rb + al);
            }
            #pragma unroll
            for (int nfp = 0; nfp < 4; nfp++) {
                uint32_t rb = (uint32_t)((wn * 64 + nfp * 16 + arow) * 128);
                uint32_t b4[4];
                ldsm_x4(b4, sB + rb + bc);
                #pragma unroll
                for (int mf = 0; mf < 2; mf++) {
                    mma16816(acc[mf][2 * nfp],     afh[mf], b4[0], b4[2]);
                    mma16816(acc[mf][2 * nfp],     afl[mf], b4[0], b4[2]);
                    mma16816(acc[mf][2 * nfp + 1], afh[mf], b4[1], b4[3]);
                    mma16816(acc[mf][2 * nfp + 1], afl[mf], b4[1], b4[3]);
                }
            }
        }
    }

    // fused l2norm + scale + RoPE epilogue.  region 0=q, 1=k, 2=v.
    int region = blockIdx.x >> 3;
    int head   = ((blockIdx.x & 7) << 1) + wn;
    float smul = (region == 0) ? __expf(fminf(sml[head], MAXSC)) : 1.f;
    const float2* fr2 = (const float2*)freqs;

    #pragma unroll
    for (int mf = 0; mf < 2; mf++) {
        int r0 = m0 + wm * 32 + mf * 16 + qrow;
        int bb = r0 >> 10;
        int lA = r0 & 1023, lB = lA + 8;
        size_t baseA = ((size_t)(bb * H_ + head) * L_ + lA) * D_;
        size_t baseB = baseA + 8 * D_;

        float sA = 0.f, sB = 0.f;
        #pragma unroll
        for (int nf = 0; nf < 8; nf++) {
            int d = nf * 8 + qk;
            float bv0 = 0.f, bv1 = 0.f;
            if (region == 0) { bv0 = bias_q[head * D_ + d]; bv1 = bias_q[head * D_ + d + 1]; }
            if (region == 2) { bv0 = bias_v[head * D_ + d]; bv1 = bias_v[head * D_ + d + 1]; }
            acc[mf][nf][0] += bv0; acc[mf][nf][1] += bv1;
            acc[mf][nf][2] += bv0; acc[mf][nf][3] += bv1;
            if (region < 2) {
                sA += acc[mf][nf][0] * acc[mf][nf][0] + acc[mf][nf][1] * acc[mf][nf][1];
                sB += acc[mf][nf][2] * acc[mf][nf][2] + acc[mf][nf][3] * acc[mf][nf][3];
            }
        }

        if (region < 2) {
            sA += __shfl_xor_sync(0xffffffffu, sA, 1);
            sA += __shfl_xor_sync(0xffffffffu, sA, 2);
            sB += __shfl_xor_sync(0xffffffffu, sB, 1);
            sB += __shfl_xor_sync(0xffffffffu, sB, 2);
            float invA = smul / fmaxf(sqrtf(sA), 1e-12f);
            float invB = smul / fmaxf(sqrtf(sB), 1e-12f);

            #pragma unroll
            for (int nf = 0; nf < 8; nf++) {
                int d = nf * 8 + qk;
                float2 fA = fr2[lA * (D_ / 2) + (d >> 1)];
                float2 fB = fr2[lB * (D_ / 2) + (d >> 1)];
                float reA = acc[mf][nf][0] * invA, imA = acc[mf][nf][1] * invA;
                float reB = acc[mf][nf][2] * invB, imB = acc[mf][nf][3] * invB;
                float oA0 = reA * fA.x - imA * fA.y, oA1 = reA * fA.y + imA * fA.x;
                float oB0 = reB * fB.x - imB * fB.y, oB1 = reB * fB.y + imB * fB.x;
                if (region == 0) {
                    uint32_t hA = pack_f16(oA0, oA1);
                    uint32_t hB = pack_f16(oB0, oB1);
                    __half2 a2 = *(__half2*)&hA;
                    __half2 b2 = *(__half2*)&hB;
                    uint32_t lAp = pack_f16(oA0 - __half2float(a2.x),
                                            oA1 - __half2float(a2.y));
                    uint32_t lBp = pack_f16(oB0 - __half2float(b2.x),
                                            oB1 - __half2float(b2.y));
                    *(uint32_t*)(g_qh + baseA + d) = hA;
                    *(uint32_t*)(g_ql + baseA + d) = lAp;
                    *(uint32_t*)(g_qh + baseB + d) = hB;
                    *(uint32_t*)(g_ql + baseB + d) = lBp;
                } else {
                    *(uint32_t*)(g_kh + baseA + d) = pack_f16(oA0, oA1);
                    *(uint32_t*)(g_kh + baseB + d) = pack_f16(oB0, oB1);
                }
            }
        } else {
            #pragma unroll
            for (int nf = 0; nf < 8; nf++) {
                int d = nf * 8 + qk;
                *(uint32_t*)(g_vh + baseA + d) = pack_f16(acc[mf][nf][0], acc[mf][nf][1]);
                *(uint32_t*)(g_vh + baseB + d) = pack_f16(acc[mf][nf][2], acc[mf][nf][3]);
            }
        }
    }
}

// ---------------------------------------------------------------------------
// Proj GEMM: pure fp16 1-term x 1-term.  K-chunk 64, 2-stage cp.async.
// Stage: A 128x128B + B 128x128B = 32KB.
// ---------------------------------------------------------------------------
#define PSTAGE 32768
__global__ __launch_bounds__(256, 2) void gemm_proj_kernel(
    const __half* __restrict__ Ahi, const __half* __restrict__ Bhi,
    float* __restrict__ Cm, const float* __restrict__ bias,
    int N, int K)
{
    extern __shared__ __align__(16) char smc[];
    uint32_t sb = smem_u32(smc);
    int t = threadIdx.x;
    int wid = t >> 5, lane = t & 31;
    int wm = wid & 3, wn = wid >> 2;
    int m0 = blockIdx.y * 128, n0 = blockIdx.x * 128;

    float acc[2][8][4];
    #pragma unroll
    for (int i = 0; i < 2; i++)
        #pragma unroll
        for (int j = 0; j < 8; j++)
            #pragma unroll
            for (int u = 0; u < 4; u++) acc[i][j][u] = 0.f;

    int qrow = lane >> 2;
    int qk   = (lane & 3) * 2;
    int g = lane >> 3, r8 = lane & 7;
    int arow = (g & 1) * 8 + r8;
    uint32_t xv = (uint32_t)(r8 << 4);
    uint32_t ccol = (uint32_t)((g >> 1) * 16);
    const int niter = K >> 6;

    auto issue = [&](int it, int s) {
        int k0 = it << 6;
        uint32_t stb = sb + (uint32_t)s * PSTAGE;
        #pragma unroll
        for (int i = 0; i < 4; i++) {
            int c = t + i * 256;
            int row = c >> 3, cg = c & 7;
            uint32_t off = (uint32_t)(row * 128 + cg * 16);
            uint32_t swo = off ^ ((off >> 3) & 0x70);
            cp_async16(stb + swo,
                       Ahi + (size_t)(m0 + row) * K + k0 + cg * 8);
            cp_async16(stb + 16384 + swo,
                       Bhi + (size_t)(n0 + row) * K + k0 + cg * 8);
        }
        cp_commit();
    };

    issue(0, 0);
    for (int it = 0; it < niter; it++) {
        int s = it & 1;
        cp_wait<0>();
        __syncthreads();
        if (it + 1 < niter) issue(it + 1, s ^ 1);

        uint32_t sA = sb + (uint32_t)s * PSTAGE;
        uint32_t sB = sA + 16384;

        #pragma unroll
        for (int ks = 0; ks < 4; ks++) {
            uint32_t cc = ((uint32_t)(ks * 32) + ccol) ^ xv;
            uint32_t afh[2][4];
            #pragma unroll
            for (int mf = 0; mf < 2; mf++) {
                uint32_t rb = (uint32_t)((wm * 32 + mf * 16 + arow) * 128);
                ldsm_x4(afh[mf], sA + rb + cc);
            }
            #pragma unroll
            for (int nfp = 0; nfp < 4; nfp++) {
                uint32_t rb = (uint32_t)((wn * 64 + nfp * 16 + arow) * 128);
                uint32_t b4[4];
                ldsm_x4(b4, sB + rb + cc);
                #pragma unroll
                for (int mf = 0; mf < 2; mf++) {
                    mma16816(acc[mf][2 * nfp],     afh[mf], b4[0], b4[2]);
                    mma16816(acc[mf][2 * nfp + 1], afh[mf], b4[1], b4[3]);
                }
            }
        }
    }

    #pragma unroll
    for (int mf = 0; mf < 2; mf++) {
        #pragma unroll
        for (int nf = 0; nf < 8; nf++) {
            int row = m0 + wm * 32 + mf * 16 + qrow;
            int col = n0 + wn * 64 + nf * 8 + qk;
            float bv0 = bias[col];
            float bv1 = bias[col + 1];
            *(float2*)(Cm + (size_t)row * N + col) =
                make_float2(acc[mf][nf][0] + bv0, acc[mf][nf][1] + bv1);
            *(float2*)(Cm + (size_t)(row + 8) * N + col) =
                make_float2(acc[mf][nf][2] + bv0, acc[mf][nf][3] + bv1);
        }
    }
}

// ---------------------------------------------------------------------------
// Flash attention, fp16 HMMA: Q 2-term, K/V/P 1-term. 3-stage cp.async.
// ---------------------------------------------------------------------------
#define ASTAGE 16384
__global__ __launch_bounds__(128) void attn_mma_kernel(
    const float* __restrict__ bias)
{
    extern __shared__ __align__(16) char asmem[];
    uint32_t sbase = smem_u32(asmem);

    int t = threadIdx.x;
    int wid = t >> 5, lane = t & 31;
    int q0 = blockIdx.x * 64;
    int bh = blockIdx.y;
    int b = bh >> 4, h = bh & 15;

    const __half* Qh = g_qh + (size_t)bh * L_ * D_;
    const __half* Ql = g_ql + (size_t)bh * L_ * D_;
    const __half* Kh = g_kh + (size_t)bh * L_ * D_;
    const __half* Vh = g_vh + (size_t)bh * L_ * D_;

    int rA = q0 + wid * 16 + (lane >> 2);
    int c0 = (lane & 3) * 2;

    uint32_t qa_h[4][4], qa_l[4][4];
    #pragma unroll
    for (int kf = 0; kf < 4; kf++) {
        int cb = kf * 16 + c0;
        qa_h[kf][0] = *(const uint32_t*)(Qh + (size_t)rA * D_ + cb);
        qa_h[kf][1] = *(const uint32_t*)(Qh + (size_t)(rA + 8) * D_ + cb);
        qa_h[kf][2] = *(const uint32_t*)(Qh + (size_t)rA * D_ + cb + 8);
        qa_h[kf][3] = *(const uint32_t*)(Qh + (size_t)(rA + 8) * D_ + cb + 8);
        qa_l[kf][0] = *(const uint32_t*)(Ql + (size_t)rA * D_ + cb);
        qa_l[kf][1] = *(const uint32_t*)(Ql + (size_t)(rA + 8) * D_ + cb);
        qa_l[kf][2] = *(const uint32_t*)(Ql + (size_t)rA * D_ + cb + 8);
        qa_l[kf][3] = *(const uint32_t*)(Ql + (size_t)(rA + 8) * D_ + cb + 8);
    }

    float m0 = -CUDART_INF_F, m1 = -CUDART_INF_F;
    float l0 = 0.f, l1 = 0.f;
    float oacc[8][4];
    #pragma unroll
    for (int nf = 0; nf < 8; nf++)
        #pragma unroll
        for (int u = 0; u < 4; u++) oacc[nf][u] = 0.f;

    int g = lane >> 3, r8 = lane & 7;
    uint32_t xv = (uint32_t)(r8 << 4);
    uint32_t krow = (uint32_t)((g >> 1) * 8 + r8);
    uint32_t kcol = (uint32_t)((g & 1) * 16);
    uint32_t vrow = (uint32_t)((g & 1) * 8 + r8);
    uint32_t vcol = (uint32_t)((g >> 1) * 16);

    const float* brow0 = bias + (size_t)rA * L_;
    const float* brow1 = bias + (size_t)(rA + 8) * L_;

    auto issue_kv = [&](int k0, int s) {
        uint32_t stb = sbase + (uint32_t)s * ASTAGE;
        #pragma unroll
        for (int i = 0; i < 4; i++) {
            int c = t + i * 128;
            int row = c >> 3, cg = c & 7;
            uint32_t off = (uint32_t)(row * 128 + cg * 16);
            uint32_t swo = off ^ ((off >> 3) & 0x70);
            size_t gsrc = (size_t)(k0 + row) * D_ + cg * 8;
            cp_async16(stb + swo,        Kh + gsrc);
            cp_async16(stb + 8192 + swo, Vh + gsrc);
        }
        cp_commit();
    };

    issue_kv(0, 0);
    issue_kv(64, 1);
    const int NIT = L_ / 64;
    int s = 0;
    for (int ki = 0; ki < NIT; ki++) {
        if (ki + 1 < NIT) cp_wait<1>(); else cp_wait<0>();
        __syncthreads();
        if (ki + 2 < NIT) {
            int s2 = s + 2; if (s2 >= 3) s2 -= 3;
            issue_kv((ki + 2) * 64, s2);
        }

        uint32_t sk = sbase + (uint32_t)s * ASTAGE;
        uint32_t sv = sk + 8192;
        int k0 = ki * 64;

        float sacc[8][4];
        #pragma unroll
        for (int nf = 0; nf < 8; nf++)
            #pragma unroll
            for (int u = 0; u < 4; u++) sacc[nf][u] = 0.f;

        #pragma unroll
        for (int nfp = 0; nfp < 4; nfp++) {
            #pragma unroll
            for (int kf = 0; kf < 4; kf++) {
                uint32_t addr = sk + (uint32_t)((nfp * 16 + krow) * 128)
                              + (((uint32_t)(kf * 32) + kcol) ^ xv);
                uint32_t kb4[4];
                ldsm_x4(kb4, addr);
                mma16816(sacc[2 * nfp],     qa_h[kf], kb4[0], kb4[1]);
                mma16816(sacc[2 * nfp],     qa_l[kf], kb4[0], kb4[1]);
                mma16816(sacc[2 * nfp + 1], qa_h[kf], kb4[2], kb4[3]);
                mma16816(sacc[2 * nfp + 1], qa_l[kf], kb4[2], kb4[3]);
            }
        }

        #pragma unroll
        for (int nf = 0; nf < 8; nf++) {
            int kc = k0 + nf * 8 + c0;
            float2 b0 = *(const float2*)(brow0 + kc);
            float2 b1 = *(const float2*)(brow1 + kc);
            sacc[nf][0] += b0.x; sacc[nf][1] += b0.y;
            sacc[nf][2] += b1.x; sacc[nf][3] += b1.y;
        }

        float mx0 = -CUDART_INF_F, mx1 = -CUDART_INF_F;
        #pragma unroll
        for (int nf = 0; nf < 8; nf++) {
            mx0 = fmaxf(mx0, fmaxf(sacc[nf][0], sacc[nf][1]));
            mx1 = fmaxf(mx1, fmaxf(sacc[nf][2], sacc[nf][3]));
        }
        mx0 = fmaxf(mx0, __shfl_xor_sync(0xffffffffu, mx0, 1));
        mx0 = fmaxf(mx0, __shfl_xor_sync(0xffffffffu, mx0, 2));
        mx1 = fmaxf(mx1, __shfl_xor_sync(0xffffffffu, mx1, 1));
        mx1 = fmaxf(mx1, __shfl_xor_sync(0xffffffffu, mx1, 2));

        float mn0 = fmaxf(m0, mx0), mn1 = fmaxf(m1, mx1);
        float cr0 = __expf(m0 - mn0), cr1 = __expf(m1 - mn1);
        float rs0 = 0.f, rs1 = 0.f;
        #pragma unroll
        for (int nf = 0; nf < 8; nf++) {
            sacc[nf][0] = __expf(sacc[nf][0] - mn0);
            sacc[nf][1] = __expf(sacc[nf][1] - mn0);
            sacc[nf][2] = __expf(sacc[nf][2] - mn1);
            sacc[nf][3] = __expf(sacc[nf][3] - mn1);
            rs0 += sacc[nf][0] + sacc[nf][1];
            rs1 += sacc[nf][2] + sacc[nf][3];
        }
        rs0 += __shfl_xor_sync(0xffffffffu, rs0, 1);
        rs0 += __shfl_xor_sync(0xffffffffu, rs0, 2);
        rs1 += __shfl_xor_sync(0xffffffffu, rs1, 1);
        rs1 += __shfl_xor_sync(0xffffffffu, rs1, 2);
        l0 = l0 * cr0 + rs0;
        l1 = l1 * cr1 + rs1;
        m0 = mn0; m1 = mn1;

        #pragma unroll
        for (int nf = 0; nf < 8; nf++) {
            oacc[nf][0] *= cr0; oacc[nf][1] *= cr0;
            oacc[nf][2] *= cr1; oacc[nf][3] *= cr1;
        }

        // pack P (hi only)
        uint32_t pa_h[4][4];
        #pragma unroll
        for (int kf = 0; kf < 4; kf++) {
            #pragma unroll
            for (int half = 0; half < 2; half++) {
                int nf = 2 * kf + half;
                pa_h[kf][2 * half]     = pack_f16(sacc[nf][0], sacc[nf][1]);
                pa_h[kf][2 * half + 1] = pack_f16(sacc[nf][2], sacc[nf][3]);
            }
        }

        #pragma unroll
        for (int nfp = 0; nfp < 4; nfp++) {
            #pragma unroll
            for (int kf = 0; kf < 4; kf++) {
                uint32_t addr = sv + (uint32_t)((kf * 16 + vrow) * 128)
                              + (((uint32_t)(nfp * 32) + vcol) ^ xv);
                uint32_t vb4[4];
                ldsm_x4_t(vb4, addr);
                mma16816(oacc[2 * nfp],     pa_h[kf], vb4[0], vb4[1]);
                mma16816(oacc[2 * nfp + 1], pa_h[kf], vb4[2], vb4[3]);
            }
        }
        if (++s >= 3) s -= 3;
    }

    float inv0 = 1.f / l0, inv1 = 1.f / l1;
    size_t orow0 = (size_t)(b * L_ + rA) * C_ + h * D_;
    size_t orow1 = (size_t)(b * L_ + rA + 8) * C_ + h * D_;
    #pragma unroll
    for (int nf = 0; nf < 8; nf++) {
        int d = nf * 8 + c0;
        *(uint32_t*)(g_aoh + orow0 + d) = pack_f16(oacc[nf][0] * inv0, oacc[nf][1] * inv0);
        *(uint32_t*)(g_aoh + orow1 + d) = pack_f16(oacc[nf][2] * inv1, oacc[nf][3] * inv1);
    }
}

// ---------------------------------------------------------------------------
extern "C" void kernel_launch(void* const* d_in, const int* in_sizes, int n_in,
                              void* d_out, int out_size)
{
    const float* x         = (const float*)d_in[0];
    const float* freqs     = (const float*)d_in[1];
    const float* attn_bias = (const float*)d_in[2];
    const float* W_qkv     = (const float*)d_in[3];
    const float* q_bias    = (const float*)d_in[4];
    const float* v_bias    = (const float*)d_in[5];
    const float* sml       = (const float*)d_in[6];
    const float* W_proj    = (const float*)d_in[7];
    const float* b_proj    = (const float*)d_in[8];
    float* out = (float*)d_out;

    void* p;
    cudaGetSymbolAddress(&p, g_xhi); __half* xhi = (__half*)p;
    cudaGetSymbolAddress(&p, g_xlo); __half* xlo = (__half*)p;
    cudaGetSymbolAddress(&p, g_wqh); __half* wqh = (__half*)p;
    cudaGetSymbolAddress(&p, g_wph); __half* wph = (__half*)p;
    cudaGetSymbolAddress(&p, g_aoh); __half* aoh = (__half*)p;

    int gsm = 2 * GSTAGE;      // 98304
    int psm = 2 * PSTAGE;      // 65536
    int asm_ = 3 * ASTAGE;     // 49152
    static bool attr_set = false;
    if (!attr_set) {
        cudaFuncSetAttribute(gemm_qkv_kernel,
                             cudaFuncAttributeMaxDynamicSharedMemorySize, gsm);
        cudaFuncSetAttribute(gemm_proj_kernel,
                             cudaFuncAttributeMaxDynamicSharedMemorySize, psm);
        cudaFuncSetAttribute(attn_mma_kernel,
                             cudaFuncAttributeMaxDynamicSharedMemorySize, asm_);
        attr_set = true;
    }

    conv_split_kernel<<<(B_ * L_ * C_ / 4 + 255) / 256, 256>>>(x, xhi, xlo, B_ * L_ * C_ / 4);
    conv_hi_kernel<<<(3 * C_ * C_ / 4 + 255) / 256, 256>>>(W_qkv, wqh, 3 * C_ * C_ / 4);
    conv_hi_kernel<<<(C_ * C_ / 4 + 255) / 256, 256>>>(W_proj, wph, C_ * C_ / 4);

    gemm_qkv_kernel<<<dim3(3 * C_ / 128, B_ * L_ / 128), 256, gsm>>>(
        xhi, xlo, wqh, q_bias, v_bias, freqs, sml, 3 * C_, C_);

    attn_mma_kernel<<<dim3(L_ / 64, B_ * H_), 128, asm_>>>(attn_bias);

    gemm_proj_kernel<<<dim3(C_ / 128, B_ * L_ / 128), 256, psm>>>(
        aoh, wph, out, b_proj, C_, C_);
}

// round 14
// speedup vs baseline: 2.6670x; 1.4229x over previous
#include <cuda_runtime.h>
#include <cuda_fp16.h>
#include <math_constants.h>
#include <cstdint>
#include <cstddef>

#define B_ 8
#define L_ 1024
#define C_ 1024
#define H_ 16
#define D_ 64
#define MAXSC 4.6051701859880914f  // log(100)

// ---------------------------------------------------------------------------
// Scratch (bss, no runtime allocation)
// ---------------------------------------------------------------------------
__device__ __half g_xhi[B_ * L_ * C_];
__device__ __half g_wqh[3 * C_ * C_];
__device__ __half g_wph[C_ * C_];

__device__ __half g_qh[B_ * H_ * L_ * D_];
__device__ __half g_kh[B_ * H_ * L_ * D_];
__device__ __half g_vh[B_ * H_ * L_ * D_];

__device__ __half g_aoh[B_ * L_ * C_];

// ---------------------------------------------------------------------------
// Helpers
// ---------------------------------------------------------------------------
__device__ __forceinline__ uint32_t smem_u32(const void* p) {
    uint32_t a;
    asm("{ .reg .u64 t; cvta.to.shared.u64 t, %1; cvt.u32.u64 %0, t; }"
        : "=r"(a) : "l"(p));
    return a;
}

__device__ __forceinline__ void mma16816(float* c, const uint32_t* a,
                                         uint32_t b0, uint32_t b1)
{
    asm volatile(
        "mma.sync.aligned.m16n8k16.row.col.f32.f16.f16.f32 "
        "{%0,%1,%2,%3}, {%4,%5,%6,%7}, {%8,%9}, {%0,%1,%2,%3};"
        : "+f"(c[0]), "+f"(c[1]), "+f"(c[2]), "+f"(c[3])
        : "r"(a[0]), "r"(a[1]), "r"(a[2]), "r"(a[3]), "r"(b0), "r"(b1));
}

__device__ __forceinline__ void ldsm_x4(uint32_t* r, uint32_t addr) {
    asm volatile("ldmatrix.sync.aligned.m8n8.x4.shared.b16 {%0,%1,%2,%3}, [%4];"
        : "=r"(r[0]), "=r"(r[1]), "=r"(r[2]), "=r"(r[3]) : "r"(addr));
}
__device__ __forceinline__ void ldsm_x4_t(uint32_t* r, uint32_t addr) {
    asm volatile("ldmatrix.sync.aligned.m8n8.x4.trans.shared.b16 {%0,%1,%2,%3}, [%4];"
        : "=r"(r[0]), "=r"(r[1]), "=r"(r[2]), "=r"(r[3]) : "r"(addr));
}

__device__ __forceinline__ uint32_t pack_f16(float a, float b) {
    __half2 t = __floats2half2_rn(a, b);
    return *(uint32_t*)&t;
}

__device__ __forceinline__ void cp_async16(uint32_t saddr, const void* gptr) {
    asm volatile("cp.async.cg.shared.global [%0], [%1], 16;"
        :: "r"(saddr), "l"(gptr) : "memory");
}
__device__ __forceinline__ void cp_commit() {
    asm volatile("cp.async.commit_group;" ::: "memory");
}
template <int N>
__device__ __forceinline__ void cp_wait() {
    asm volatile("cp.async.wait_group %0;" :: "n"(N) : "memory");
}

// ---------------------------------------------------------------------------
// fp32 -> fp16
// ---------------------------------------------------------------------------
__global__ __launch_bounds__(256) void conv_hi_kernel(
    const float* __restrict__ src, __half* __restrict__ hi, int n4)
{
    int i = blockIdx.x * blockDim.x + threadIdx.x;
    if (i >= n4) return;
    float4 v = ((const float4*)src)[i];
    ((__half2*)hi)[2 * i]     = __floats2half2_rn(v.x, v.y);
    ((__half2*)hi)[2 * i + 1] = __floats2half2_rn(v.z, v.w);
}

// ---------------------------------------------------------------------------
// QKV GEMM: pure fp16 1-term.  K-chunk 64, 2-stage cp.async.
// Stage: A 128x128B + B 128x128B = 32KB, SW128.
// Fused epilogue: l2norm + scale + RoPE -> g_qh/kh/vh.
// ---------------------------------------------------------------------------
#define PSTAGE 32768
__global__ __launch_bounds__(256, 2) void gemm_qkv_kernel(
    const __half* __restrict__ Ahi, const __half* __restrict__ Bhi,
    const float* __restrict__ bias_q, const float* __restrict__ bias_v,
    const float* __restrict__ freqs, const float* __restrict__ sml,
    int N, int K)
{
    extern __shared__ __align__(16) char smc[];
    uint32_t sb = smem_u32(smc);
    int t = threadIdx.x;
    int wid = t >> 5, lane = t & 31;
    int wm = wid & 3, wn = wid >> 2;
    int m0 = blockIdx.y * 128, n0 = blockIdx.x * 128;

    float acc[2][8][4];
    #pragma unroll
    for (int i = 0; i < 2; i++)
        #pragma unroll
        for (int j = 0; j < 8; j++)
            #pragma unroll
            for (int u = 0; u < 4; u++) acc[i][j][u] = 0.f;

    int qrow = lane >> 2;
    int qk   = (lane & 3) * 2;
    int g = lane >> 3, r8 = lane & 7;
    int arow = (g & 1) * 8 + r8;
    uint32_t xv = (uint32_t)(r8 << 4);
    uint32_t ccol = (uint32_t)((g >> 1) * 16);
    const int niter = K >> 6;

    auto issue = [&](int it, int s) {
        int k0 = it << 6;
        uint32_t stb = sb + (uint32_t)s * PSTAGE;
        #pragma unroll
        for (int i = 0; i < 4; i++) {
            int c = t + i * 256;
            int row = c >> 3, cg = c & 7;
            uint32_t off = (uint32_t)(row * 128 + cg * 16);
            uint32_t swo = off ^ ((off >> 3) & 0x70);
            cp_async16(stb + swo,
                       Ahi + (size_t)(m0 + row) * K + k0 + cg * 8);
            cp_async16(stb + 16384 + swo,
                       Bhi + (size_t)(n0 + row) * K + k0 + cg * 8);
        }
        cp_commit();
    };

    issue(0, 0);
    for (int it = 0; it < niter; it++) {
        int s = it & 1;
        cp_wait<0>();
        __syncthreads();
        if (it + 1 < niter) issue(it + 1, s ^ 1);

        uint32_t sA = sb + (uint32_t)s * PSTAGE;
        uint32_t sB = sA + 16384;

        #pragma unroll
        for (int ks = 0; ks < 4; ks++) {
            uint32_t cc = ((uint32_t)(ks * 32) + ccol) ^ xv;
            uint32_t afh[2][4];
            #pragma unroll
            for (int mf = 0; mf < 2; mf++) {
                uint32_t rb = (uint32_t)((wm * 32 + mf * 16 + arow) * 128);
                ldsm_x4(afh[mf], sA + rb + cc);
            }
            #pragma unroll
            for (int nfp = 0; nfp < 4; nfp++) {
                uint32_t rb = (uint32_t)((wn * 64 + nfp * 16 + arow) * 128);
                uint32_t b4[4];
                ldsm_x4(b4, sB + rb + cc);
                #pragma unroll
                for (int mf = 0; mf < 2; mf++) {
                    mma16816(acc[mf][2 * nfp],     afh[mf], b4[0], b4[2]);
                    mma16816(acc[mf][2 * nfp + 1], afh[mf], b4[1], b4[3]);
                }
            }
        }
    }

    // fused l2norm + scale + RoPE epilogue.  region 0=q, 1=k, 2=v.
    int region = blockIdx.x >> 3;
    int head   = ((blockIdx.x & 7) << 1) + wn;
    float smul = (region == 0) ? __expf(fminf(sml[head], MAXSC)) : 1.f;
    const float2* fr2 = (const float2*)freqs;

    #pragma unroll
    for (int mf = 0; mf < 2; mf++) {
        int r0 = m0 + wm * 32 + mf * 16 + qrow;
        int bb = r0 >> 10;
        int lA = r0 & 1023, lB = lA + 8;
        size_t baseA = ((size_t)(bb * H_ + head) * L_ + lA) * D_;
        size_t baseB = baseA + 8 * D_;

        float sA = 0.f, sB = 0.f;
        #pragma unroll
        for (int nf = 0; nf < 8; nf++) {
            int d = nf * 8 + qk;
            float bv0 = 0.f, bv1 = 0.f;
            if (region == 0) { bv0 = bias_q[head * D_ + d]; bv1 = bias_q[head * D_ + d + 1]; }
            if (region == 2) { bv0 = bias_v[head * D_ + d]; bv1 = bias_v[head * D_ + d + 1]; }
            acc[mf][nf][0] += bv0; acc[mf][nf][1] += bv1;
            acc[mf][nf][2] += bv0; acc[mf][nf][3] += bv1;
            if (region < 2) {
                sA += acc[mf][nf][0] * acc[mf][nf][0] + acc[mf][nf][1] * acc[mf][nf][1];
                sB += acc[mf][nf][2] * acc[mf][nf][2] + acc[mf][nf][3] * acc[mf][nf][3];
            }
        }

        if (region < 2) {
            sA += __shfl_xor_sync(0xffffffffu, sA, 1);
            sA += __shfl_xor_sync(0xffffffffu, sA, 2);
            sB += __shfl_xor_sync(0xffffffffu, sB, 1);
            sB += __shfl_xor_sync(0xffffffffu, sB, 2);
            float invA = smul / fmaxf(sqrtf(sA), 1e-12f);
            float invB = smul / fmaxf(sqrtf(sB), 1e-12f);

            __half* dst = (region == 0) ? g_qh : g_kh;
            #pragma unroll
            for (int nf = 0; nf < 8; nf++) {
                int d = nf * 8 + qk;
                float2 fA = fr2[lA * (D_ / 2) + (d >> 1)];
                float2 fB = fr2[lB * (D_ / 2) + (d >> 1)];
                float reA = acc[mf][nf][0] * invA, imA = acc[mf][nf][1] * invA;
                float reB = acc[mf][nf][2] * invB, imB = acc[mf][nf][3] * invB;
                *(uint32_t*)(dst + baseA + d) =
                    pack_f16(reA * fA.x - imA * fA.y, reA * fA.y + imA * fA.x);
                *(uint32_t*)(dst + baseB + d) =
                    pack_f16(reB * fB.x - imB * fB.y, reB * fB.y + imB * fB.x);
            }
        } else {
            #pragma unroll
            for (int nf = 0; nf < 8; nf++) {
                int d = nf * 8 + qk;
                *(uint32_t*)(g_vh + baseA + d) = pack_f16(acc[mf][nf][0], acc[mf][nf][1]);
                *(uint32_t*)(g_vh + baseB + d) = pack_f16(acc[mf][nf][2], acc[mf][nf][3]);
            }
        }
    }
}

// ---------------------------------------------------------------------------
// Proj GEMM: pure fp16 1-term. K-chunk 64, 2-stage cp.async.
// ---------------------------------------------------------------------------
__global__ __launch_bounds__(256, 2) void gemm_proj_kernel(
    const __half* __restrict__ Ahi, const __half* __restrict__ Bhi,
    float* __restrict__ Cm, const float* __restrict__ bias,
    int N, int K)
{
    extern __shared__ __align__(16) char smc[];
    uint32_t sb = smem_u32(smc);
    int t = threadIdx.x;
    int wid = t >> 5, lane = t & 31;
    int wm = wid & 3, wn = wid >> 2;
    int m0 = blockIdx.y * 128, n0 = blockIdx.x * 128;

    float acc[2][8][4];
    #pragma unroll
    for (int i = 0; i < 2; i++)
        #pragma unroll
        for (int j = 0; j < 8; j++)
            #pragma unroll
            for (int u = 0; u < 4; u++) acc[i][j][u] = 0.f;

    int qrow = lane >> 2;
    int qk   = (lane & 3) * 2;
    int g = lane >> 3, r8 = lane & 7;
    int arow = (g & 1) * 8 + r8;
    uint32_t xv = (uint32_t)(r8 << 4);
    uint32_t ccol = (uint32_t)((g >> 1) * 16);
    const int niter = K >> 6;

    auto issue = [&](int it, int s) {
        int k0 = it << 6;
        uint32_t stb = sb + (uint32_t)s * PSTAGE;
        #pragma unroll
        for (int i = 0; i < 4; i++) {
            int c = t + i * 256;
            int row = c >> 3, cg = c & 7;
            uint32_t off = (uint32_t)(row * 128 + cg * 16);
            uint32_t swo = off ^ ((off >> 3) & 0x70);
            cp_async16(stb + swo,
                       Ahi + (size_t)(m0 + row) * K + k0 + cg * 8);
            cp_async16(stb + 16384 + swo,
                       Bhi + (size_t)(n0 + row) * K + k0 + cg * 8);
        }
        cp_commit();
    };

    issue(0, 0);
    for (int it = 0; it < niter; it++) {
        int s = it & 1;
        cp_wait<0>();
        __syncthreads();
        if (it + 1 < niter) issue(it + 1, s ^ 1);

        uint32_t sA = sb + (uint32_t)s * PSTAGE;
        uint32_t sB = sA + 16384;

        #pragma unroll
        for (int ks = 0; ks < 4; ks++) {
            uint32_t cc = ((uint32_t)(ks * 32) + ccol) ^ xv;
            uint32_t afh[2][4];
            #pragma unroll
            for (int mf = 0; mf < 2; mf++) {
                uint32_t rb = (uint32_t)((wm * 32 + mf * 16 + arow) * 128);
                ldsm_x4(afh[mf], sA + rb + cc);
            }
            #pragma unroll
            for (int nfp = 0; nfp < 4; nfp++) {
                uint32_t rb = (uint32_t)((wn * 64 + nfp * 16 + arow) * 128);
                uint32_t b4[4];
                ldsm_x4(b4, sB + rb + cc);
                #pragma unroll
                for (int mf = 0; mf < 2; mf++) {
                    mma16816(acc[mf][2 * nfp],     afh[mf], b4[0], b4[2]);
                    mma16816(acc[mf][2 * nfp + 1], afh[mf], b4[1], b4[3]);
                }
            }
        }
    }

    #pragma unroll
    for (int mf = 0; mf < 2; mf++) {
        #pragma unroll
        for (int nf = 0; nf < 8; nf++) {
            int row = m0 + wm * 32 + mf * 16 + qrow;
            int col = n0 + wn * 64 + nf * 8 + qk;
            float bv0 = bias[col];
            float bv1 = bias[col + 1];
            *(float2*)(Cm + (size_t)row * N + col) =
                make_float2(acc[mf][nf][0] + bv0, acc[mf][nf][1] + bv1);
            *(float2*)(Cm + (size_t)(row + 8) * N + col) =
                make_float2(acc[mf][nf][2] + bv0, acc[mf][nf][3] + bv1);
        }
    }
}

// ---------------------------------------------------------------------------
// Flash attention, pure fp16 HMMA (all operands 1-term). 3-stage cp.async.
// ---------------------------------------------------------------------------
#define ASTAGE 16384
__global__ __launch_bounds__(128) void attn_mma_kernel(
    const float* __restrict__ bias)
{
    extern __shared__ __align__(16) char asmem[];
    uint32_t sbase = smem_u32(asmem);

    int t = threadIdx.x;
    int wid = t >> 5, lane = t & 31;
    int q0 = blockIdx.x * 64;
    int bh = blockIdx.y;
    int b = bh >> 4, h = bh & 15;

    const __half* Qh = g_qh + (size_t)bh * L_ * D_;
    const __half* Kh = g_kh + (size_t)bh * L_ * D_;
    const __half* Vh = g_vh + (size_t)bh * L_ * D_;

    int rA = q0 + wid * 16 + (lane >> 2);
    int c0 = (lane & 3) * 2;

    uint32_t qa_h[4][4];
    #pragma unroll
    for (int kf = 0; kf < 4; kf++) {
        int cb = kf * 16 + c0;
        qa_h[kf][0] = *(const uint32_t*)(Qh + (size_t)rA * D_ + cb);
        qa_h[kf][1] = *(const uint32_t*)(Qh + (size_t)(rA + 8) * D_ + cb);
        qa_h[kf][2] = *(const uint32_t*)(Qh + (size_t)rA * D_ + cb + 8);
        qa_h[kf][3] = *(const uint32_t*)(Qh + (size_t)(rA + 8) * D_ + cb + 8);
    }

    float m0 = -CUDART_INF_F, m1 = -CUDART_INF_F;
    float l0 = 0.f, l1 = 0.f;
    float oacc[8][4];
    #pragma unroll
    for (int nf = 0; nf < 8; nf++)
        #pragma unroll
        for (int u = 0; u < 4; u++) oacc[nf][u] = 0.f;

    int g = lane >> 3, r8 = lane & 7;
    uint32_t xv = (uint32_t)(r8 << 4);
    uint32_t krow = (uint32_t)((g >> 1) * 8 + r8);
    uint32_t kcol = (uint32_t)((g & 1) * 16);
    uint32_t vrow = (uint32_t)((g & 1) * 8 + r8);
    uint32_t vcol = (uint32_t)((g >> 1) * 16);

    const float* brow0 = bias + (size_t)rA * L_;
    const float* brow1 = bias + (size_t)(rA + 8) * L_;

    auto issue_kv = [&](int k0, int s) {
        uint32_t stb = sbase + (uint32_t)s * ASTAGE;
        #pragma unroll
        for (int i = 0; i < 4; i++) {
            int c = t + i * 128;
            int row = c >> 3, cg = c & 7;
            uint32_t off = (uint32_t)(row * 128 + cg * 16);
            uint32_t swo = off ^ ((off >> 3) & 0x70);
            size_t gsrc = (size_t)(k0 + row) * D_ + cg * 8;
            cp_async16(stb + swo,        Kh + gsrc);
            cp_async16(stb + 8192 + swo, Vh + gsrc);
        }
        cp_commit();
    };

    issue_kv(0, 0);
    issue_kv(64, 1);
    const int NIT = L_ / 64;
    int s = 0;
    for (int ki = 0; ki < NIT; ki++) {
        if (ki + 1 < NIT) cp_wait<1>(); else cp_wait<0>();
        __syncthreads();
        if (ki + 2 < NIT) {
            int s2 = s + 2; if (s2 >= 3) s2 -= 3;
            issue_kv((ki + 2) * 64, s2);
        }

        uint32_t sk = sbase + (uint32_t)s * ASTAGE;
        uint32_t sv = sk + 8192;
        int k0 = ki * 64;

        float sacc[8][4];
        #pragma unroll
        for (int nf = 0; nf < 8; nf++)
            #pragma unroll
            for (int u = 0; u < 4; u++) sacc[nf][u] = 0.f;

        #pragma unroll
        for (int nfp = 0; nfp < 4; nfp++) {
            #pragma unroll
            for (int kf = 0; kf < 4; kf++) {
                uint32_t addr = sk + (uint32_t)((nfp * 16 + krow) * 128)
                              + (((uint32_t)(kf * 32) + kcol) ^ xv);
                uint32_t kb4[4];
                ldsm_x4(kb4, addr);
                mma16816(sacc[2 * nfp],     qa_h[kf], kb4[0], kb4[1]);
                mma16816(sacc[2 * nfp + 1], qa_h[kf], kb4[2], kb4[3]);
            }
        }

        #pragma unroll
        for (int nf = 0; nf < 8; nf++) {
            int kc = k0 + nf * 8 + c0;
            float2 b0 = *(const float2*)(brow0 + kc);
            float2 b1 = *(const float2*)(brow1 + kc);
            sacc[nf][0] += b0.x; sacc[nf][1] += b0.y;
            sacc[nf][2] += b1.x; sacc[nf][3] += b1.y;
        }

        float mx0 = -CUDART_INF_F, mx1 = -CUDART_INF_F;
        #pragma unroll
        for (int nf = 0; nf < 8; nf++) {
            mx0 = fmaxf(mx0, fmaxf(sacc[nf][0], sacc[nf][1]));
            mx1 = fmaxf(mx1, fmaxf(sacc[nf][2], sacc[nf][3]));
        }
        mx0 = fmaxf(mx0, __shfl_xor_sync(0xffffffffu, mx0, 1));
        mx0 = fmaxf(mx0, __shfl_xor_sync(0xffffffffu, mx0, 2));
        mx1 = fmaxf(mx1, __shfl_xor_sync(0xffffffffu, mx1, 1));
        mx1 = fmaxf(mx1, __shfl_xor_sync(0xffffffffu, mx1, 2));

        float mn0 = fmaxf(m0, mx0), mn1 = fmaxf(m1, mx1);
        float cr0 = __expf(m0 - mn0), cr1 = __expf(m1 - mn1);
        float rs0 = 0.f, rs1 = 0.f;
        #pragma unroll
        for (int nf = 0; nf < 8; nf++) {
            sacc[nf][0] = __expf(sacc[nf][0] - mn0);
            sacc[nf][1] = __expf(sacc[nf][1] - mn0);
            sacc[nf][2] = __expf(sacc[nf][2] - mn1);
            sacc[nf][3] = __expf(sacc[nf][3] - mn1);
            rs0 += sacc[nf][0] + sacc[nf][1];
            rs1 += sacc[nf][2] + sacc[nf][3];
        }
        rs0 += __shfl_xor_sync(0xffffffffu, rs0, 1);
        rs0 += __shfl_xor_sync(0xffffffffu, rs0, 2);
        rs1 += __shfl_xor_sync(0xffffffffu, rs1, 1);
        rs1 += __shfl_xor_sync(0xffffffffu, rs1, 2);
        l0 = l0 * cr0 + rs0;
        l1 = l1 * cr1 + rs1;
        m0 = mn0; m1 = mn1;

        #pragma unroll
        for (int nf = 0; nf < 8; nf++) {
            oacc[nf][0] *= cr0; oacc[nf][1] *= cr0;
            oacc[nf][2] *= cr1; oacc[nf][3] *= cr1;
        }

        uint32_t pa_h[4][4];
        #pragma unroll
        for (int kf = 0; kf < 4; kf++) {
            #pragma unroll
            for (int half = 0; half < 2; half++) {
                int nf = 2 * kf + half;
                pa_h[kf][2 * half]     = pack_f16(sacc[nf][0], sacc[nf][1]);
                pa_h[kf][2 * half + 1] = pack_f16(sacc[nf][2], sacc[nf][3]);
            }
        }

        #pragma unroll
        for (int nfp = 0; nfp < 4; nfp++) {
            #pragma unroll
            for (int kf = 0; kf < 4; kf++) {
                uint32_t addr = sv + (uint32_t)((kf * 16 + vrow) * 128)
                              + (((uint32_t)(nfp * 32) + vcol) ^ xv);
                uint32_t vb4[4];
                ldsm_x4_t(vb4, addr);
                mma16816(oacc[2 * nfp],     pa_h[kf], vb4[0], vb4[1]);
                mma16816(oacc[2 * nfp + 1], pa_h[kf], vb4[2], vb4[3]);
            }
        }
        if (++s >= 3) s -= 3;
    }

    float inv0 = 1.f / l0, inv1 = 1.f / l1;
    size_t orow0 = (size_t)(b * L_ + rA) * C_ + h * D_;
    size_t orow1 = (size_t)(b * L_ + rA + 8) * C_ + h * D_;
    #pragma unroll
    for (int nf = 0; nf < 8; nf++) {
        int d = nf * 8 + c0;
        *(uint32_t*)(g_aoh + orow0 + d) = pack_f16(oacc[nf][0] * inv0, oacc[nf][1] * inv0);
        *(uint32_t*)(g_aoh + orow1 + d) = pack_f16(oacc[nf][2] * inv1, oacc[nf][3] * inv1);
    }
}

// ---------------------------------------------------------------------------
extern "C" void kernel_launch(void* const* d_in, const int* in_sizes, int n_in,
                              void* d_out, int out_size)
{
    const float* x         = (const float*)d_in[0];
    const float* freqs     = (const float*)d_in[1];
    const float* attn_bias = (const float*)d_in[2];
    const float* W_qkv     = (const float*)d_in[3];
    const float* q_bias    = (const float*)d_in[4];
    const float* v_bias    = (const float*)d_in[5];
    const float* sml       = (const float*)d_in[6];
    const float* W_proj    = (const float*)d_in[7];
    const float* b_proj    = (const float*)d_in[8];
    float* out = (float*)d_out;

    void* p;
    cudaGetSymbolAddress(&p, g_xhi); __half* xhi = (__half*)p;
    cudaGetSymbolAddress(&p, g_wqh); __half* wqh = (__half*)p;
    cudaGetSymbolAddress(&p, g_wph); __half* wph = (__half*)p;
    cudaGetSymbolAddress(&p, g_aoh); __half* aoh = (__half*)p;

    int psm = 2 * PSTAGE;      // 65536
    int asm_ = 3 * ASTAGE;     // 49152
    static bool attr_set = false;
    if (!attr_set) {
        cudaFuncSetAttribute(gemm_qkv_kernel,
                             cudaFuncAttributeMaxDynamicSharedMemorySize, psm);
        cudaFuncSetAttribute(gemm_proj_kernel,
                             cudaFuncAttributeMaxDynamicSharedMemorySize, psm);
        cudaFuncSetAttribute(attn_mma_kernel,
                             cudaFuncAttributeMaxDynamicSharedMemorySize, asm_);
        attr_set = true;
    }

    conv_hi_kernel<<<(B_ * L_ * C_ / 4 + 255) / 256, 256>>>(x, xhi, B_ * L_ * C_ / 4);
    conv_hi_kernel<<<(3 * C_ * C_ / 4 + 255) / 256, 256>>>(W_qkv, wqh, 3 * C_ * C_ / 4);
    conv_hi_kernel<<<(C_ * C_ / 4 + 255) / 256, 256>>>(W_proj, wph, C_ * C_ / 4);

    gemm_qkv_kernel<<<dim3(3 * C_ / 128, B_ * L_ / 128), 256, psm>>>(
        xhi, wqh, q_bias, v_bias, freqs, sml, 3 * C_, C_);

    attn_mma_kernel<<<dim3(L_ / 64, B_ * H_), 128, asm_>>>(attn_bias);

    gemm_proj_kernel<<<dim3(C_ / 128, B_ * L_ / 128), 256, psm>>>(
        aoh, wph, out, b_proj, C_, C_);
}

// round 15
// speedup vs baseline: 2.6838x; 1.0063x over previous
#include <cuda_runtime.h>
#include <cuda_fp16.h>
#include <math_constants.h>
#include <cstdint>
#include <cstddef>

#define B_ 8
#define L_ 1024
#define C_ 1024
#define H_ 16
#define D_ 64
#define MAXSC 4.6051701859880914f  // log(100)

// ---------------------------------------------------------------------------
// Scratch (bss, no runtime allocation)
// ---------------------------------------------------------------------------
__device__ __half g_xhi[B_ * L_ * C_];
__device__ __half g_wqh[3 * C_ * C_];
__device__ __half g_wph[C_ * C_];

__device__ __half g_qh[B_ * H_ * L_ * D_];
__device__ __half g_kh[B_ * H_ * L_ * D_];
__device__ __half g_vh[B_ * H_ * L_ * D_];

__device__ __half g_aoh[B_ * L_ * C_];

// ---------------------------------------------------------------------------
// Helpers
// ---------------------------------------------------------------------------
__device__ __forceinline__ uint32_t smem_u32(const void* p) {
    uint32_t a;
    asm("{ .reg .u64 t; cvta.to.shared.u64 t, %1; cvt.u32.u64 %0, t; }"
        : "=r"(a) : "l"(p));
    return a;
}

__device__ __forceinline__ void mma16816(float* c, const uint32_t* a,
                                         uint32_t b0, uint32_t b1)
{
    asm volatile(
        "mma.sync.aligned.m16n8k16.row.col.f32.f16.f16.f32 "
        "{%0,%1,%2,%3}, {%4,%5,%6,%7}, {%8,%9}, {%0,%1,%2,%3};"
        : "+f"(c[0]), "+f"(c[1]), "+f"(c[2]), "+f"(c[3])
        : "r"(a[0]), "r"(a[1]), "r"(a[2]), "r"(a[3]), "r"(b0), "r"(b1));
}

__device__ __forceinline__ void ldsm_x4(uint32_t* r, uint32_t addr) {
    asm volatile("ldmatrix.sync.aligned.m8n8.x4.shared.b16 {%0,%1,%2,%3}, [%4];"
        : "=r"(r[0]), "=r"(r[1]), "=r"(r[2]), "=r"(r[3]) : "r"(addr));
}
__device__ __forceinline__ void ldsm_x4_t(uint32_t* r, uint32_t addr) {
    asm volatile("ldmatrix.sync.aligned.m8n8.x4.trans.shared.b16 {%0,%1,%2,%3}, [%4];"
        : "=r"(r[0]), "=r"(r[1]), "=r"(r[2]), "=r"(r[3]) : "r"(addr));
}

__device__ __forceinline__ uint32_t pack_f16(float a, float b) {
    __half2 t = __floats2half2_rn(a, b);
    return *(uint32_t*)&t;
}

__device__ __forceinline__ void cp_async16(uint32_t saddr, const void* gptr) {
    asm volatile("cp.async.cg.shared.global [%0], [%1], 16;"
        :: "r"(saddr), "l"(gptr) : "memory");
}
__device__ __forceinline__ void cp_commit() {
    asm volatile("cp.async.commit_group;" ::: "memory");
}
template <int N>
__device__ __forceinline__ void cp_wait() {
    asm volatile("cp.async.wait_group %0;" :: "n"(N) : "memory");
}

// ---------------------------------------------------------------------------
// Merged fp32->fp16 conversion for x, W_qkv, W_proj (one launch)
// ---------------------------------------------------------------------------
#define N4X  (B_ * L_ * C_ / 4)
#define N4WQ (3 * C_ * C_ / 4)
#define N4WP (C_ * C_ / 4)
__global__ __launch_bounds__(256) void conv_all_kernel(
    const float* __restrict__ x, const float* __restrict__ wq,
    const float* __restrict__ wp,
    __half* __restrict__ xhi, __half* __restrict__ wqh,
    __half* __restrict__ wph)
{
    int i = blockIdx.x * blockDim.x + threadIdx.x;
    const float* src;
    __half* dst;
    int j;
    if (i < N4X) { src = x; dst = xhi; j = i; }
    else if (i < N4X + N4WQ) { src = wq; dst = wqh; j = i - N4X; }
    else if (i < N4X + N4WQ + N4WP) { src = wp; dst = wph; j = i - N4X - N4WQ; }
    else return;
    float4 v = ((const float4*)src)[j];
    ((__half2*)dst)[2 * j]     = __floats2half2_rn(v.x, v.y);
    ((__half2*)dst)[2 * j + 1] = __floats2half2_rn(v.z, v.w);
}

// ---------------------------------------------------------------------------
// QKV GEMM: pure fp16 1-term.  K-chunk 64, 2-stage cp.async.
// Fused epilogue: l2norm + scale + RoPE -> g_qh/kh/vh.
// ---------------------------------------------------------------------------
#define PSTAGE 32768
__global__ __launch_bounds__(256, 2) void gemm_qkv_kernel(
    const __half* __restrict__ Ahi, const __half* __restrict__ Bhi,
    const float* __restrict__ bias_q, const float* __restrict__ bias_v,
    const float* __restrict__ freqs, const float* __restrict__ sml,
    int N, int K)
{
    extern __shared__ __align__(16) char smc[];
    uint32_t sb = smem_u32(smc);
    int t = threadIdx.x;
    int wid = t >> 5, lane = t & 31;
    int wm = wid & 3, wn = wid >> 2;
    int m0 = blockIdx.y * 128, n0 = blockIdx.x * 128;

    float acc[2][8][4];
    #pragma unroll
    for (int i = 0; i < 2; i++)
        #pragma unroll
        for (int j = 0; j < 8; j++)
            #pragma unroll
            for (int u = 0; u < 4; u++) acc[i][j][u] = 0.f;

    int qrow = lane >> 2;
    int qk   = (lane & 3) * 2;
    int g = lane >> 3, r8 = lane & 7;
    int arow = (g & 1) * 8 + r8;
    uint32_t xv = (uint32_t)(r8 << 4);
    uint32_t ccol = (uint32_t)((g >> 1) * 16);
    const int niter = K >> 6;

    auto issue = [&](int it, int s) {
        int k0 = it << 6;
        uint32_t stb = sb + (uint32_t)s * PSTAGE;
        #pragma unroll
        for (int i = 0; i < 4; i++) {
            int c = t + i * 256;
            int row = c >> 3, cg = c & 7;
            uint32_t off = (uint32_t)(row * 128 + cg * 16);
            uint32_t swo = off ^ ((off >> 3) & 0x70);
            cp_async16(stb + swo,
                       Ahi + (size_t)(m0 + row) * K + k0 + cg * 8);
            cp_async16(stb + 16384 + swo,
                       Bhi + (size_t)(n0 + row) * K + k0 + cg * 8);
        }
        cp_commit();
    };

    issue(0, 0);
    for (int it = 0; it < niter; it++) {
        int s = it & 1;
        cp_wait<0>();
        __syncthreads();
        if (it + 1 < niter) issue(it + 1, s ^ 1);

        uint32_t sA = sb + (uint32_t)s * PSTAGE;
        uint32_t sB = sA + 16384;

        #pragma unroll
        for (int ks = 0; ks < 4; ks++) {
            uint32_t cc = ((uint32_t)(ks * 32) + ccol) ^ xv;
            uint32_t afh[2][4];
            #pragma unroll
            for (int mf = 0; mf < 2; mf++) {
                uint32_t rb = (uint32_t)((wm * 32 + mf * 16 + arow) * 128);
                ldsm_x4(afh[mf], sA + rb + cc);
            }
            #pragma unroll
            for (int nfp = 0; nfp < 4; nfp++) {
                uint32_t rb = (uint32_t)((wn * 64 + nfp * 16 + arow) * 128);
                uint32_t b4[4];
                ldsm_x4(b4, sB + rb + cc);
                #pragma unroll
                for (int mf = 0; mf < 2; mf++) {
                    mma16816(acc[mf][2 * nfp],     afh[mf], b4[0], b4[2]);
                    mma16816(acc[mf][2 * nfp + 1], afh[mf], b4[1], b4[3]);
                }
            }
        }
    }

    // fused l2norm + scale + RoPE epilogue.  region 0=q, 1=k, 2=v.
    int region = blockIdx.x >> 3;
    int head   = ((blockIdx.x & 7) << 1) + wn;
    float smul = (region == 0) ? __expf(fminf(sml[head], MAXSC)) : 1.f;
    const float2* fr2 = (const float2*)freqs;

    #pragma unroll
    for (int mf = 0; mf < 2; mf++) {
        int r0 = m0 + wm * 32 + mf * 16 + qrow;
        int bb = r0 >> 10;
        int lA = r0 & 1023, lB = lA + 8;
        size_t baseA = ((size_t)(bb * H_ + head) * L_ + lA) * D_;
        size_t baseB = baseA + 8 * D_;

        float sA = 0.f, sB = 0.f;
        #pragma unroll
        for (int nf = 0; nf < 8; nf++) {
            int d = nf * 8 + qk;
            float bv0 = 0.f, bv1 = 0.f;
            if (region == 0) { bv0 = bias_q[head * D_ + d]; bv1 = bias_q[head * D_ + d + 1]; }
            if (region == 2) { bv0 = bias_v[head * D_ + d]; bv1 = bias_v[head * D_ + d + 1]; }
            acc[mf][nf][0] += bv0; acc[mf][nf][1] += bv1;
            acc[mf][nf][2] += bv0; acc[mf][nf][3] += bv1;
            if (region < 2) {
                sA += acc[mf][nf][0] * acc[mf][nf][0] + acc[mf][nf][1] * acc[mf][nf][1];
                sB += acc[mf][nf][2] * acc[mf][nf][2] + acc[mf][nf][3] * acc[mf][nf][3];
            }
        }

        if (region < 2) {
            sA += __shfl_xor_sync(0xffffffffu, sA, 1);
            sA += __shfl_xor_sync(0xffffffffu, sA, 2);
            sB += __shfl_xor_sync(0xffffffffu, sB, 1);
            sB += __shfl_xor_sync(0xffffffffu, sB, 2);
            float invA = smul / fmaxf(sqrtf(sA), 1e-12f);
            float invB = smul / fmaxf(sqrtf(sB), 1e-12f);

            __half* dst = (region == 0) ? g_qh : g_kh;
            #pragma unroll
            for (int nf = 0; nf < 8; nf++) {
                int d = nf * 8 + qk;
                float2 fA = fr2[lA * (D_ / 2) + (d >> 1)];
                float2 fB = fr2[lB * (D_ / 2) + (d >> 1)];
                float reA = acc[mf][nf][0] * invA, imA = acc[mf][nf][1] * invA;
                float reB = acc[mf][nf][2] * invB, imB = acc[mf][nf][3] * invB;
                *(uint32_t*)(dst + baseA + d) =
                    pack_f16(reA * fA.x - imA * fA.y, reA * fA.y + imA * fA.x);
                *(uint32_t*)(dst + baseB + d) =
                    pack_f16(reB * fB.x - imB * fB.y, reB * fB.y + imB * fB.x);
            }
        } else {
            #pragma unroll
            for (int nf = 0; nf < 8; nf++) {
                int d = nf * 8 + qk;
                *(uint32_t*)(g_vh + baseA + d) = pack_f16(acc[mf][nf][0], acc[mf][nf][1]);
                *(uint32_t*)(g_vh + baseB + d) = pack_f16(acc[mf][nf][2], acc[mf][nf][3]);
            }
        }
    }
}

// ---------------------------------------------------------------------------
// Proj GEMM: pure fp16 1-term. K-chunk 64, 2-stage cp.async.
// ---------------------------------------------------------------------------
__global__ __launch_bounds__(256, 2) void gemm_proj_kernel(
    const __half* __restrict__ Ahi, const __half* __restrict__ Bhi,
    float* __restrict__ Cm, const float* __restrict__ bias,
    int N, int K)
{
    extern __shared__ __align__(16) char smc[];
    uint32_t sb = smem_u32(smc);
    int t = threadIdx.x;
    int wid = t >> 5, lane = t & 31;
    int wm = wid & 3, wn = wid >> 2;
    int m0 = blockIdx.y * 128, n0 = blockIdx.x * 128;

    float acc[2][8][4];
    #pragma unroll
    for (int i = 0; i < 2; i++)
        #pragma unroll
        for (int j = 0; j < 8; j++)
            #pragma unroll
            for (int u = 0; u < 4; u++) acc[i][j][u] = 0.f;

    int qrow = lane >> 2;
    int qk   = (lane & 3) * 2;
    int g = lane >> 3, r8 = lane & 7;
    int arow = (g & 1) * 8 + r8;
    uint32_t xv = (uint32_t)(r8 << 4);
    uint32_t ccol = (uint32_t)((g >> 1) * 16);
    const int niter = K >> 6;

    auto issue = [&](int it, int s) {
        int k0 = it << 6;
        uint32_t stb = sb + (uint32_t)s * PSTAGE;
        #pragma unroll
        for (int i = 0; i < 4; i++) {
            int c = t + i * 256;
            int row = c >> 3, cg = c & 7;
            uint32_t off = (uint32_t)(row * 128 + cg * 16);
            uint32_t swo = off ^ ((off >> 3) & 0x70);
            cp_async16(stb + swo,
                       Ahi + (size_t)(m0 + row) * K + k0 + cg * 8);
            cp_async16(stb + 16384 + swo,
                       Bhi + (size_t)(n0 + row) * K + k0 + cg * 8);
        }
        cp_commit();
    };

    issue(0, 0);
    for (int it = 0; it < niter; it++) {
        int s = it & 1;
        cp_wait<0>();
        __syncthreads();
        if (it + 1 < niter) issue(it + 1, s ^ 1);

        uint32_t sA = sb + (uint32_t)s * PSTAGE;
        uint32_t sB = sA + 16384;

        #pragma unroll
        for (int ks = 0; ks < 4; ks++) {
            uint32_t cc = ((uint32_t)(ks * 32) + ccol) ^ xv;
            uint32_t afh[2][4];
            #pragma unroll
            for (int mf = 0; mf < 2; mf++) {
                uint32_t rb = (uint32_t)((wm * 32 + mf * 16 + arow) * 128);
                ldsm_x4(afh[mf], sA + rb + cc);
            }
            #pragma unroll
            for (int nfp = 0; nfp < 4; nfp++) {
                uint32_t rb = (uint32_t)((wn * 64 + nfp * 16 + arow) * 128);
                uint32_t b4[4];
                ldsm_x4(b4, sB + rb + cc);
                #pragma unroll
                for (int mf = 0; mf < 2; mf++) {
                    mma16816(acc[mf][2 * nfp],     afh[mf], b4[0], b4[2]);
                    mma16816(acc[mf][2 * nfp + 1], afh[mf], b4[1], b4[3]);
                }
            }
        }
    }

    #pragma unroll
    for (int mf = 0; mf < 2; mf++) {
        #pragma unroll
        for (int nf = 0; nf < 8; nf++) {
            int row = m0 + wm * 32 + mf * 16 + qrow;
            int col = n0 + wn * 64 + nf * 8 + qk;
            float bv0 = bias[col];
            float bv1 = bias[col + 1];
            *(float2*)(Cm + (size_t)row * N + col) =
                make_float2(acc[mf][nf][0] + bv0, acc[mf][nf][1] + bv1);
            *(float2*)(Cm + (size_t)(row + 8) * N + col) =
                make_float2(acc[mf][nf][2] + bv0, acc[mf][nf][3] + bv1);
        }
    }
}

// ---------------------------------------------------------------------------
// Flash attention, pure fp16 HMMA. 128-query CTA (8 warps, 256 threads),
// 3-stage cp.async on 64-key K/V tiles.
// ---------------------------------------------------------------------------
#define ASTAGE 16384
__global__ __launch_bounds__(256) void attn_mma_kernel(
    const float* __restrict__ bias)
{
    extern __shared__ __align__(16) char asmem[];
    uint32_t sbase = smem_u32(asmem);

    int t = threadIdx.x;
    int wid = t >> 5, lane = t & 31;
    int q0 = blockIdx.x * 128;
    int bh = blockIdx.y;
    int b = bh >> 4, h = bh & 15;

    const __half* Qh = g_qh + (size_t)bh * L_ * D_;
    const __half* Kh = g_kh + (size_t)bh * L_ * D_;
    const __half* Vh = g_vh + (size_t)bh * L_ * D_;

    int rA = q0 + wid * 16 + (lane >> 2);
    int c0 = (lane & 3) * 2;

    uint32_t qa_h[4][4];
    #pragma unroll
    for (int kf = 0; kf < 4; kf++) {
        int cb = kf * 16 + c0;
        qa_h[kf][0] = *(const uint32_t*)(Qh + (size_t)rA * D_ + cb);
        qa_h[kf][1] = *(const uint32_t*)(Qh + (size_t)(rA + 8) * D_ + cb);
        qa_h[kf][2] = *(const uint32_t*)(Qh + (size_t)rA * D_ + cb + 8);
        qa_h[kf][3] = *(const uint32_t*)(Qh + (size_t)(rA + 8) * D_ + cb + 8);
    }

    float m0 = -CUDART_INF_F, m1 = -CUDART_INF_F;
    float l0 = 0.f, l1 = 0.f;
    float oacc[8][4];
    #pragma unroll
    for (int nf = 0; nf < 8; nf++)
        #pragma unroll
        for (int u = 0; u < 4; u++) oacc[nf][u] = 0.f;

    int g = lane >> 3, r8 = lane & 7;
    uint32_t xv = (uint32_t)(r8 << 4);
    uint32_t krow = (uint32_t)((g >> 1) * 8 + r8);
    uint32_t kcol = (uint32_t)((g & 1) * 16);
    uint32_t vrow = (uint32_t)((g & 1) * 8 + r8);
    uint32_t vcol = (uint32_t)((g >> 1) * 16);

    const float* brow0 = bias + (size_t)rA * L_;
    const float* brow1 = bias + (size_t)(rA + 8) * L_;

    auto issue_kv = [&](int k0, int s) {
        uint32_t stb = sbase + (uint32_t)s * ASTAGE;
        #pragma unroll
        for (int i = 0; i < 2; i++) {
            int c = t + i * 256;
            int row = c >> 3, cg = c & 7;
            uint32_t off = (uint32_t)(row * 128 + cg * 16);
            uint32_t swo = off ^ ((off >> 3) & 0x70);
            size_t gsrc = (size_t)(k0 + row) * D_ + cg * 8;
            cp_async16(stb + swo,        Kh + gsrc);
            cp_async16(stb + 8192 + swo, Vh + gsrc);
        }
        cp_commit();
    };

    issue_kv(0, 0);
    issue_kv(64, 1);
    const int NIT = L_ / 64;
    int s = 0;
    for (int ki = 0; ki < NIT; ki++) {
        if (ki + 1 < NIT) cp_wait<1>(); else cp_wait<0>();
        __syncthreads();
        if (ki + 2 < NIT) {
            int s2 = s + 2; if (s2 >= 3) s2 -= 3;
            issue_kv((ki + 2) * 64, s2);
        }

        uint32_t sk = sbase + (uint32_t)s * ASTAGE;
        uint32_t sv = sk + 8192;
        int k0 = ki * 64;

        float sacc[8][4];
        #pragma unroll
        for (int nf = 0; nf < 8; nf++)
            #pragma unroll
            for (int u = 0; u < 4; u++) sacc[nf][u] = 0.f;

        #pragma unroll
        for (int nfp = 0; nfp < 4; nfp++) {
            #pragma unroll
            for (int kf = 0; kf < 4; kf++) {
                uint32_t addr = sk + (uint32_t)((nfp * 16 + krow) * 128)
                              + (((uint32_t)(kf * 32) + kcol) ^ xv);
                uint32_t kb4[4];
                ldsm_x4(kb4, addr);
                mma16816(sacc[2 * nfp],     qa_h[kf], kb4[0], kb4[1]);
                mma16816(sacc[2 * nfp + 1], qa_h[kf], kb4[2], kb4[3]);
            }
        }

        #pragma unroll
        for (int nf = 0; nf < 8; nf++) {
            int kc = k0 + nf * 8 + c0;
            float2 b0 = *(const float2*)(brow0 + kc);
            float2 b1 = *(const float2*)(brow1 + kc);
            sacc[nf][0] += b0.x; sacc[nf][1] += b0.y;
            sacc[nf][2] += b1.x; sacc[nf][3] += b1.y;
        }

        float mx0 = -CUDART_INF_F, mx1 = -CUDART_INF_F;
        #pragma unroll
        for (int nf = 0; nf < 8; nf++) {
            mx0 = fmaxf(mx0, fmaxf(sacc[nf][0], sacc[nf][1]));
            mx1 = fmaxf(mx1, fmaxf(sacc[nf][2], sacc[nf][3]));
        }
        mx0 = fmaxf(mx0, __shfl_xor_sync(0xffffffffu, mx0, 1));
        mx0 = fmaxf(mx0, __shfl_xor_sync(0xffffffffu, mx0, 2));
        mx1 = fmaxf(mx1, __shfl_xor_sync(0xffffffffu, mx1, 1));
        mx1 = fmaxf(mx1, __shfl_xor_sync(0xffffffffu, mx1, 2));

        float mn0 = fmaxf(m0, mx0), mn1 = fmaxf(m1, mx1);
        float cr0 = __expf(m0 - mn0), cr1 = __expf(m1 - mn1);
        float rs0 = 0.f, rs1 = 0.f;
        #pragma unroll
        for (int nf = 0; nf < 8; nf++) {
            sacc[nf][0] = __expf(sacc[nf][0] - mn0);
            sacc[nf][1] = __expf(sacc[nf][1] - mn0);
            sacc[nf][2] = __expf(sacc[nf][2] - mn1);
            sacc[nf][3] = __expf(sacc[nf][3] - mn1);
            rs0 += sacc[nf][0] + sacc[nf][1];
            rs1 += sacc[nf][2] + sacc[nf][3];
        }
        rs0 += __shfl_xor_sync(0xffffffffu, rs0, 1);
        rs0 += __shfl_xor_sync(0xffffffffu, rs0, 2);
        rs1 += __shfl_xor_sync(0xffffffffu, rs1, 1);
        rs1 += __shfl_xor_sync(0xffffffffu, rs1, 2);
        l0 = l0 * cr0 + rs0;
        l1 = l1 * cr1 + rs1;
        m0 = mn0; m1 = mn1;

        #pragma unroll
        for (int nf = 0; nf < 8; nf++) {
            oacc[nf][0] *= cr0; oacc[nf][1] *= cr0;
            oacc[nf][2] *= cr1; oacc[nf][3] *= cr1;
        }

        uint32_t pa_h[4][4];
        #pragma unroll
        for (int kf = 0; kf < 4; kf++) {
            #pragma unroll
            for (int half = 0; half < 2; half++) {
                int nf = 2 * kf + half;
                pa_h[kf][2 * half]     = pack_f16(sacc[nf][0], sacc[nf][1]);
                pa_h[kf][2 * half + 1] = pack_f16(sacc[nf][2], sacc[nf][3]);
            }
        }

        #pragma unroll
        for (int nfp = 0; nfp < 4; nfp++) {
            #pragma unroll
            for (int kf = 0; kf < 4; kf++) {
                uint32_t addr = sv + (uint32_t)((kf * 16 + vrow) * 128)
                              + (((uint32_t)(nfp * 32) + vcol) ^ xv);
                uint32_t vb4[4];
                ldsm_x4_t(vb4, addr);
                mma16816(oacc[2 * nfp],     pa_h[kf], vb4[0], vb4[1]);
                mma16816(oacc[2 * nfp + 1], pa_h[kf], vb4[2], vb4[3]);
            }
        }
        if (++s >= 3) s -= 3;
    }

    float inv0 = 1.f / l0, inv1 = 1.f / l1;
    size_t orow0 = (size_t)(b * L_ + rA) * C_ + h * D_;
    size_t orow1 = (size_t)(b * L_ + rA + 8) * C_ + h * D_;
    #pragma unroll
    for (int nf = 0; nf < 8; nf++) {
        int d = nf * 8 + c0;
        *(uint32_t*)(g_aoh + orow0 + d) = pack_f16(oacc[nf][0] * inv0, oacc[nf][1] * inv0);
        *(uint32_t*)(g_aoh + orow1 + d) = pack_f16(oacc[nf][2] * inv1, oacc[nf][3] * inv1);
    }
}

// ---------------------------------------------------------------------------
extern "C" void kernel_launch(void* const* d_in, const int* in_sizes, int n_in,
                              void* d_out, int out_size)
{
    const float* x         = (const float*)d_in[0];
    const float* freqs     = (const float*)d_in[1];
    const float* attn_bias = (const float*)d_in[2];
    const float* W_qkv     = (const float*)d_in[3];
    const float* q_bias    = (const float*)d_in[4];
    const float* v_bias    = (const float*)d_in[5];
    const float* sml       = (const float*)d_in[6];
    const float* W_proj    = (const float*)d_in[7];
    const float* b_proj    = (const float*)d_in[8];
    float* out = (float*)d_out;

    void* p;
    cudaGetSymbolAddress(&p, g_xhi); __half* xhi = (__half*)p;
    cudaGetSymbolAddress(&p, g_wqh); __half* wqh = (__half*)p;
    cudaGetSymbolAddress(&p, g_wph); __half* wph = (__half*)p;
    cudaGetSymbolAddress(&p, g_aoh); __half* aoh = (__half*)p;

    int psm = 2 * PSTAGE;      // 65536
    int asm_ = 3 * ASTAGE;     // 49152
    static bool attr_set = false;
    if (!attr_set) {
        cudaFuncSetAttribute(gemm_qkv_kernel,
                             cudaFuncAttributeMaxDynamicSharedMemorySize, psm);
        cudaFuncSetAttribute(gemm_proj_kernel,
                             cudaFuncAttributeMaxDynamicSharedMemorySize, psm);
        cudaFuncSetAttribute(attn_mma_kernel,
                             cudaFuncAttributeMaxDynamicSharedMemorySize, asm_);
        attr_set = true;
    }

    int ntot = N4X + N4WQ + N4WP;
    conv_all_kernel<<<(ntot + 255) / 256, 256>>>(x, W_qkv, W_proj, xhi, wqh, wph);

    gemm_qkv_kernel<<<dim3(3 * C_ / 128, B_ * L_ / 128), 256, psm>>>(
        xhi, wqh, q_bias, v_bias, freqs, sml, 3 * C_, C_);

    attn_mma_kernel<<<dim3(L_ / 128, B_ * H_), 256, asm_>>>(attn_bias);

    gemm_proj_kernel<<<dim3(C_ / 128, B_ * L_ / 128), 256, psm>>>(
        aoh, wph, out, b_proj, C_, C_);
}